// round 1
// baseline (speedup 1.0000x reference)
#include <cuda_runtime.h>
#include <cuda_bf16.h>
#include <math.h>

#define D_MODEL 1024
#define NHEAD   16
#define DHEAD   64
#define BATCH   4
#define SEQ     2048
#define NTOK    (BATCH*SEQ)   // 8192
#define KDIM    1024

// Scratch (allocation-free rule: __device__ globals)
__device__ float g_q[BATCH*NHEAD*SEQ*DHEAD];    // [B,H,S,Dh]
__device__ float g_k[BATCH*NHEAD*SEQ*DHEAD];
__device__ float g_v[BATCH*NHEAD*SEQ*DHEAD];
__device__ float g_attn[NTOK*D_MODEL];          // [B,S,D]

// ---------------------------------------------------------------------------
// SGEMM (NT): Y[n,m] = sum_k A[n,k] * W[m,k] + bias[m]
// A: [NTOK, 1024] row-major, W: [1024, 1024] row-major (torch Linear weight)
// HEAD_LAYOUT: write Y to [B,H,S,Dh] instead of [N,M]
// Block tile 128x128, BK=16, 256 threads, 8x8 per thread.
// ---------------------------------------------------------------------------
template<bool HEAD_LAYOUT>
__global__ __launch_bounds__(256)
void sgemm_nt(const float* __restrict__ A, const float* __restrict__ W,
              const float* __restrict__ bias, float* __restrict__ Y)
{
    __shared__ __align__(16) float As[16][132];  // [k][n] transposed
    __shared__ __align__(16) float Ws[16][132];  // [k][m] transposed

    const int tid = threadIdx.x;
    const int bn  = blockIdx.y * 128;   // token rows
    const int bm  = blockIdx.x * 128;   // output cols
    const int tr  = (tid / 16) * 8;     // row offset in tile
    const int tc  = (tid % 16) * 8;     // col offset in tile

    const int lrow = tid / 4;           // 0..63 (load row within 64-row pass)
    const int lc4  = (tid % 4) * 4;     // k offset (float index)

    const float* Aptr = A + (size_t)(bn + lrow) * KDIM + lc4;
    const float* Wptr = W + (size_t)(bm + lrow) * KDIM + lc4;

    float acc[8][8];
    #pragma unroll
    for (int i = 0; i < 8; i++)
        #pragma unroll
        for (int j = 0; j < 8; j++) acc[i][j] = 0.f;

    for (int k0 = 0; k0 < KDIM; k0 += 16) {
        #pragma unroll
        for (int p = 0; p < 2; p++) {
            float4 a = *(const float4*)(Aptr + (size_t)(p*64)*KDIM + k0);
            float4 w = *(const float4*)(Wptr + (size_t)(p*64)*KDIM + k0);
            int r = lrow + p*64;
            As[lc4+0][r]=a.x; As[lc4+1][r]=a.y; As[lc4+2][r]=a.z; As[lc4+3][r]=a.w;
            Ws[lc4+0][r]=w.x; Ws[lc4+1][r]=w.y; Ws[lc4+2][r]=w.z; Ws[lc4+3][r]=w.w;
        }
        __syncthreads();
        #pragma unroll
        for (int kk = 0; kk < 16; kk++) {
            float a[8], b[8];
            #pragma unroll
            for (int i = 0; i < 8; i += 4) {
                float4 t = *(const float4*)&As[kk][tr+i];
                a[i]=t.x; a[i+1]=t.y; a[i+2]=t.z; a[i+3]=t.w;
            }
            #pragma unroll
            for (int j = 0; j < 8; j += 4) {
                float4 t = *(const float4*)&Ws[kk][tc+j];
                b[j]=t.x; b[j+1]=t.y; b[j+2]=t.z; b[j+3]=t.w;
            }
            #pragma unroll
            for (int i = 0; i < 8; i++)
                #pragma unroll
                for (int j = 0; j < 8; j++)
                    acc[i][j] += a[i] * b[j];
        }
        __syncthreads();
    }

    // Epilogue: bias + store
    float bj[8];
    #pragma unroll
    for (int j = 0; j < 8; j++) bj[j] = bias[bm + tc + j];

    #pragma unroll
    for (int i = 0; i < 8; i++) {
        int row = bn + tr + i;                   // token index
        if (HEAD_LAYOUT) {
            int b = row / SEQ, s = row % SEQ;
            // cols bm+tc .. bm+tc+7 stay within one head (DHEAD=64, tc mult of 8)
            int col0 = bm + tc;
            int h = col0 / DHEAD, d0 = col0 % DHEAD;
            float* yp = Y + (((size_t)(b*NHEAD + h)*SEQ + s)*DHEAD + d0);
            #pragma unroll
            for (int j = 0; j < 8; j++) yp[j] = acc[i][j] + bj[j];
        } else {
            float* yp = Y + (size_t)row * D_MODEL + bm + tc;
            #pragma unroll
            for (int j = 0; j < 8; j++) yp[j] = acc[i][j] + bj[j];
        }
    }
}

// ---------------------------------------------------------------------------
// Causal flash attention, fp32. Br=Bc=64, Dh=64, 256 threads.
// Thread (r = tid/4, cg = tid%4) computes scores s[r][cg*16..+15] and
// output o[r][cg*16..+15]. Row reductions via shfl within 4-lane group.
// ---------------------------------------------------------------------------
#define ATTN_SMEM_FLOATS (4 * 64 * 68)

__global__ __launch_bounds__(256)
void attn_kernel()
{
    extern __shared__ __align__(16) float smem[];
    float (*Qs)[68] = (float(*)[68])(smem);
    float (*Kt)[68] = (float(*)[68])(smem + 64*68);     // [dh][c]
    float (*Vs)[68] = (float(*)[68])(smem + 2*64*68);   // [c][dh]
    float (*Ps)[68] = (float(*)[68])(smem + 3*64*68);

    const int bh = blockIdx.y;                   // b*NHEAD + h
    const int qi = (int)gridDim.x - 1 - (int)blockIdx.x;  // heavy blocks first
    const int q0 = qi * 64;

    const float* Qg = g_q + (size_t)bh * SEQ * DHEAD;
    const float* Kg = g_k + (size_t)bh * SEQ * DHEAD;
    const float* Vg = g_v + (size_t)bh * SEQ * DHEAD;

    const int tid = threadIdx.x;
    const int r   = tid / 4;      // 0..63
    const int cg  = tid % 4;
    const int c0  = cg * 16;

    // Load Q tile [64 x 64]
    #pragma unroll
    for (int p = 0; p < 4; p++) {
        int kk = (cg + p*4) * 4;
        *(float4*)&Qs[r][kk] = *(const float4*)&Qg[(size_t)(q0+r)*DHEAD + kk];
    }

    float m = -1e30f, l = 0.f;
    float o[16];
    #pragma unroll
    for (int i = 0; i < 16; i++) o[i] = 0.f;

    for (int j = 0; j <= qi; j++) {
        __syncthreads();   // protects Qs on first iter; Vs/Ps reuse after
        const int kv0 = j * 64;
        #pragma unroll
        for (int p = 0; p < 4; p++) {
            int kk = (cg + p*4) * 4;
            float4 kv = *(const float4*)&Kg[(size_t)(kv0+r)*DHEAD + kk];
            Kt[kk+0][r]=kv.x; Kt[kk+1][r]=kv.y; Kt[kk+2][r]=kv.z; Kt[kk+3][r]=kv.w;
            *(float4*)&Vs[r][kk] = *(const float4*)&Vg[(size_t)(kv0+r)*DHEAD + kk];
        }
        __syncthreads();

        // scores: s[i] = dot(Q[r,:], K[c0+i,:])
        float s[16];
        #pragma unroll
        for (int i = 0; i < 16; i++) s[i] = 0.f;
        #pragma unroll 8
        for (int kk = 0; kk < 64; kk++) {
            float qv = Qs[r][kk];
            #pragma unroll
            for (int q4 = 0; q4 < 4; q4++) {
                float4 kv = *(const float4*)&Kt[kk][c0 + q4*4];
                s[q4*4+0] += qv * kv.x;
                s[q4*4+1] += qv * kv.y;
                s[q4*4+2] += qv * kv.z;
                s[q4*4+3] += qv * kv.w;
            }
        }

        const float sc = 0.125f;  // 1/sqrt(64)
        const bool diag = (j == qi);
        float rmax = -1e30f;
        #pragma unroll
        for (int i = 0; i < 16; i++) {
            float sv = s[i] * sc;
            if (diag && (kv0 + c0 + i > q0 + r)) sv = -1e30f;
            s[i] = sv;
            rmax = fmaxf(rmax, sv);
        }
        rmax = fmaxf(rmax, __shfl_xor_sync(0xffffffffu, rmax, 1));
        rmax = fmaxf(rmax, __shfl_xor_sync(0xffffffffu, rmax, 2));

        float mnew  = fmaxf(m, rmax);
        float alpha = __expf(m - mnew);
        float rsum = 0.f;
        #pragma unroll
        for (int i = 0; i < 16; i++) {
            float p = __expf(s[i] - mnew);
            s[i] = p;
            rsum += p;
        }
        rsum += __shfl_xor_sync(0xffffffffu, rsum, 1);
        rsum += __shfl_xor_sync(0xffffffffu, rsum, 2);
        l = l * alpha + rsum;
        m = mnew;
        #pragma unroll
        for (int i = 0; i < 16; i++) o[i] *= alpha;

        // stage P to smem for the cross-thread PV product
        #pragma unroll
        for (int q4 = 0; q4 < 4; q4++) {
            float4 t = make_float4(s[q4*4+0], s[q4*4+1], s[q4*4+2], s[q4*4+3]);
            *(float4*)&Ps[r][c0 + q4*4] = t;
        }
        __syncthreads();

        // o[r][c0+i] += sum_c P[r][c] * V[c][c0+i]
        #pragma unroll 8
        for (int c = 0; c < 64; c++) {
            float pv = Ps[r][c];
            #pragma unroll
            for (int q4 = 0; q4 < 4; q4++) {
                float4 vv = *(const float4*)&Vs[c][c0 + q4*4];
                o[q4*4+0] += pv * vv.x;
                o[q4*4+1] += pv * vv.y;
                o[q4*4+2] += pv * vv.z;
                o[q4*4+3] += pv * vv.w;
            }
        }
    }

    // normalize + write to [B,S,D] layout
    const float inv = 1.f / l;
    const int b = bh / NHEAD, h = bh % NHEAD;
    float* outp = g_attn + ((size_t)(b*SEQ + q0 + r)) * D_MODEL + h*DHEAD + c0;
    #pragma unroll
    for (int q4 = 0; q4 < 4; q4++) {
        float4 t = make_float4(o[q4*4+0]*inv, o[q4*4+1]*inv,
                               o[q4*4+2]*inv, o[q4*4+3]*inv);
        *(float4*)&outp[q4*4] = t;
    }
}

// ---------------------------------------------------------------------------
extern "C" void kernel_launch(void* const* d_in, const int* in_sizes, int n_in,
                              void* d_out, int out_size)
{
    const float* x  = (const float*)d_in[0];
    const float* Wq = (const float*)d_in[1];
    const float* bq = (const float*)d_in[2];
    const float* Wk = (const float*)d_in[3];
    const float* bk = (const float*)d_in[4];
    const float* Wv = (const float*)d_in[5];
    const float* bv = (const float*)d_in[6];
    const float* Wo = (const float*)d_in[7];
    const float* bo = (const float*)d_in[8];

    float *qp, *kp, *vp, *ap;
    cudaGetSymbolAddress((void**)&qp, g_q);
    cudaGetSymbolAddress((void**)&kp, g_k);
    cudaGetSymbolAddress((void**)&vp, g_v);
    cudaGetSymbolAddress((void**)&ap, g_attn);

    dim3 gg(D_MODEL/128, NTOK/128);   // (8, 64)
    sgemm_nt<true ><<<gg, 256>>>(x, Wq, bq, qp);
    sgemm_nt<true ><<<gg, 256>>>(x, Wk, bk, kp);
    sgemm_nt<true ><<<gg, 256>>>(x, Wv, bv, vp);

    const int smem_bytes = ATTN_SMEM_FLOATS * (int)sizeof(float);  // 69632
    cudaFuncSetAttribute(attn_kernel,
                         cudaFuncAttributeMaxDynamicSharedMemorySize, smem_bytes);
    attn_kernel<<<dim3(SEQ/64, BATCH*NHEAD), 256, smem_bytes>>>();

    sgemm_nt<false><<<gg, 256>>>(ap, Wo, bo, (float*)d_out);
}

// round 3
// speedup vs baseline: 1.2592x; 1.2592x over previous
#include <cuda_runtime.h>
#include <cuda_bf16.h>
#include <math.h>
#include <cstdint>

#define D_MODEL 1024
#define NHEAD   16
#define DHEAD   64
#define BATCH   4
#define SEQ     2048
#define NTOK    (BATCH*SEQ)   // 8192
#define KDIM    1024

// Scratch (allocation-free rule: __device__ globals)
__device__ float g_q[BATCH*NHEAD*SEQ*DHEAD];    // [B,H,S,Dh]
__device__ float g_k[BATCH*NHEAD*SEQ*DHEAD];
__device__ float g_v[BATCH*NHEAD*SEQ*DHEAD];
__device__ float g_attn[NTOK*D_MODEL];          // [B,S,D]

__device__ __forceinline__ uint32_t f2tf32(float f) {
    uint32_t r;
    asm("cvt.rna.tf32.f32 %0, %1;" : "=r"(r) : "f"(f));
    return r;
}

// D += A*B, m16n8k8 tf32 (A row-major 16x8, B col-major 8x8)
__device__ __forceinline__ void mma_tf32(float* c, const uint32_t* a, const uint32_t* b) {
    asm volatile(
        "mma.sync.aligned.m16n8k8.row.col.f32.tf32.tf32.f32 "
        "{%0,%1,%2,%3}, {%4,%5,%6,%7}, {%8,%9}, {%0,%1,%2,%3};"
        : "+f"(c[0]), "+f"(c[1]), "+f"(c[2]), "+f"(c[3])
        : "r"(a[0]), "r"(a[1]), "r"(a[2]), "r"(a[3]), "r"(b[0]), "r"(b[1]));
}

// ---------------------------------------------------------------------------
// tf32 mma.sync GEMM (NT): Y[n,m] = sum_k A[n,k]*W[m,k] + bias[m]
// CTA tile 128x128, BK=32, 256 threads (8 warps, 2x4), warp tile 64x32.
// ---------------------------------------------------------------------------
#define BK       32
#define KCHUNKS  (KDIM / BK)      // 32
#define ROWPAD   36               // floats per smem row (conflict-free frag LDS)
#define TILE_FLOATS (128 * ROWPAD)
#define GEMM_SMEM_BYTES (4 * TILE_FLOATS * 4)   // 73728

template<bool HEAD_LAYOUT>
__global__ __launch_bounds__(256)
void gemm_mma(const float* __restrict__ A, const float* __restrict__ W,
              const float* __restrict__ bias, float* __restrict__ Y)
{
    extern __shared__ __align__(16) float smem[];
    float* As = smem;                    // [2][128][ROWPAD]
    float* Ws = smem + 2 * TILE_FLOATS;  // [2][128][ROWPAD]

    const int tid    = threadIdx.x;
    const int lane   = tid & 31;
    const int wid    = tid >> 5;
    const int warp_m = wid & 1;          // 0..1  (64-row groups)
    const int warp_n = wid >> 1;         // 0..3  (32-col groups)
    const int gr     = lane >> 2;        // 0..7
    const int t4     = lane & 3;         // 0..3

    const int bn = blockIdx.y * 128;     // token rows
    const int bm = blockIdx.x * 128;     // output cols

    const float* Ag = A + (size_t)bn * KDIM;
    const float* Wg = W + (size_t)bm * KDIM;

    // loader indices: thread covers rows {r0, r0+32, r0+64, r0+96}, 16B col c4*4
    const int r0 = tid >> 3;
    const int c4 = tid & 7;

    float4 pa[4], pw[4];
    auto ldg = [&](int c) {
        const int koff = c * BK + c4 * 4;
        #pragma unroll
        for (int p = 0; p < 4; p++) {
            pa[p] = *(const float4*)(Ag + (size_t)(r0 + p*32) * KDIM + koff);
            pw[p] = *(const float4*)(Wg + (size_t)(r0 + p*32) * KDIM + koff);
        }
    };
    auto sts = [&](int buf) {
        float* ab = As + buf * TILE_FLOATS;
        float* wb = Ws + buf * TILE_FLOATS;
        #pragma unroll
        for (int p = 0; p < 4; p++) {
            const int off = (r0 + p*32) * ROWPAD + c4 * 4;
            ab[off+0] = __uint_as_float(f2tf32(pa[p].x));
            ab[off+1] = __uint_as_float(f2tf32(pa[p].y));
            ab[off+2] = __uint_as_float(f2tf32(pa[p].z));
            ab[off+3] = __uint_as_float(f2tf32(pa[p].w));
            wb[off+0] = __uint_as_float(f2tf32(pw[p].x));
            wb[off+1] = __uint_as_float(f2tf32(pw[p].y));
            wb[off+2] = __uint_as_float(f2tf32(pw[p].z));
            wb[off+3] = __uint_as_float(f2tf32(pw[p].w));
        }
    };

    float acc[4][4][4];
    #pragma unroll
    for (int mt = 0; mt < 4; mt++)
        #pragma unroll
        for (int nt = 0; nt < 4; nt++)
            #pragma unroll
            for (int i = 0; i < 4; i++) acc[mt][nt][i] = 0.f;

    ldg(0); sts(0);
    __syncthreads();

    for (int c = 0; c < KCHUNKS; c++) {
        const int buf = c & 1;
        if (c + 1 < KCHUNKS) ldg(c + 1);

        const float* Ab = As + buf * TILE_FLOATS + (warp_m * 64) * ROWPAD;
        const float* Wb = Ws + buf * TILE_FLOATS + (warp_n * 32) * ROWPAD;
        #pragma unroll
        for (int kk = 0; kk < 4; kk++) {
            const int k0 = kk * 8 + t4;
            uint32_t af[4][4], bf[4][2];
            #pragma unroll
            for (int mt = 0; mt < 4; mt++) {
                const int base = (mt * 16 + gr) * ROWPAD + k0;
                af[mt][0] = __float_as_uint(Ab[base]);
                af[mt][1] = __float_as_uint(Ab[base + 8 * ROWPAD]);
                af[mt][2] = __float_as_uint(Ab[base + 4]);
                af[mt][3] = __float_as_uint(Ab[base + 8 * ROWPAD + 4]);
            }
            #pragma unroll
            for (int nt = 0; nt < 4; nt++) {
                const int base = (nt * 8 + gr) * ROWPAD + k0;
                bf[nt][0] = __float_as_uint(Wb[base]);
                bf[nt][1] = __float_as_uint(Wb[base + 4]);
            }
            #pragma unroll
            for (int mt = 0; mt < 4; mt++)
                #pragma unroll
                for (int nt = 0; nt < 4; nt++)
                    mma_tf32(acc[mt][nt], af[mt], bf[nt]);
        }

        if (c + 1 < KCHUNKS) sts(1 - buf);
        __syncthreads();
    }

    // ---- epilogue: bias + store (fragment layout) ----
    #pragma unroll
    for (int nt = 0; nt < 4; nt++) {
        const int col = bm + warp_n * 32 + nt * 8 + t4 * 2;
        const float2 bv = *(const float2*)&bias[col];
        #pragma unroll
        for (int mt = 0; mt < 4; mt++) {
            const int row = bn + warp_m * 64 + mt * 16 + gr;
            float2 v0 = make_float2(acc[mt][nt][0] + bv.x, acc[mt][nt][1] + bv.y);
            float2 v1 = make_float2(acc[mt][nt][2] + bv.x, acc[mt][nt][3] + bv.y);
            if (HEAD_LAYOUT) {
                const int h = col / DHEAD, d = col % DHEAD;
                const int bb0 = row / SEQ, s0 = row % SEQ;
                const int bb1 = (row + 8) / SEQ, s1 = (row + 8) % SEQ;
                *(float2*)&Y[(((size_t)(bb0*NHEAD + h)*SEQ + s0)*DHEAD) + d] = v0;
                *(float2*)&Y[(((size_t)(bb1*NHEAD + h)*SEQ + s1)*DHEAD) + d] = v1;
            } else {
                *(float2*)&Y[(size_t)row * D_MODEL + col] = v0;
                *(float2*)&Y[(size_t)(row + 8) * D_MODEL + col] = v1;
            }
        }
    }
}

// ---------------------------------------------------------------------------
// Causal flash attention, fp32 SIMT (unchanged from R1). Br=Bc=64, 256 thr.
// ---------------------------------------------------------------------------
#define ATTN_SMEM_FLOATS (4 * 64 * 68)

__global__ __launch_bounds__(256)
void attn_kernel()
{
    extern __shared__ __align__(16) float asmem[];
    float (*Qs)[68] = (float(*)[68])(asmem);
    float (*Kt)[68] = (float(*)[68])(asmem + 64*68);     // [dh][c]
    float (*Vs)[68] = (float(*)[68])(asmem + 2*64*68);   // [c][dh]
    float (*Ps)[68] = (float(*)[68])(asmem + 3*64*68);

    const int bh = blockIdx.y;
    const int qi = (int)gridDim.x - 1 - (int)blockIdx.x;
    const int q0 = qi * 64;

    const float* Qg = g_q + (size_t)bh * SEQ * DHEAD;
    const float* Kg = g_k + (size_t)bh * SEQ * DHEAD;
    const float* Vg = g_v + (size_t)bh * SEQ * DHEAD;

    const int tid = threadIdx.x;
    const int r   = tid / 4;
    const int cg  = tid % 4;
    const int c0  = cg * 16;

    #pragma unroll
    for (int p = 0; p < 4; p++) {
        int kk = (cg + p*4) * 4;
        *(float4*)&Qs[r][kk] = *(const float4*)&Qg[(size_t)(q0+r)*DHEAD + kk];
    }

    float m = -1e30f, l = 0.f;
    float o[16];
    #pragma unroll
    for (int i = 0; i < 16; i++) o[i] = 0.f;

    for (int j = 0; j <= qi; j++) {
        __syncthreads();
        const int kv0 = j * 64;
        #pragma unroll
        for (int p = 0; p < 4; p++) {
            int kk = (cg + p*4) * 4;
            float4 kv = *(const float4*)&Kg[(size_t)(kv0+r)*DHEAD + kk];
            Kt[kk+0][r]=kv.x; Kt[kk+1][r]=kv.y; Kt[kk+2][r]=kv.z; Kt[kk+3][r]=kv.w;
            *(float4*)&Vs[r][kk] = *(const float4*)&Vg[(size_t)(kv0+r)*DHEAD + kk];
        }
        __syncthreads();

        float s[16];
        #pragma unroll
        for (int i = 0; i < 16; i++) s[i] = 0.f;
        #pragma unroll 8
        for (int kk = 0; kk < 64; kk++) {
            float qv = Qs[r][kk];
            #pragma unroll
            for (int q4 = 0; q4 < 4; q4++) {
                float4 kv = *(const float4*)&Kt[kk][c0 + q4*4];
                s[q4*4+0] += qv * kv.x;
                s[q4*4+1] += qv * kv.y;
                s[q4*4+2] += qv * kv.z;
                s[q4*4+3] += qv * kv.w;
            }
        }

        const float sc = 0.125f;
        const bool diag = (j == qi);
        float rmax = -1e30f;
        #pragma unroll
        for (int i = 0; i < 16; i++) {
            float sv = s[i] * sc;
            if (diag && (kv0 + c0 + i > q0 + r)) sv = -1e30f;
            s[i] = sv;
            rmax = fmaxf(rmax, sv);
        }
        rmax = fmaxf(rmax, __shfl_xor_sync(0xffffffffu, rmax, 1));
        rmax = fmaxf(rmax, __shfl_xor_sync(0xffffffffu, rmax, 2));

        float mnew  = fmaxf(m, rmax);
        float alpha = __expf(m - mnew);
        float rsum = 0.f;
        #pragma unroll
        for (int i = 0; i < 16; i++) {
            float p = __expf(s[i] - mnew);
            s[i] = p;
            rsum += p;
        }
        rsum += __shfl_xor_sync(0xffffffffu, rsum, 1);
        rsum += __shfl_xor_sync(0xffffffffu, rsum, 2);
        l = l * alpha + rsum;
        m = mnew;
        #pragma unroll
        for (int i = 0; i < 16; i++) o[i] *= alpha;

        #pragma unroll
        for (int q4 = 0; q4 < 4; q4++) {
            float4 t = make_float4(s[q4*4+0], s[q4*4+1], s[q4*4+2], s[q4*4+3]);
            *(float4*)&Ps[r][c0 + q4*4] = t;
        }
        __syncthreads();

        #pragma unroll 8
        for (int c = 0; c < 64; c++) {
            float pv = Ps[r][c];
            #pragma unroll
            for (int q4 = 0; q4 < 4; q4++) {
                float4 vv = *(const float4*)&Vs[c][c0 + q4*4];
                o[q4*4+0] += pv * vv.x;
                o[q4*4+1] += pv * vv.y;
                o[q4*4+2] += pv * vv.z;
                o[q4*4+3] += pv * vv.w;
            }
        }
    }

    const float inv = 1.f / l;
    const int b = bh / NHEAD, h = bh % NHEAD;
    float* outp = g_attn + ((size_t)(b*SEQ + q0 + r)) * D_MODEL + h*DHEAD + c0;
    #pragma unroll
    for (int q4 = 0; q4 < 4; q4++) {
        float4 t = make_float4(o[q4*4+0]*inv, o[q4*4+1]*inv,
                               o[q4*4+2]*inv, o[q4*4+3]*inv);
        *(float4*)&outp[q4*4] = t;
    }
}

// ---------------------------------------------------------------------------
extern "C" void kernel_launch(void* const* d_in, const int* in_sizes, int n_in,
                              void* d_out, int out_size)
{
    const float* x  = (const float*)d_in[0];
    const float* Wq = (const float*)d_in[1];
    const float* bq = (const float*)d_in[2];
    const float* Wk = (const float*)d_in[3];
    const float* bk = (const float*)d_in[4];
    const float* Wv = (const float*)d_in[5];
    const float* bv = (const float*)d_in[6];
    const float* Wo = (const float*)d_in[7];
    const float* bo = (const float*)d_in[8];

    float *qp, *kp, *vp, *ap;
    cudaGetSymbolAddress((void**)&qp, g_q);
    cudaGetSymbolAddress((void**)&kp, g_k);
    cudaGetSymbolAddress((void**)&vp, g_v);
    cudaGetSymbolAddress((void**)&ap, g_attn);

    cudaFuncSetAttribute(gemm_mma<true>,
                         cudaFuncAttributeMaxDynamicSharedMemorySize, GEMM_SMEM_BYTES);
    cudaFuncSetAttribute(gemm_mma<false>,
                         cudaFuncAttributeMaxDynamicSharedMemorySize, GEMM_SMEM_BYTES);

    dim3 gg(D_MODEL/128, NTOK/128);   // (8, 64)
    gemm_mma<true ><<<gg, 256, GEMM_SMEM_BYTES>>>(x, Wq, bq, qp);
    gemm_mma<true ><<<gg, 256, GEMM_SMEM_BYTES>>>(x, Wk, bk, kp);
    gemm_mma<true ><<<gg, 256, GEMM_SMEM_BYTES>>>(x, Wv, bv, vp);

    const int smem_bytes = ATTN_SMEM_FLOATS * (int)sizeof(float);  // 69632
    cudaFuncSetAttribute(attn_kernel,
                         cudaFuncAttributeMaxDynamicSharedMemorySize, smem_bytes);
    attn_kernel<<<dim3(SEQ/64, BATCH*NHEAD), 256, smem_bytes>>>();

    gemm_mma<false><<<gg, 256, GEMM_SMEM_BYTES>>>(ap, Wo, bo, (float*)d_out);
}

// round 4
// speedup vs baseline: 6.2012x; 4.9247x over previous
#include <cuda_runtime.h>
#include <cuda_bf16.h>
#include <math.h>
#include <cstdint>

#define D_MODEL 1024
#define NHEAD   16
#define DHEAD   64
#define BATCH   4
#define SEQ     2048
#define NTOK    (BATCH*SEQ)   // 8192
#define KDIM    1024

// Scratch (allocation-free rule: __device__ globals)
__device__ float g_q[BATCH*NHEAD*SEQ*DHEAD];    // [B,H,S,Dh]
__device__ float g_k[BATCH*NHEAD*SEQ*DHEAD];
__device__ float g_v[BATCH*NHEAD*SEQ*DHEAD];
__device__ float g_attn[NTOK*D_MODEL];          // [B,S,D]

__device__ __forceinline__ uint32_t f2tf32(float f) {
    uint32_t r;
    asm("cvt.rna.tf32.f32 %0, %1;" : "=r"(r) : "f"(f));
    return r;
}

// D += A*B, m16n8k8 tf32 (A row-major 16x8, B col-major 8x8)
__device__ __forceinline__ void mma_tf32(float* c, const uint32_t* a, const uint32_t* b) {
    asm volatile(
        "mma.sync.aligned.m16n8k8.row.col.f32.tf32.tf32.f32 "
        "{%0,%1,%2,%3}, {%4,%5,%6,%7}, {%8,%9}, {%0,%1,%2,%3};"
        : "+f"(c[0]), "+f"(c[1]), "+f"(c[2]), "+f"(c[3])
        : "r"(a[0]), "r"(a[1]), "r"(a[2]), "r"(a[3]), "r"(b[0]), "r"(b[1]));
}

// ---------------------------------------------------------------------------
// tf32 mma.sync GEMM (NT): Y[n,m] = sum_k A[n,k]*W[m,k] + bias[m]
// CTA tile 128x128, BK=32, 256 threads (8 warps, 2x4), warp tile 64x32.
// ---------------------------------------------------------------------------
#define BK       32
#define KCHUNKS  (KDIM / BK)      // 32
#define ROWPAD   36               // floats per smem row (conflict-free frag LDS)
#define TILE_FLOATS (128 * ROWPAD)
#define GEMM_SMEM_BYTES (4 * TILE_FLOATS * 4)   // 73728

template<bool HEAD_LAYOUT>
__global__ __launch_bounds__(256)
void gemm_mma(const float* __restrict__ A, const float* __restrict__ W,
              const float* __restrict__ bias, float* __restrict__ Y)
{
    extern __shared__ __align__(16) float smem[];
    float* As = smem;                    // [2][128][ROWPAD]
    float* Ws = smem + 2 * TILE_FLOATS;  // [2][128][ROWPAD]

    const int tid    = threadIdx.x;
    const int lane   = tid & 31;
    const int wid    = tid >> 5;
    const int warp_m = wid & 1;          // 0..1  (64-row groups)
    const int warp_n = wid >> 1;         // 0..3  (32-col groups)
    const int gr     = lane >> 2;        // 0..7
    const int t4     = lane & 3;         // 0..3

    const int bn = blockIdx.y * 128;     // token rows
    const int bm = blockIdx.x * 128;     // output cols

    const float* Ag = A + (size_t)bn * KDIM;
    const float* Wg = W + (size_t)bm * KDIM;

    const int r0 = tid >> 3;
    const int c4 = tid & 7;

    float4 pa[4], pw[4];
    auto ldg = [&](int c) {
        const int koff = c * BK + c4 * 4;
        #pragma unroll
        for (int p = 0; p < 4; p++) {
            pa[p] = *(const float4*)(Ag + (size_t)(r0 + p*32) * KDIM + koff);
            pw[p] = *(const float4*)(Wg + (size_t)(r0 + p*32) * KDIM + koff);
        }
    };
    auto sts = [&](int buf) {
        float* ab = As + buf * TILE_FLOATS;
        float* wb = Ws + buf * TILE_FLOATS;
        #pragma unroll
        for (int p = 0; p < 4; p++) {
            const int off = (r0 + p*32) * ROWPAD + c4 * 4;
            ab[off+0] = __uint_as_float(f2tf32(pa[p].x));
            ab[off+1] = __uint_as_float(f2tf32(pa[p].y));
            ab[off+2] = __uint_as_float(f2tf32(pa[p].z));
            ab[off+3] = __uint_as_float(f2tf32(pa[p].w));
            wb[off+0] = __uint_as_float(f2tf32(pw[p].x));
            wb[off+1] = __uint_as_float(f2tf32(pw[p].y));
            wb[off+2] = __uint_as_float(f2tf32(pw[p].z));
            wb[off+3] = __uint_as_float(f2tf32(pw[p].w));
        }
    };

    float acc[4][4][4];
    #pragma unroll
    for (int mt = 0; mt < 4; mt++)
        #pragma unroll
        for (int nt = 0; nt < 4; nt++)
            #pragma unroll
            for (int i = 0; i < 4; i++) acc[mt][nt][i] = 0.f;

    ldg(0); sts(0);
    __syncthreads();

    for (int c = 0; c < KCHUNKS; c++) {
        const int buf = c & 1;
        if (c + 1 < KCHUNKS) ldg(c + 1);

        const float* Ab = As + buf * TILE_FLOATS + (warp_m * 64) * ROWPAD;
        const float* Wb = Ws + buf * TILE_FLOATS + (warp_n * 32) * ROWPAD;
        #pragma unroll
        for (int kk = 0; kk < 4; kk++) {
            const int k0 = kk * 8 + t4;
            uint32_t af[4][4], bf[4][2];
            #pragma unroll
            for (int mt = 0; mt < 4; mt++) {
                const int base = (mt * 16 + gr) * ROWPAD + k0;
                af[mt][0] = __float_as_uint(Ab[base]);
                af[mt][1] = __float_as_uint(Ab[base + 8 * ROWPAD]);
                af[mt][2] = __float_as_uint(Ab[base + 4]);
                af[mt][3] = __float_as_uint(Ab[base + 8 * ROWPAD + 4]);
            }
            #pragma unroll
            for (int nt = 0; nt < 4; nt++) {
                const int base = (nt * 8 + gr) * ROWPAD + k0;
                bf[nt][0] = __float_as_uint(Wb[base]);
                bf[nt][1] = __float_as_uint(Wb[base + 4]);
            }
            #pragma unroll
            for (int mt = 0; mt < 4; mt++)
                #pragma unroll
                for (int nt = 0; nt < 4; nt++)
                    mma_tf32(acc[mt][nt], af[mt], bf[nt]);
        }

        if (c + 1 < KCHUNKS) sts(1 - buf);
        __syncthreads();
    }

    #pragma unroll
    for (int nt = 0; nt < 4; nt++) {
        const int col = bm + warp_n * 32 + nt * 8 + t4 * 2;
        const float2 bv = *(const float2*)&bias[col];
        #pragma unroll
        for (int mt = 0; mt < 4; mt++) {
            const int row = bn + warp_m * 64 + mt * 16 + gr;
            float2 v0 = make_float2(acc[mt][nt][0] + bv.x, acc[mt][nt][1] + bv.y);
            float2 v1 = make_float2(acc[mt][nt][2] + bv.x, acc[mt][nt][3] + bv.y);
            if (HEAD_LAYOUT) {
                const int h = col / DHEAD, d = col % DHEAD;
                const int bb0 = row / SEQ, s0 = row % SEQ;
                const int bb1 = (row + 8) / SEQ, s1 = (row + 8) % SEQ;
                *(float2*)&Y[(((size_t)(bb0*NHEAD + h)*SEQ + s0)*DHEAD) + d] = v0;
                *(float2*)&Y[(((size_t)(bb1*NHEAD + h)*SEQ + s1)*DHEAD) + d] = v1;
            } else {
                *(float2*)&Y[(size_t)row * D_MODEL + col] = v0;
                *(float2*)&Y[(size_t)(row + 8) * D_MODEL + col] = v1;
            }
        }
    }
}

// ---------------------------------------------------------------------------
// Causal flash attention via tf32 mma.sync. Br=128, Bc=64, Dh=64.
// 256 threads = 8 warps; warp w owns q rows [16w, 16w+16).
// Q pre-scaled by 1/8, resident in registers as tf32 A-fragments.
// K/V staged in SMEM (pad 72: conflict-free for both fragment patterns).
// P staged per-warp-private through Ps (no CTA sync needed, only syncwarp).
// ---------------------------------------------------------------------------
#define ABR   128
#define ABC   64
#define APAD  72
#define ATTN_SMEM_FLOATS (2*ABC*APAD + ABR*APAD)   // 18432 floats = 73728 B

__global__ __launch_bounds__(256, 2)
void attn_mma()
{
    extern __shared__ __align__(16) float sm[];
    float* Ks = sm;                   // [64][72]
    float* Vs = sm + ABC*APAD;        // [64][72]
    float* Ps = sm + 2*ABC*APAD;      // [128][72]; also Q staging at start

    const int bh = blockIdx.y;
    const int qb = (int)gridDim.x - 1 - (int)blockIdx.x;   // heavy blocks first
    const int q0 = qb * ABR;

    const float* Qg = g_q + (size_t)bh * SEQ * DHEAD;
    const float* Kg = g_k + (size_t)bh * SEQ * DHEAD;
    const float* Vg = g_v + (size_t)bh * SEQ * DHEAD;

    const int tid  = threadIdx.x;
    const int lane = tid & 31;
    const int wid  = tid >> 5;
    const int gr   = lane >> 2;    // 0..7
    const int t4   = lane & 3;     // 0..3
    const int r0   = wid * 16;     // warp's q-row base within tile

    // ---- stage Q (scaled by 1/8, tf32-rounded) into Ps, then load frags ----
    {
        const int r = tid >> 1, h = (tid & 1) * 32;
        const float* src = Qg + (size_t)(q0 + r) * DHEAD + h;
        float* dst = Ps + r * APAD + h;
        #pragma unroll
        for (int i = 0; i < 8; i++) {
            float4 v = *(const float4*)(src + i * 4);
            float4 t;
            t.x = __uint_as_float(f2tf32(v.x * 0.125f));
            t.y = __uint_as_float(f2tf32(v.y * 0.125f));
            t.z = __uint_as_float(f2tf32(v.z * 0.125f));
            t.w = __uint_as_float(f2tf32(v.w * 0.125f));
            *(float4*)(dst + i * 4) = t;
        }
    }
    __syncthreads();

    uint32_t Qf[8][4];
    #pragma unroll
    for (int kk = 0; kk < 8; kk++) {
        Qf[kk][0] = __float_as_uint(Ps[(r0+gr  )*APAD + kk*8 + t4    ]);
        Qf[kk][1] = __float_as_uint(Ps[(r0+gr+8)*APAD + kk*8 + t4    ]);
        Qf[kk][2] = __float_as_uint(Ps[(r0+gr  )*APAD + kk*8 + t4 + 4]);
        Qf[kk][3] = __float_as_uint(Ps[(r0+gr+8)*APAD + kk*8 + t4 + 4]);
    }
    // After this, warp w only touches Ps rows [r0, r0+16) — private; no sync.

    float m0 = -1e30f, m1 = -1e30f, l0 = 0.f, l1 = 0.f;
    float oacc[8][4];
    #pragma unroll
    for (int nt = 0; nt < 8; nt++)
        #pragma unroll
        for (int i = 0; i < 4; i++) oacc[nt][i] = 0.f;

    const int rowa = q0 + r0 + gr;
    const int rowb = rowa + 8;
    const int jmax = 2 * qb + 1;

    for (int j = 0; j <= jmax; j++) {
        const int kv0 = j * ABC;
        __syncthreads();   // all warps done reading prior K/V
        {
            const int r = tid >> 2, cb = (tid & 3) * 16;
            const float* ks = Kg + (size_t)(kv0 + r) * DHEAD + cb;
            const float* vs = Vg + (size_t)(kv0 + r) * DHEAD + cb;
            float* kd = Ks + r * APAD + cb;
            float* vd = Vs + r * APAD + cb;
            #pragma unroll
            for (int i = 0; i < 4; i++) {
                float4 a = *(const float4*)(ks + i * 4);
                float4 b = *(const float4*)(vs + i * 4);
                float4 ta, tb;
                ta.x = __uint_as_float(f2tf32(a.x)); ta.y = __uint_as_float(f2tf32(a.y));
                ta.z = __uint_as_float(f2tf32(a.z)); ta.w = __uint_as_float(f2tf32(a.w));
                tb.x = __uint_as_float(f2tf32(b.x)); tb.y = __uint_as_float(f2tf32(b.y));
                tb.z = __uint_as_float(f2tf32(b.z)); tb.w = __uint_as_float(f2tf32(b.w));
                *(float4*)(kd + i * 4) = ta;
                *(float4*)(vd + i * 4) = tb;
            }
        }
        __syncthreads();

        // ---- scores S = Qs * K^T (already includes 1/8 scale via Q) ----
        float sacc[8][4];
        #pragma unroll
        for (int nt = 0; nt < 8; nt++)
            #pragma unroll
            for (int i = 0; i < 4; i++) sacc[nt][i] = 0.f;

        #pragma unroll
        for (int kk = 0; kk < 8; kk++) {
            #pragma unroll
            for (int nt = 0; nt < 8; nt++) {
                uint32_t bf[2];
                const int base = (nt*8 + gr) * APAD + kk*8 + t4;
                bf[0] = __float_as_uint(Ks[base]);
                bf[1] = __float_as_uint(Ks[base + 4]);
                mma_tf32(sacc[nt], Qf[kk], bf);
            }
        }

        // ---- causal mask (only last two tiles of this q-block need it) ----
        if (kv0 + ABC - 1 > q0) {
            #pragma unroll
            for (int nt = 0; nt < 8; nt++) {
                const int col0 = kv0 + nt*8 + 2*t4;
                if (col0     > rowa) sacc[nt][0] = -1e30f;
                if (col0 + 1 > rowa) sacc[nt][1] = -1e30f;
                if (col0     > rowb) sacc[nt][2] = -1e30f;
                if (col0 + 1 > rowb) sacc[nt][3] = -1e30f;
            }
        }

        // ---- online softmax (2 rows per thread) ----
        float mx0 = -1e30f, mx1 = -1e30f;
        #pragma unroll
        for (int nt = 0; nt < 8; nt++) {
            mx0 = fmaxf(mx0, fmaxf(sacc[nt][0], sacc[nt][1]));
            mx1 = fmaxf(mx1, fmaxf(sacc[nt][2], sacc[nt][3]));
        }
        mx0 = fmaxf(mx0, __shfl_xor_sync(0xffffffffu, mx0, 1));
        mx0 = fmaxf(mx0, __shfl_xor_sync(0xffffffffu, mx0, 2));
        mx1 = fmaxf(mx1, __shfl_xor_sync(0xffffffffu, mx1, 1));
        mx1 = fmaxf(mx1, __shfl_xor_sync(0xffffffffu, mx1, 2));

        const float mn0 = fmaxf(m0, mx0), mn1 = fmaxf(m1, mx1);
        const float a0 = __expf(m0 - mn0), a1 = __expf(m1 - mn1);
        float s0 = 0.f, s1 = 0.f;
        #pragma unroll
        for (int nt = 0; nt < 8; nt++) {
            sacc[nt][0] = __expf(sacc[nt][0] - mn0);
            sacc[nt][1] = __expf(sacc[nt][1] - mn0);
            sacc[nt][2] = __expf(sacc[nt][2] - mn1);
            sacc[nt][3] = __expf(sacc[nt][3] - mn1);
            s0 += sacc[nt][0] + sacc[nt][1];
            s1 += sacc[nt][2] + sacc[nt][3];
        }
        s0 += __shfl_xor_sync(0xffffffffu, s0, 1);
        s0 += __shfl_xor_sync(0xffffffffu, s0, 2);
        s1 += __shfl_xor_sync(0xffffffffu, s1, 1);
        s1 += __shfl_xor_sync(0xffffffffu, s1, 2);
        l0 = l0 * a0 + s0;  m0 = mn0;
        l1 = l1 * a1 + s1;  m1 = mn1;
        #pragma unroll
        for (int nt = 0; nt < 8; nt++) {
            oacc[nt][0] *= a0; oacc[nt][1] *= a0;
            oacc[nt][2] *= a1; oacc[nt][3] *= a1;
        }

        // ---- stage P (tf32 bits) into warp-private Ps rows ----
        #pragma unroll
        for (int nt = 0; nt < 8; nt++) {
            float2 pa, pb;
            pa.x = __uint_as_float(f2tf32(sacc[nt][0]));
            pa.y = __uint_as_float(f2tf32(sacc[nt][1]));
            pb.x = __uint_as_float(f2tf32(sacc[nt][2]));
            pb.y = __uint_as_float(f2tf32(sacc[nt][3]));
            *(float2*)&Ps[(r0+gr  )*APAD + nt*8 + 2*t4] = pa;
            *(float2*)&Ps[(r0+gr+8)*APAD + nt*8 + 2*t4] = pb;
        }
        __syncwarp();

        // ---- O += P * V ----
        #pragma unroll
        for (int kk = 0; kk < 8; kk++) {
            uint32_t pf[4];
            pf[0] = __float_as_uint(Ps[(r0+gr  )*APAD + kk*8 + t4    ]);
            pf[1] = __float_as_uint(Ps[(r0+gr+8)*APAD + kk*8 + t4    ]);
            pf[2] = __float_as_uint(Ps[(r0+gr  )*APAD + kk*8 + t4 + 4]);
            pf[3] = __float_as_uint(Ps[(r0+gr+8)*APAD + kk*8 + t4 + 4]);
            #pragma unroll
            for (int nt = 0; nt < 8; nt++) {
                uint32_t bf[2];
                bf[0] = __float_as_uint(Vs[(kk*8 + t4    )*APAD + nt*8 + gr]);
                bf[1] = __float_as_uint(Vs[(kk*8 + t4 + 4)*APAD + nt*8 + gr]);
                mma_tf32(oacc[nt], pf, bf);
            }
        }
        __syncwarp();   // P reads done before next iter's P writes
    }

    // ---- normalize + write [B,S,D] ----
    const float inv0 = 1.f / l0, inv1 = 1.f / l1;
    const int b = bh >> 4, h = bh & 15;
    #pragma unroll
    for (int nt = 0; nt < 8; nt++) {
        const int col = h * DHEAD + nt*8 + 2*t4;
        float2 v0 = make_float2(oacc[nt][0] * inv0, oacc[nt][1] * inv0);
        float2 v1 = make_float2(oacc[nt][2] * inv1, oacc[nt][3] * inv1);
        *(float2*)&g_attn[((size_t)(b*SEQ + rowa)) * D_MODEL + col] = v0;
        *(float2*)&g_attn[((size_t)(b*SEQ + rowb)) * D_MODEL + col] = v1;
    }
}

// ---------------------------------------------------------------------------
extern "C" void kernel_launch(void* const* d_in, const int* in_sizes, int n_in,
                              void* d_out, int out_size)
{
    const float* x  = (const float*)d_in[0];
    const float* Wq = (const float*)d_in[1];
    const float* bq = (const float*)d_in[2];
    const float* Wk = (const float*)d_in[3];
    const float* bk = (const float*)d_in[4];
    const float* Wv = (const float*)d_in[5];
    const float* bv = (const float*)d_in[6];
    const float* Wo = (const float*)d_in[7];
    const float* bo = (const float*)d_in[8];

    float *qp, *kp, *vp, *ap;
    cudaGetSymbolAddress((void**)&qp, g_q);
    cudaGetSymbolAddress((void**)&kp, g_k);
    cudaGetSymbolAddress((void**)&vp, g_v);
    cudaGetSymbolAddress((void**)&ap, g_attn);

    cudaFuncSetAttribute(gemm_mma<true>,
                         cudaFuncAttributeMaxDynamicSharedMemorySize, GEMM_SMEM_BYTES);
    cudaFuncSetAttribute(gemm_mma<false>,
                         cudaFuncAttributeMaxDynamicSharedMemorySize, GEMM_SMEM_BYTES);

    dim3 gg(D_MODEL/128, NTOK/128);   // (8, 64)
    gemm_mma<true ><<<gg, 256, GEMM_SMEM_BYTES>>>(x, Wq, bq, qp);
    gemm_mma<true ><<<gg, 256, GEMM_SMEM_BYTES>>>(x, Wk, bk, kp);
    gemm_mma<true ><<<gg, 256, GEMM_SMEM_BYTES>>>(x, Wv, bv, vp);

    const int attn_smem = ATTN_SMEM_FLOATS * (int)sizeof(float);  // 73728
    cudaFuncSetAttribute(attn_mma,
                         cudaFuncAttributeMaxDynamicSharedMemorySize, attn_smem);
    attn_mma<<<dim3(SEQ/ABR, BATCH*NHEAD), 256, attn_smem>>>();

    gemm_mma<false><<<gg, 256, GEMM_SMEM_BYTES>>>(ap, Wo, bo, (float*)d_out);
}

// round 5
// speedup vs baseline: 9.9090x; 1.5979x over previous
#include <cuda_runtime.h>
#include <cuda_fp16.h>
#include <math.h>
#include <cstdint>

#define D_MODEL 1024
#define NHEAD   16
#define DHEAD   64
#define BATCH   4
#define SEQ     2048
#define NTOK    (BATCH*SEQ)   // 8192
#define KDIM    1024

// Scratch (allocation-free rule: __device__ globals)
__device__ float g_q[BATCH*NHEAD*SEQ*DHEAD];    // [B,H,S,Dh]
__device__ float g_k[BATCH*NHEAD*SEQ*DHEAD];
__device__ float g_v[BATCH*NHEAD*SEQ*DHEAD];
__device__ float g_attn[NTOK*D_MODEL];          // [B,S,D]

// ---------------------------------------------------------------------------
// helpers
// ---------------------------------------------------------------------------
__device__ __forceinline__ uint32_t packh2(float a, float b) {
    __half2 h = __floats2half2_rn(a, b);
    return *reinterpret_cast<uint32_t*>(&h);
}
__device__ __forceinline__ void mma_f16(float* c, const uint32_t* a, const uint32_t* b) {
    asm volatile(
        "mma.sync.aligned.m16n8k16.row.col.f32.f16.f16.f32 "
        "{%0,%1,%2,%3}, {%4,%5,%6,%7}, {%8,%9}, {%0,%1,%2,%3};"
        : "+f"(c[0]), "+f"(c[1]), "+f"(c[2]), "+f"(c[3])
        : "r"(a[0]), "r"(a[1]), "r"(a[2]), "r"(a[3]), "r"(b[0]), "r"(b[1]));
}
__device__ __forceinline__ void ldmx4(uint32_t* r, const void* p) {
    uint32_t a = (uint32_t)__cvta_generic_to_shared(p);
    asm volatile("ldmatrix.sync.aligned.m8n8.x4.shared.b16 {%0,%1,%2,%3}, [%4];"
                 : "=r"(r[0]), "=r"(r[1]), "=r"(r[2]), "=r"(r[3]) : "r"(a));
}
__device__ __forceinline__ void ldmx4t(uint32_t* r, const void* p) {
    uint32_t a = (uint32_t)__cvta_generic_to_shared(p);
    asm volatile("ldmatrix.sync.aligned.m8n8.x4.trans.shared.b16 {%0,%1,%2,%3}, [%4];"
                 : "=r"(r[0]), "=r"(r[1]), "=r"(r[2]), "=r"(r[3]) : "r"(a));
}

// ---------------------------------------------------------------------------
// fp16 mma GEMM (NT): Y[n,m] = sum_k A[n,k]*W[m,k] + bias[m]
// CTA tile 128x128, BK=32, 256 threads (8 warps, 2x4), warp tile 64x32.
// ---------------------------------------------------------------------------
#define BK    32
#define KCH   (KDIM / BK)      // 32
#define GPAD  40               // halves per smem row

template<bool HEAD_LAYOUT>
__global__ __launch_bounds__(256)
void gemm_h(const float* __restrict__ A, const float* __restrict__ W,
            const float* __restrict__ bias, float* __restrict__ Y)
{
    __shared__ __align__(16) __half As[2][128][GPAD];
    __shared__ __align__(16) __half Ws[2][128][GPAD];

    const int tid    = threadIdx.x;
    const int lane   = tid & 31;
    const int wid    = tid >> 5;
    const int warp_m = wid & 1;          // 0..1  (64-row groups)
    const int warp_n = wid >> 1;         // 0..3  (32-col groups)
    const int gr     = lane >> 2;
    const int t4     = lane & 3;

    // ldmatrix lane address components
    const int lr   = lane & 7;
    const int arow = ((lane >> 3) & 1) * 8 + lr;   // A: m1/m3 -> row+8
    const int acol = ((lane >> 4) & 1) * 8;        // A: m2/m3 -> col+8
    const int brow = ((lane >> 4) & 1) * 8 + lr;   // B: m2/m3 -> row+8
    const int bcol = ((lane >> 3) & 1) * 8;        // B: m1/m3 -> col+8

    const int bn = blockIdx.y * 128;
    const int bm = blockIdx.x * 128;

    const float* Ag = A + (size_t)bn * KDIM;
    const float* Wg = W + (size_t)bm * KDIM;

    const int r0 = tid >> 3;       // 0..31
    const int c4 = tid & 7;        // float4 within 32-float chunk row

    float4 pa[4], pw[4];
    auto ldg = [&](int c) {
        const int koff = c * BK + c4 * 4;
        #pragma unroll
        for (int p = 0; p < 4; p++) {
            pa[p] = *(const float4*)(Ag + (size_t)(r0 + p*32) * KDIM + koff);
            pw[p] = *(const float4*)(Wg + (size_t)(r0 + p*32) * KDIM + koff);
        }
    };
    auto sts = [&](int buf) {
        #pragma unroll
        for (int p = 0; p < 4; p++) {
            const int r = r0 + p*32, cc = c4 * 4;
            uint2 ua, uw;
            ua.x = packh2(pa[p].x, pa[p].y);  ua.y = packh2(pa[p].z, pa[p].w);
            uw.x = packh2(pw[p].x, pw[p].y);  uw.y = packh2(pw[p].z, pw[p].w);
            *(uint2*)&As[buf][r][cc] = ua;
            *(uint2*)&Ws[buf][r][cc] = uw;
        }
    };

    float acc[4][4][4];
    #pragma unroll
    for (int mt = 0; mt < 4; mt++)
        #pragma unroll
        for (int nt = 0; nt < 4; nt++)
            #pragma unroll
            for (int i = 0; i < 4; i++) acc[mt][nt][i] = 0.f;

    ldg(0); sts(0);
    __syncthreads();

    for (int c = 0; c < KCH; c++) {
        const int buf = c & 1;
        if (c + 1 < KCH) ldg(c + 1);

        #pragma unroll
        for (int kk = 0; kk < 2; kk++) {
            const int k0 = kk * 16;
            uint32_t af[4][4], bb[2][4];
            #pragma unroll
            for (int mt = 0; mt < 4; mt++)
                ldmx4(af[mt], &As[buf][warp_m*64 + mt*16 + arow][k0 + acol]);
            #pragma unroll
            for (int np = 0; np < 2; np++)
                ldmx4(bb[np], &Ws[buf][warp_n*32 + np*16 + brow][k0 + bcol]);
            #pragma unroll
            for (int mt = 0; mt < 4; mt++)
                #pragma unroll
                for (int nt = 0; nt < 4; nt++)
                    mma_f16(acc[mt][nt], af[mt], &bb[nt >> 1][(nt & 1) * 2]);
        }

        if (c + 1 < KCH) sts(1 - buf);
        __syncthreads();
    }

    #pragma unroll
    for (int nt = 0; nt < 4; nt++) {
        const int col = bm + warp_n * 32 + nt * 8 + t4 * 2;
        const float2 bv = *(const float2*)&bias[col];
        #pragma unroll
        for (int mt = 0; mt < 4; mt++) {
            const int row = bn + warp_m * 64 + mt * 16 + gr;
            float2 v0 = make_float2(acc[mt][nt][0] + bv.x, acc[mt][nt][1] + bv.y);
            float2 v1 = make_float2(acc[mt][nt][2] + bv.x, acc[mt][nt][3] + bv.y);
            if (HEAD_LAYOUT) {
                const int h = col / DHEAD, d = col % DHEAD;
                const int bb0 = row / SEQ, s0 = row % SEQ;
                const int bb1 = (row + 8) / SEQ, s1 = (row + 8) % SEQ;
                *(float2*)&Y[(((size_t)(bb0*NHEAD + h)*SEQ + s0)*DHEAD) + d] = v0;
                *(float2*)&Y[(((size_t)(bb1*NHEAD + h)*SEQ + s1)*DHEAD) + d] = v1;
            } else {
                *(float2*)&Y[(size_t)row * D_MODEL + col] = v0;
                *(float2*)&Y[(size_t)(row + 8) * D_MODEL + col] = v1;
            }
        }
    }
}

// ---------------------------------------------------------------------------
// Causal flash attention, fp16 mma. Br=128, Bc=64, Dh=64, 256 threads.
// Warp w owns q rows [16w,16w+16). Q resident as fp16 A-frags (pre-scaled).
// QK C-frag layout == PV A-frag layout -> P stays in registers.
// V B-frags via ldmatrix.trans (no smem transpose).
// ---------------------------------------------------------------------------
#define ABR   128
#define ABC   64
#define APAD  72

__global__ __launch_bounds__(256, 2)
void attn_h()
{
    __shared__ __align__(16) __half Ks[ABC][APAD];
    __shared__ __align__(16) __half Vs[ABC][APAD];
    __shared__ __align__(16) __half Qs[ABR][APAD];

    const int bh = blockIdx.y;
    const int qb = (int)gridDim.x - 1 - (int)blockIdx.x;   // heavy blocks first
    const int q0 = qb * ABR;

    const float* Qg = g_q + (size_t)bh * SEQ * DHEAD;
    const float* Kg = g_k + (size_t)bh * SEQ * DHEAD;
    const float* Vg = g_v + (size_t)bh * SEQ * DHEAD;

    const int tid  = threadIdx.x;
    const int lane = tid & 31;
    const int wid  = tid >> 5;
    const int gr   = lane >> 2;
    const int t4   = lane & 3;
    const int r0   = wid * 16;

    const int lr   = lane & 7;
    const int arow = ((lane >> 3) & 1) * 8 + lr;
    const int acol = ((lane >> 4) & 1) * 8;
    const int brow = ((lane >> 4) & 1) * 8 + lr;   // K B-frags (non-trans)
    const int bcol = ((lane >> 3) & 1) * 8;
    const int trow = ((lane >> 3) & 1) * 8 + lr;   // V B-frags (trans): m1/m3 row+8
    const int tcol = ((lane >> 4) & 1) * 8;        //                    m2/m3 col+8

    // ---- stage Q (scaled 1/8, fp16) ----
    {
        const int r = tid >> 1, h = (tid & 1) * 32;
        const float* src = Qg + (size_t)(q0 + r) * DHEAD + h;
        #pragma unroll
        for (int i = 0; i < 8; i++) {
            float4 v = *(const float4*)(src + i * 4);
            uint2 u;
            u.x = packh2(v.x * 0.125f, v.y * 0.125f);
            u.y = packh2(v.z * 0.125f, v.w * 0.125f);
            *(uint2*)&Qs[r][h + i * 4] = u;
        }
    }
    __syncthreads();

    uint32_t Qf[4][4];
    #pragma unroll
    for (int kk = 0; kk < 4; kk++)
        ldmx4(Qf[kk], &Qs[r0 + arow][kk * 16 + acol]);

    float m0 = -1e30f, m1 = -1e30f, l0 = 0.f, l1 = 0.f;
    float oacc[8][4];
    #pragma unroll
    for (int nt = 0; nt < 8; nt++)
        #pragma unroll
        for (int i = 0; i < 4; i++) oacc[nt][i] = 0.f;

    const int rowa = q0 + r0 + gr;
    const int rowb = rowa + 8;
    const int jmax = 2 * qb + 1;

    for (int j = 0; j <= jmax; j++) {
        const int kv0 = j * ABC;
        __syncthreads();   // prior tile's reads complete
        {
            const int r = tid >> 2, cb = (tid & 3) * 16;
            const float* ks = Kg + (size_t)(kv0 + r) * DHEAD + cb;
            const float* vs = Vg + (size_t)(kv0 + r) * DHEAD + cb;
            #pragma unroll
            for (int i = 0; i < 4; i++) {
                float4 a = *(const float4*)(ks + i * 4);
                float4 b = *(const float4*)(vs + i * 4);
                uint2 ua, ub;
                ua.x = packh2(a.x, a.y);  ua.y = packh2(a.z, a.w);
                ub.x = packh2(b.x, b.y);  ub.y = packh2(b.z, b.w);
                *(uint2*)&Ks[r][cb + i * 4] = ua;
                *(uint2*)&Vs[r][cb + i * 4] = ub;
            }
        }
        __syncthreads();

        // ---- S = Qs * K^T (1/8 folded into Q) ----
        float sacc[8][4];
        #pragma unroll
        for (int nt = 0; nt < 8; nt++)
            #pragma unroll
            for (int i = 0; i < 4; i++) sacc[nt][i] = 0.f;

        #pragma unroll
        for (int kk = 0; kk < 4; kk++) {
            #pragma unroll
            for (int np = 0; np < 4; np++) {
                uint32_t bb[4];
                ldmx4(bb, &Ks[np*16 + brow][kk*16 + bcol]);
                mma_f16(sacc[2*np    ], Qf[kk], &bb[0]);
                mma_f16(sacc[2*np + 1], Qf[kk], &bb[2]);
            }
        }

        // ---- causal mask ----
        if (kv0 + ABC - 1 > q0) {
            #pragma unroll
            for (int nt = 0; nt < 8; nt++) {
                const int col0 = kv0 + nt*8 + 2*t4;
                if (col0     > rowa) sacc[nt][0] = -1e30f;
                if (col0 + 1 > rowa) sacc[nt][1] = -1e30f;
                if (col0     > rowb) sacc[nt][2] = -1e30f;
                if (col0 + 1 > rowb) sacc[nt][3] = -1e30f;
            }
        }

        // ---- online softmax (rows gr, gr+8) ----
        float mx0 = -1e30f, mx1 = -1e30f;
        #pragma unroll
        for (int nt = 0; nt < 8; nt++) {
            mx0 = fmaxf(mx0, fmaxf(sacc[nt][0], sacc[nt][1]));
            mx1 = fmaxf(mx1, fmaxf(sacc[nt][2], sacc[nt][3]));
        }
        mx0 = fmaxf(mx0, __shfl_xor_sync(0xffffffffu, mx0, 1));
        mx0 = fmaxf(mx0, __shfl_xor_sync(0xffffffffu, mx0, 2));
        mx1 = fmaxf(mx1, __shfl_xor_sync(0xffffffffu, mx1, 1));
        mx1 = fmaxf(mx1, __shfl_xor_sync(0xffffffffu, mx1, 2));

        const float mn0 = fmaxf(m0, mx0), mn1 = fmaxf(m1, mx1);
        const float a0 = __expf(m0 - mn0), a1 = __expf(m1 - mn1);
        float s0 = 0.f, s1 = 0.f;
        #pragma unroll
        for (int nt = 0; nt < 8; nt++) {
            sacc[nt][0] = __expf(sacc[nt][0] - mn0);
            sacc[nt][1] = __expf(sacc[nt][1] - mn0);
            sacc[nt][2] = __expf(sacc[nt][2] - mn1);
            sacc[nt][3] = __expf(sacc[nt][3] - mn1);
            s0 += sacc[nt][0] + sacc[nt][1];
            s1 += sacc[nt][2] + sacc[nt][3];
        }
        s0 += __shfl_xor_sync(0xffffffffu, s0, 1);
        s0 += __shfl_xor_sync(0xffffffffu, s0, 2);
        s1 += __shfl_xor_sync(0xffffffffu, s1, 1);
        s1 += __shfl_xor_sync(0xffffffffu, s1, 2);
        l0 = l0 * a0 + s0;  m0 = mn0;
        l1 = l1 * a1 + s1;  m1 = mn1;
        #pragma unroll
        for (int nt = 0; nt < 8; nt++) {
            oacc[nt][0] *= a0; oacc[nt][1] *= a0;
            oacc[nt][2] *= a1; oacc[nt][3] *= a1;
        }

        // ---- O += P * V ; P packed from sacc regs (C-frag == A-frag) ----
        #pragma unroll
        for (int kk = 0; kk < 4; kk++) {
            uint32_t pf[4];
            pf[0] = packh2(sacc[2*kk    ][0], sacc[2*kk    ][1]);
            pf[1] = packh2(sacc[2*kk    ][2], sacc[2*kk    ][3]);
            pf[2] = packh2(sacc[2*kk + 1][0], sacc[2*kk + 1][1]);
            pf[3] = packh2(sacc[2*kk + 1][2], sacc[2*kk + 1][3]);
            #pragma unroll
            for (int np = 0; np < 4; np++) {
                uint32_t bt[4];
                ldmx4t(bt, &Vs[kk*16 + trow][np*16 + tcol]);
                mma_f16(oacc[2*np    ], pf, &bt[0]);
                mma_f16(oacc[2*np + 1], pf, &bt[2]);
            }
        }
    }

    // ---- normalize + write [B,S,D] ----
    const float inv0 = 1.f / l0, inv1 = 1.f / l1;
    const int b = bh >> 4, h = bh & 15;
    #pragma unroll
    for (int nt = 0; nt < 8; nt++) {
        const int col = h * DHEAD + nt*8 + 2*t4;
        float2 v0 = make_float2(oacc[nt][0] * inv0, oacc[nt][1] * inv0);
        float2 v1 = make_float2(oacc[nt][2] * inv1, oacc[nt][3] * inv1);
        *(float2*)&g_attn[((size_t)(b*SEQ + rowa)) * D_MODEL + col] = v0;
        *(float2*)&g_attn[((size_t)(b*SEQ + rowb)) * D_MODEL + col] = v1;
    }
}

// ---------------------------------------------------------------------------
extern "C" void kernel_launch(void* const* d_in, const int* in_sizes, int n_in,
                              void* d_out, int out_size)
{
    const float* x  = (const float*)d_in[0];
    const float* Wq = (const float*)d_in[1];
    const float* bq = (const float*)d_in[2];
    const float* Wk = (const float*)d_in[3];
    const float* bk = (const float*)d_in[4];
    const float* Wv = (const float*)d_in[5];
    const float* bv = (const float*)d_in[6];
    const float* Wo = (const float*)d_in[7];
    const float* bo = (const float*)d_in[8];

    float *qp, *kp, *vp, *ap;
    cudaGetSymbolAddress((void**)&qp, g_q);
    cudaGetSymbolAddress((void**)&kp, g_k);
    cudaGetSymbolAddress((void**)&vp, g_v);
    cudaGetSymbolAddress((void**)&ap, g_attn);

    dim3 gg(D_MODEL/128, NTOK/128);   // (8, 64)
    gemm_h<true ><<<gg, 256>>>(x, Wq, bq, qp);
    gemm_h<true ><<<gg, 256>>>(x, Wk, bk, kp);
    gemm_h<true ><<<gg, 256>>>(x, Wv, bv, vp);

    attn_h<<<dim3(SEQ/ABR, BATCH*NHEAD), 256>>>();

    gemm_h<false><<<gg, 256>>>(ap, Wo, bo, (float*)d_out);
}

// round 8
// speedup vs baseline: 13.6806x; 1.3806x over previous
#include <cuda_runtime.h>
#include <cuda_fp16.h>
#include <math.h>
#include <cstdint>

#define D_MODEL 1024
#define NHEAD   16
#define DHEAD   64
#define BATCH   4
#define SEQ     2048
#define NTOK    (BATCH*SEQ)   // 8192
#define KDIM    1024

// ---------------------------------------------------------------------------
// fp16 scratch (allocation-free rule: __device__ globals)
// ---------------------------------------------------------------------------
__device__ __half g_xh[(size_t)NTOK*KDIM];
__device__ __half g_wqh[(size_t)KDIM*D_MODEL];
__device__ __half g_wkh[(size_t)KDIM*D_MODEL];
__device__ __half g_wvh[(size_t)KDIM*D_MODEL];
__device__ __half g_woh[(size_t)KDIM*D_MODEL];
__device__ __half g_qh[(size_t)BATCH*NHEAD*SEQ*DHEAD];   // [B,H,S,Dh]
__device__ __half g_kh[(size_t)BATCH*NHEAD*SEQ*DHEAD];
__device__ __half g_vh[(size_t)BATCH*NHEAD*SEQ*DHEAD];
__device__ __half g_ah[(size_t)NTOK*D_MODEL];            // [B,S,D]

// ---------------------------------------------------------------------------
// helpers
// ---------------------------------------------------------------------------
__device__ __forceinline__ uint32_t packh2(float a, float b) {
    __half2 h = __floats2half2_rn(a, b);
    return *reinterpret_cast<uint32_t*>(&h);
}
__device__ __forceinline__ float ex2f(float x) {
    float y;
    asm("ex2.approx.ftz.f32 %0, %1;" : "=f"(y) : "f"(x));
    return y;
}
__device__ __forceinline__ void mma_f16(float* c, const uint32_t* a, const uint32_t* b) {
    asm volatile(
        "mma.sync.aligned.m16n8k16.row.col.f32.f16.f16.f32 "
        "{%0,%1,%2,%3}, {%4,%5,%6,%7}, {%8,%9}, {%0,%1,%2,%3};"
        : "+f"(c[0]), "+f"(c[1]), "+f"(c[2]), "+f"(c[3])
        : "r"(a[0]), "r"(a[1]), "r"(a[2]), "r"(a[3]), "r"(b[0]), "r"(b[1]));
}
__device__ __forceinline__ void ldmx4(uint32_t* r, const void* p) {
    uint32_t a = (uint32_t)__cvta_generic_to_shared(p);
    asm volatile("ldmatrix.sync.aligned.m8n8.x4.shared.b16 {%0,%1,%2,%3}, [%4];"
                 : "=r"(r[0]), "=r"(r[1]), "=r"(r[2]), "=r"(r[3]) : "r"(a));
}
__device__ __forceinline__ void ldmx4t(uint32_t* r, const void* p) {
    uint32_t a = (uint32_t)__cvta_generic_to_shared(p);
    asm volatile("ldmatrix.sync.aligned.m8n8.x4.trans.shared.b16 {%0,%1,%2,%3}, [%4];"
                 : "=r"(r[0]), "=r"(r[1]), "=r"(r[2]), "=r"(r[3]) : "r"(a));
}
__device__ __forceinline__ void cp16(void* s, const void* g) {
    uint32_t a = (uint32_t)__cvta_generic_to_shared(s);
    asm volatile("cp.async.cg.shared.global [%0], [%1], 16;" :: "r"(a), "l"(g) : "memory");
}
__device__ __forceinline__ void cp_commit() {
    asm volatile("cp.async.commit_group;" ::: "memory");
}
template<int N>
__device__ __forceinline__ void cp_wait() {
    asm volatile("cp.async.wait_group %0;" :: "n"(N) : "memory");
}

// ---------------------------------------------------------------------------
// fp32 -> fp16 conversion (8 elems/thread)
// ---------------------------------------------------------------------------
__global__ __launch_bounds__(256)
void cvt_f2h(const float* __restrict__ src, __half* __restrict__ dst, int n8)
{
    int i = blockIdx.x * 256 + threadIdx.x;
    if (i >= n8) return;
    float4 a = ((const float4*)src)[2*i];
    float4 b = ((const float4*)src)[2*i + 1];
    uint4 o;
    o.x = packh2(a.x, a.y);  o.y = packh2(a.z, a.w);
    o.z = packh2(b.x, b.y);  o.w = packh2(b.z, b.w);
    ((uint4*)dst)[i] = o;
}

// ---------------------------------------------------------------------------
// fp16 GEMM (NT), cp.async 3-stage: Y[n,m] = sum_k A[n,k]*W[m,k] + bias[m]
// CTA tile 128x128, BK=32 halves (= 64B/row = 4x16B chunks), 256 threads.
// ---------------------------------------------------------------------------
#define GBK   32
#define GKCH  (KDIM / GBK)      // 32
#define GPAD  40                // halves per smem row
#define GSTR  (128 * GPAD)      // halves per stage per operand
#define GEMM_SMEM (3 * 2 * GSTR * 2)   // 61440 B

template<bool HEAD_HALF>
__global__ __launch_bounds__(256)
void gemm_h(const __half* __restrict__ A, const __half* __restrict__ W,
            const float* __restrict__ bias, void* __restrict__ Yv)
{
    extern __shared__ __align__(16) char dsm[];
    __half* As = (__half*)dsm;            // [3][128][GPAD]
    __half* Ws = As + 3 * GSTR;           // [3][128][GPAD]

    const int tid    = threadIdx.x;
    const int lane   = tid & 31;
    const int wid    = tid >> 5;
    const int warp_m = wid & 1;
    const int warp_n = wid >> 1;
    const int gr     = lane >> 2;
    const int t4     = lane & 3;

    const int lr   = lane & 7;
    const int arow = ((lane >> 3) & 1) * 8 + lr;
    const int acol = ((lane >> 4) & 1) * 8;
    const int brow = ((lane >> 4) & 1) * 8 + lr;
    const int bcol = ((lane >> 3) & 1) * 8;

    const int bn = blockIdx.y * 128;
    const int bm = blockIdx.x * 128;

    const __half* Ag = A + (size_t)bn * KDIM;
    const __half* Wg = W + (size_t)bm * KDIM;

    // 128 rows x 32 halves(64B) = 512 chunks of 16B per operand; 2/thread
    auto issue = [&](int c, int s) {
        __half* ab = As + s * GSTR;
        __half* wb = Ws + s * GSTR;
        #pragma unroll
        for (int i = 0; i < 2; i++) {
            const int idx = tid + i * 256;        // 0..511
            const int r = idx >> 2, ch = idx & 3;
            cp16(ab + r * GPAD + ch * 8, Ag + (size_t)r * KDIM + c * GBK + ch * 8);
            cp16(wb + r * GPAD + ch * 8, Wg + (size_t)r * KDIM + c * GBK + ch * 8);
        }
    };

    float acc[4][4][4];
    #pragma unroll
    for (int mt = 0; mt < 4; mt++)
        #pragma unroll
        for (int nt = 0; nt < 4; nt++)
            #pragma unroll
            for (int i = 0; i < 4; i++) acc[mt][nt][i] = 0.f;

    issue(0, 0); cp_commit();
    issue(1, 1); cp_commit();

    for (int c = 0; c < GKCH; c++) {
        if (c == GKCH - 1) cp_wait<0>(); else cp_wait<1>();
        __syncthreads();

        const int s = c % 3;
        const __half* Ab = As + s * GSTR + (warp_m * 64) * GPAD;
        const __half* Wb = Ws + s * GSTR + (warp_n * 32) * GPAD;
        #pragma unroll
        for (int kk = 0; kk < 2; kk++) {
            const int k0 = kk * 16;
            uint32_t af[4][4], bb[2][4];
            #pragma unroll
            for (int mt = 0; mt < 4; mt++)
                ldmx4(af[mt], Ab + (mt*16 + arow) * GPAD + k0 + acol);
            #pragma unroll
            for (int np = 0; np < 2; np++)
                ldmx4(bb[np], Wb + (np*16 + brow) * GPAD + k0 + bcol);
            #pragma unroll
            for (int mt = 0; mt < 4; mt++)
                #pragma unroll
                for (int nt = 0; nt < 4; nt++)
                    mma_f16(acc[mt][nt], af[mt], &bb[nt >> 1][(nt & 1) * 2]);
        }

        if (c + 2 < GKCH) {
            __syncthreads();               // reads of reused buffer done
            issue(c + 2, (c + 2) % 3); cp_commit();
        }
    }

    #pragma unroll
    for (int nt = 0; nt < 4; nt++) {
        const int col = bm + warp_n * 32 + nt * 8 + t4 * 2;
        const float2 bv = *(const float2*)&bias[col];
        #pragma unroll
        for (int mt = 0; mt < 4; mt++) {
            const int row = bn + warp_m * 64 + mt * 16 + gr;
            float2 v0 = make_float2(acc[mt][nt][0] + bv.x, acc[mt][nt][1] + bv.y);
            float2 v1 = make_float2(acc[mt][nt][2] + bv.x, acc[mt][nt][3] + bv.y);
            if (HEAD_HALF) {
                __half* Y = (__half*)Yv;
                const int h = col / DHEAD, d = col % DHEAD;
                const int bb0 = row / SEQ, s0 = row % SEQ;
                const int bb1 = (row + 8) / SEQ, s1 = (row + 8) % SEQ;
                *(uint32_t*)&Y[(((size_t)(bb0*NHEAD + h)*SEQ + s0)*DHEAD) + d] = packh2(v0.x, v0.y);
                *(uint32_t*)&Y[(((size_t)(bb1*NHEAD + h)*SEQ + s1)*DHEAD) + d] = packh2(v1.x, v1.y);
            } else {
                float* Y = (float*)Yv;
                *(float2*)&Y[(size_t)row * D_MODEL + col] = v0;
                *(float2*)&Y[(size_t)(row + 8) * D_MODEL + col] = v1;
            }
        }
    }
}

// ---------------------------------------------------------------------------
// Causal flash attention, fp16 mma + cp.async triple-buffered K/V staging.
// Br=128, Bc=64, Dh=64, 256 threads; warp w owns q rows [16w,16w+16).
// K/V rows are 64 halves = 128 B = 8x16B chunks -> 512 chunks/operand (2/thread).
// log2-domain softmax (log2e folded into Q scale); P stays in registers.
// ---------------------------------------------------------------------------
#define ABR   128
#define ABC   64
#define APAD  72
#define KVSTR (ABC * APAD)               // halves per K (or V) stage
#define ATTN_SMEM ((3 * 2 * KVSTR + ABR * APAD) * 2)   // 73728 B
#define QSCALE (0.125f * 1.44269504088896340736f)

__global__ __launch_bounds__(256, 2)
void attn_h()
{
    extern __shared__ __align__(16) char dsm[];
    __half* Ksm = (__half*)dsm;               // [3][64][APAD]
    __half* Vsm = Ksm + 3 * KVSTR;            // [3][64][APAD]
    __half* Qs  = Vsm + 3 * KVSTR;            // [128][APAD]

    const int bh = blockIdx.y;
    const int qb = (int)gridDim.x - 1 - (int)blockIdx.x;   // heavy blocks first
    const int q0 = qb * ABR;

    const __half* Qg = g_qh + (size_t)bh * SEQ * DHEAD;
    const __half* Kg = g_kh + (size_t)bh * SEQ * DHEAD;
    const __half* Vg = g_vh + (size_t)bh * SEQ * DHEAD;

    const int tid  = threadIdx.x;
    const int lane = tid & 31;
    const int wid  = tid >> 5;
    const int gr   = lane >> 2;
    const int t4   = lane & 3;
    const int r0   = wid * 16;

    const int lr   = lane & 7;
    const int arow = ((lane >> 3) & 1) * 8 + lr;
    const int acol = ((lane >> 4) & 1) * 8;
    const int brow = ((lane >> 4) & 1) * 8 + lr;   // K B-frags
    const int bcol = ((lane >> 3) & 1) * 8;
    const int trow = ((lane >> 3) & 1) * 8 + lr;   // V B-frags (trans)
    const int tcol = ((lane >> 4) & 1) * 8;

    const int jmax = 2 * qb + 1;

    // FIXED: 64 rows x 8 chunks(16B) = 512 chunks per operand; 2 per thread.
    auto issue = [&](int j, int s) {
        #pragma unroll
        for (int i = 0; i < 2; i++) {
            const int idx = tid + i * 256;     // 0..511
            const int r = idx >> 3, ch = idx & 7;
            const size_t goff = (size_t)(j * ABC + r) * DHEAD + ch * 8;
            cp16(Ksm + s * KVSTR + r * APAD + ch * 8, Kg + goff);
            cp16(Vsm + s * KVSTR + r * APAD + ch * 8, Vg + goff);
        }
    };

    issue(0, 0); cp_commit();
    issue(1, 1); cp_commit();

    // ---- stage Q (x log2e/8) ----
    {
        const int r = tid >> 1, h = (tid & 1) * 32;
        const __half* src = Qg + (size_t)(q0 + r) * DHEAD + h;
        #pragma unroll
        for (int i = 0; i < 4; i++) {
            uint4 u = *(const uint4*)(src + i * 8);
            const __half2* hp = (const __half2*)&u;
            uint4 o;
            uint32_t* op = (uint32_t*)&o;
            #pragma unroll
            for (int k = 0; k < 4; k++) {
                float2 f = __half22float2(hp[k]);
                op[k] = packh2(f.x * QSCALE, f.y * QSCALE);
            }
            *(uint4*)&Qs[r * APAD + h + i * 8] = o;
        }
    }
    __syncthreads();

    uint32_t Qf[4][4];
    #pragma unroll
    for (int kk = 0; kk < 4; kk++)
        ldmx4(Qf[kk], Qs + (r0 + arow) * APAD + kk * 16 + acol);

    float m0 = -1e30f, m1 = -1e30f, l0 = 0.f, l1 = 0.f;
    float oacc[8][4];
    #pragma unroll
    for (int nt = 0; nt < 8; nt++)
        #pragma unroll
        for (int i = 0; i < 4; i++) oacc[nt][i] = 0.f;

    const int rowa = q0 + r0 + gr;
    const int rowb = rowa + 8;

    for (int j = 0; j <= jmax; j++) {
        if (j + 1 <= jmax) cp_wait<1>(); else cp_wait<0>();
        __syncthreads();

        const int s = j % 3;
        const __half* Ks = Ksm + s * KVSTR;
        const __half* Vs = Vsm + s * KVSTR;
        const int kv0 = j * ABC;

        // ---- S = Qs * K^T (scale + log2e folded into Q) ----
        float sacc[8][4];
        #pragma unroll
        for (int nt = 0; nt < 8; nt++)
            #pragma unroll
            for (int i = 0; i < 4; i++) sacc[nt][i] = 0.f;

        #pragma unroll
        for (int kk = 0; kk < 4; kk++) {
            #pragma unroll
            for (int np = 0; np < 4; np++) {
                uint32_t bb[4];
                ldmx4(bb, Ks + (np*16 + brow) * APAD + kk*16 + bcol);
                mma_f16(sacc[2*np    ], Qf[kk], &bb[0]);
                mma_f16(sacc[2*np + 1], Qf[kk], &bb[2]);
            }
        }

        // ---- causal mask (diag tiles only) ----
        if (kv0 + ABC - 1 > q0) {
            #pragma unroll
            for (int nt = 0; nt < 8; nt++) {
                const int col0 = kv0 + nt*8 + 2*t4;
                if (col0     > rowa) sacc[nt][0] = -1e30f;
                if (col0 + 1 > rowa) sacc[nt][1] = -1e30f;
                if (col0     > rowb) sacc[nt][2] = -1e30f;
                if (col0 + 1 > rowb) sacc[nt][3] = -1e30f;
            }
        }

        // ---- online softmax, log2 domain (rows gr, gr+8) ----
        float mx0 = -1e30f, mx1 = -1e30f;
        #pragma unroll
        for (int nt = 0; nt < 8; nt++) {
            mx0 = fmaxf(mx0, fmaxf(sacc[nt][0], sacc[nt][1]));
            mx1 = fmaxf(mx1, fmaxf(sacc[nt][2], sacc[nt][3]));
        }
        mx0 = fmaxf(mx0, __shfl_xor_sync(0xffffffffu, mx0, 1));
        mx0 = fmaxf(mx0, __shfl_xor_sync(0xffffffffu, mx0, 2));
        mx1 = fmaxf(mx1, __shfl_xor_sync(0xffffffffu, mx1, 1));
        mx1 = fmaxf(mx1, __shfl_xor_sync(0xffffffffu, mx1, 2));

        const float mn0 = fmaxf(m0, mx0), mn1 = fmaxf(m1, mx1);
        const float a0 = ex2f(m0 - mn0), a1 = ex2f(m1 - mn1);
        float s0 = 0.f, s1 = 0.f;
        #pragma unroll
        for (int nt = 0; nt < 8; nt++) {
            sacc[nt][0] = ex2f(sacc[nt][0] - mn0);
            sacc[nt][1] = ex2f(sacc[nt][1] - mn0);
            sacc[nt][2] = ex2f(sacc[nt][2] - mn1);
            sacc[nt][3] = ex2f(sacc[nt][3] - mn1);
            s0 += sacc[nt][0] + sacc[nt][1];
            s1 += sacc[nt][2] + sacc[nt][3];
        }
        s0 += __shfl_xor_sync(0xffffffffu, s0, 1);
        s0 += __shfl_xor_sync(0xffffffffu, s0, 2);
        s1 += __shfl_xor_sync(0xffffffffu, s1, 1);
        s1 += __shfl_xor_sync(0xffffffffu, s1, 2);
        l0 = l0 * a0 + s0;  m0 = mn0;
        l1 = l1 * a1 + s1;  m1 = mn1;
        #pragma unroll
        for (int nt = 0; nt < 8; nt++) {
            oacc[nt][0] *= a0; oacc[nt][1] *= a0;
            oacc[nt][2] *= a1; oacc[nt][3] *= a1;
        }

        // ---- O += P * V ; P packed from regs (C-frag == A-frag) ----
        #pragma unroll
        for (int kk = 0; kk < 4; kk++) {
            uint32_t pf[4];
            pf[0] = packh2(sacc[2*kk    ][0], sacc[2*kk    ][1]);
            pf[1] = packh2(sacc[2*kk    ][2], sacc[2*kk    ][3]);
            pf[2] = packh2(sacc[2*kk + 1][0], sacc[2*kk + 1][1]);
            pf[3] = packh2(sacc[2*kk + 1][2], sacc[2*kk + 1][3]);
            #pragma unroll
            for (int np = 0; np < 4; np++) {
                uint32_t bt[4];
                ldmx4t(bt, Vs + (kk*16 + trow) * APAD + np*16 + tcol);
                mma_f16(oacc[2*np    ], pf, &bt[0]);
                mma_f16(oacc[2*np + 1], pf, &bt[2]);
            }
        }

        if (j + 2 <= jmax) {
            __syncthreads();               // reads of reused buffer done
            issue(j + 2, (j + 2) % 3); cp_commit();
        }
    }

    // ---- normalize + write half [B,S,D] ----
    const float inv0 = 1.f / l0, inv1 = 1.f / l1;
    const int b = bh >> 4, h = bh & 15;
    #pragma unroll
    for (int nt = 0; nt < 8; nt++) {
        const int col = h * DHEAD + nt*8 + 2*t4;
        *(uint32_t*)&g_ah[((size_t)(b*SEQ + rowa)) * D_MODEL + col] =
            packh2(oacc[nt][0] * inv0, oacc[nt][1] * inv0);
        *(uint32_t*)&g_ah[((size_t)(b*SEQ + rowb)) * D_MODEL + col] =
            packh2(oacc[nt][2] * inv1, oacc[nt][3] * inv1);
    }
}

// ---------------------------------------------------------------------------
extern "C" void kernel_launch(void* const* d_in, const int* in_sizes, int n_in,
                              void* d_out, int out_size)
{
    const float* x  = (const float*)d_in[0];
    const float* Wq = (const float*)d_in[1];
    const float* bq = (const float*)d_in[2];
    const float* Wk = (const float*)d_in[3];
    const float* bk = (const float*)d_in[4];
    const float* Wv = (const float*)d_in[5];
    const float* bv = (const float*)d_in[6];
    const float* Wo = (const float*)d_in[7];
    const float* bo = (const float*)d_in[8];

    __half *xh, *wqh, *wkh, *wvh, *woh, *qh, *kh, *vh, *ah;
    cudaGetSymbolAddress((void**)&xh,  g_xh);
    cudaGetSymbolAddress((void**)&wqh, g_wqh);
    cudaGetSymbolAddress((void**)&wkh, g_wkh);
    cudaGetSymbolAddress((void**)&wvh, g_wvh);
    cudaGetSymbolAddress((void**)&woh, g_woh);
    cudaGetSymbolAddress((void**)&qh,  g_qh);
    cudaGetSymbolAddress((void**)&kh,  g_kh);
    cudaGetSymbolAddress((void**)&vh,  g_vh);
    cudaGetSymbolAddress((void**)&ah,  g_ah);

    // fp32 -> fp16 pre-pass
    const int nx8 = NTOK * KDIM / 8;        // 1048576
    const int nw8 = KDIM * D_MODEL / 8;     // 131072
    cvt_f2h<<<nx8/256, 256>>>(x,  xh,  nx8);
    cvt_f2h<<<nw8/256, 256>>>(Wq, wqh, nw8);
    cvt_f2h<<<nw8/256, 256>>>(Wk, wkh, nw8);
    cvt_f2h<<<nw8/256, 256>>>(Wv, wvh, nw8);
    cvt_f2h<<<nw8/256, 256>>>(Wo, woh, nw8);

    cudaFuncSetAttribute(gemm_h<true>,
                         cudaFuncAttributeMaxDynamicSharedMemorySize, GEMM_SMEM);
    cudaFuncSetAttribute(gemm_h<false>,
                         cudaFuncAttributeMaxDynamicSharedMemorySize, GEMM_SMEM);
    cudaFuncSetAttribute(attn_h,
                         cudaFuncAttributeMaxDynamicSharedMemorySize, ATTN_SMEM);

    dim3 gg(D_MODEL/128, NTOK/128);   // (8, 64)
    gemm_h<true ><<<gg, 256, GEMM_SMEM>>>(xh, wqh, bq, qh);
    gemm_h<true ><<<gg, 256, GEMM_SMEM>>>(xh, wkh, bk, kh);
    gemm_h<true ><<<gg, 256, GEMM_SMEM>>>(xh, wvh, bv, vh);

    attn_h<<<dim3(SEQ/ABR, BATCH*NHEAD), 256, ATTN_SMEM>>>();

    gemm_h<false><<<gg, 256, GEMM_SMEM>>>(ah, woh, bo, d_out);
}

// round 9
// speedup vs baseline: 14.7762x; 1.0801x over previous
#include <cuda_runtime.h>
#include <cuda_fp16.h>
#include <math.h>
#include <cstdint>

#define D_MODEL 1024
#define NHEAD   16
#define DHEAD   64
#define BATCH   4
#define SEQ     2048
#define NTOK    (BATCH*SEQ)   // 8192
#define KDIM    1024

// ---------------------------------------------------------------------------
// fp16 scratch (allocation-free rule: __device__ globals)
// ---------------------------------------------------------------------------
__device__ __half g_xh[(size_t)NTOK*KDIM];
__device__ __half g_wqh[(size_t)KDIM*D_MODEL];
__device__ __half g_wkh[(size_t)KDIM*D_MODEL];
__device__ __half g_wvh[(size_t)KDIM*D_MODEL];
__device__ __half g_woh[(size_t)KDIM*D_MODEL];
__device__ __half g_qh[(size_t)BATCH*NHEAD*SEQ*DHEAD];   // [B,H,S,Dh]
__device__ __half g_kh[(size_t)BATCH*NHEAD*SEQ*DHEAD];
__device__ __half g_vh[(size_t)BATCH*NHEAD*SEQ*DHEAD];
__device__ __half g_ah[(size_t)NTOK*D_MODEL];            // [B,S,D]

// ---------------------------------------------------------------------------
// helpers
// ---------------------------------------------------------------------------
__device__ __forceinline__ uint32_t packh2(float a, float b) {
    __half2 h = __floats2half2_rn(a, b);
    return *reinterpret_cast<uint32_t*>(&h);
}
__device__ __forceinline__ float ex2f(float x) {
    float y;
    asm("ex2.approx.ftz.f32 %0, %1;" : "=f"(y) : "f"(x));
    return y;
}
__device__ __forceinline__ void mma_f16(float* c, const uint32_t* a, const uint32_t* b) {
    asm volatile(
        "mma.sync.aligned.m16n8k16.row.col.f32.f16.f16.f32 "
        "{%0,%1,%2,%3}, {%4,%5,%6,%7}, {%8,%9}, {%0,%1,%2,%3};"
        : "+f"(c[0]), "+f"(c[1]), "+f"(c[2]), "+f"(c[3])
        : "r"(a[0]), "r"(a[1]), "r"(a[2]), "r"(a[3]), "r"(b[0]), "r"(b[1]));
}
__device__ __forceinline__ void ldmx4(uint32_t* r, const void* p) {
    uint32_t a = (uint32_t)__cvta_generic_to_shared(p);
    asm volatile("ldmatrix.sync.aligned.m8n8.x4.shared.b16 {%0,%1,%2,%3}, [%4];"
                 : "=r"(r[0]), "=r"(r[1]), "=r"(r[2]), "=r"(r[3]) : "r"(a));
}
__device__ __forceinline__ void ldmx4t(uint32_t* r, const void* p) {
    uint32_t a = (uint32_t)__cvta_generic_to_shared(p);
    asm volatile("ldmatrix.sync.aligned.m8n8.x4.trans.shared.b16 {%0,%1,%2,%3}, [%4];"
                 : "=r"(r[0]), "=r"(r[1]), "=r"(r[2]), "=r"(r[3]) : "r"(a));
}
__device__ __forceinline__ void cp16(void* s, const void* g) {
    uint32_t a = (uint32_t)__cvta_generic_to_shared(s);
    asm volatile("cp.async.cg.shared.global [%0], [%1], 16;" :: "r"(a), "l"(g) : "memory");
}
__device__ __forceinline__ void cp_commit() {
    asm volatile("cp.async.commit_group;" ::: "memory");
}
template<int N>
__device__ __forceinline__ void cp_wait() {
    asm volatile("cp.async.wait_group %0;" :: "n"(N) : "memory");
}

// ---------------------------------------------------------------------------
// fused fp32 -> fp16 conversion: x (NX8 chunks) then 4 weights (NW8 each).
// One chunk = 8 floats -> 8 halves (uint4 out).
// ---------------------------------------------------------------------------
#define NX8 (NTOK * KDIM / 8)       // 1048576 = 2^20
#define NW8 (KDIM * D_MODEL / 8)    // 131072  = 2^17
#define NCVT (NX8 + 4 * NW8)        // 1572864

__global__ __launch_bounds__(256)
void cvt_all(const float* __restrict__ x,
             const float* __restrict__ w0, const float* __restrict__ w1,
             const float* __restrict__ w2, const float* __restrict__ w3)
{
    const int i = blockIdx.x * 256 + threadIdx.x;
    const float* src;
    __half* dst;
    int off;
    if (i < NX8) {
        src = x; dst = g_xh; off = i;
    } else {
        const int t = i - NX8;
        const int w = t >> 17;            // NW8 = 2^17
        off = t & (NW8 - 1);
        switch (w) {
            case 0:  src = w0; dst = g_wqh; break;
            case 1:  src = w1; dst = g_wkh; break;
            case 2:  src = w2; dst = g_wvh; break;
            default: src = w3; dst = g_woh; break;
        }
    }
    float4 a = ((const float4*)src)[2*off];
    float4 b = ((const float4*)src)[2*off + 1];
    uint4 o;
    o.x = packh2(a.x, a.y);  o.y = packh2(a.z, a.w);
    o.z = packh2(b.x, b.y);  o.w = packh2(b.z, b.w);
    ((uint4*)dst)[off] = o;
}

// ---------------------------------------------------------------------------
// fp16 GEMM (NT), cp.async 3-stage: Y[n,m] = sum_k A[n,k]*W[m,k] + bias[m]
// CTA tile 128x128, BK=32 halves, 256 threads (8 warps, 2x4), warp 64x32.
// QKV=true: blockIdx.z in {0,1,2} selects Wq/Wk/Wv -> g_qh/g_kh/g_vh (half,
// head layout). QKV=false: single W/bias -> float [N,M].
// ---------------------------------------------------------------------------
#define GBK   32
#define GKCH  (KDIM / GBK)      // 32
#define GPAD  40                // halves per smem row
#define GSTR  (128 * GPAD)      // halves per stage per operand
#define GEMM_SMEM (3 * 2 * GSTR * 2)   // 61440 B

template<bool QKV>
__global__ __launch_bounds__(256)
void gemm_h(const __half* __restrict__ A,
            const __half* __restrict__ W0, const float* __restrict__ b0,
            const __half* __restrict__ W1, const float* __restrict__ b1,
            const __half* __restrict__ W2, const float* __restrict__ b2,
            void* __restrict__ Yv)
{
    extern __shared__ __align__(16) char dsm[];
    __half* As = (__half*)dsm;            // [3][128][GPAD]
    __half* Ws = As + 3 * GSTR;           // [3][128][GPAD]

    const __half* Wsel = W0;
    const float*  bsel = b0;
    __half* Hout = g_qh;
    if (QKV) {
        if (blockIdx.z == 1)      { Wsel = W1; bsel = b1; Hout = g_kh; }
        else if (blockIdx.z == 2) { Wsel = W2; bsel = b2; Hout = g_vh; }
    }

    const int tid    = threadIdx.x;
    const int lane   = tid & 31;
    const int wid    = tid >> 5;
    const int warp_m = wid & 1;
    const int warp_n = wid >> 1;
    const int gr     = lane >> 2;
    const int t4     = lane & 3;

    const int lr   = lane & 7;
    const int arow = ((lane >> 3) & 1) * 8 + lr;
    const int acol = ((lane >> 4) & 1) * 8;
    const int brow = ((lane >> 4) & 1) * 8 + lr;
    const int bcol = ((lane >> 3) & 1) * 8;

    const int bn = blockIdx.y * 128;
    const int bm = blockIdx.x * 128;

    const __half* Ag = A + (size_t)bn * KDIM;
    const __half* Wg = Wsel + (size_t)bm * KDIM;

    // 128 rows x 32 halves(64B) = 512 chunks of 16B per operand; 2/thread
    auto issue = [&](int c, int s) {
        __half* ab = As + s * GSTR;
        __half* wb = Ws + s * GSTR;
        #pragma unroll
        for (int i = 0; i < 2; i++) {
            const int idx = tid + i * 256;        // 0..511
            const int r = idx >> 2, ch = idx & 3;
            cp16(ab + r * GPAD + ch * 8, Ag + (size_t)r * KDIM + c * GBK + ch * 8);
            cp16(wb + r * GPAD + ch * 8, Wg + (size_t)r * KDIM + c * GBK + ch * 8);
        }
    };

    float acc[4][4][4];
    #pragma unroll
    for (int mt = 0; mt < 4; mt++)
        #pragma unroll
        for (int nt = 0; nt < 4; nt++)
            #pragma unroll
            for (int i = 0; i < 4; i++) acc[mt][nt][i] = 0.f;

    issue(0, 0); cp_commit();
    issue(1, 1); cp_commit();

    for (int c = 0; c < GKCH; c++) {
        if (c == GKCH - 1) cp_wait<0>(); else cp_wait<1>();
        __syncthreads();
        // NOTE: buffer (c+2)%3 == (c-1)%3 was last read in iter c-1, and every
        // warp passed the barrier above (i.e. finished iter c-1) => safe to
        // overwrite without a second barrier.

        const int s = c % 3;
        const __half* Ab = As + s * GSTR + (warp_m * 64) * GPAD;
        const __half* Wb = Ws + s * GSTR + (warp_n * 32) * GPAD;

        if (c + 2 < GKCH) { issue(c + 2, (c + 2) % 3); cp_commit(); }

        #pragma unroll
        for (int kk = 0; kk < 2; kk++) {
            const int k0 = kk * 16;
            uint32_t af[4][4], bb[2][4];
            #pragma unroll
            for (int mt = 0; mt < 4; mt++)
                ldmx4(af[mt], Ab + (mt*16 + arow) * GPAD + k0 + acol);
            #pragma unroll
            for (int np = 0; np < 2; np++)
                ldmx4(bb[np], Wb + (np*16 + brow) * GPAD + k0 + bcol);
            #pragma unroll
            for (int mt = 0; mt < 4; mt++)
                #pragma unroll
                for (int nt = 0; nt < 4; nt++)
                    mma_f16(acc[mt][nt], af[mt], &bb[nt >> 1][(nt & 1) * 2]);
        }
    }

    #pragma unroll
    for (int nt = 0; nt < 4; nt++) {
        const int col = bm + warp_n * 32 + nt * 8 + t4 * 2;
        const float2 bv = *(const float2*)&bsel[col];
        #pragma unroll
        for (int mt = 0; mt < 4; mt++) {
            const int row = bn + warp_m * 64 + mt * 16 + gr;
            float2 v0 = make_float2(acc[mt][nt][0] + bv.x, acc[mt][nt][1] + bv.y);
            float2 v1 = make_float2(acc[mt][nt][2] + bv.x, acc[mt][nt][3] + bv.y);
            if (QKV) {
                const int h = col / DHEAD, d = col % DHEAD;
                const int bb0 = row / SEQ, s0 = row % SEQ;
                const int bb1 = (row + 8) / SEQ, s1 = (row + 8) % SEQ;
                *(uint32_t*)&Hout[(((size_t)(bb0*NHEAD + h)*SEQ + s0)*DHEAD) + d] = packh2(v0.x, v0.y);
                *(uint32_t*)&Hout[(((size_t)(bb1*NHEAD + h)*SEQ + s1)*DHEAD) + d] = packh2(v1.x, v1.y);
            } else {
                float* Y = (float*)Yv;
                *(float2*)&Y[(size_t)row * D_MODEL + col] = v0;
                *(float2*)&Y[(size_t)(row + 8) * D_MODEL + col] = v1;
            }
        }
    }
}

// ---------------------------------------------------------------------------
// Causal flash attention, fp16 mma + cp.async triple-buffered K/V staging.
// Br=128, Bc=64, Dh=64, 256 threads; warp w owns q rows [16w,16w+16).
// log2-domain softmax (log2e folded into Q scale); P stays in registers.
// ---------------------------------------------------------------------------
#define ABR   128
#define ABC   64
#define APAD  72
#define KVSTR (ABC * APAD)               // halves per K (or V) stage
#define ATTN_SMEM ((3 * 2 * KVSTR + ABR * APAD) * 2)   // 73728 B
#define QSCALE (0.125f * 1.44269504088896340736f)

__global__ __launch_bounds__(256, 2)
void attn_h()
{
    extern __shared__ __align__(16) char dsm[];
    __half* Ksm = (__half*)dsm;               // [3][64][APAD]
    __half* Vsm = Ksm + 3 * KVSTR;            // [3][64][APAD]
    __half* Qs  = Vsm + 3 * KVSTR;            // [128][APAD]

    const int bh = blockIdx.y;
    const int qb = (int)gridDim.x - 1 - (int)blockIdx.x;   // heavy blocks first
    const int q0 = qb * ABR;

    const __half* Qg = g_qh + (size_t)bh * SEQ * DHEAD;
    const __half* Kg = g_kh + (size_t)bh * SEQ * DHEAD;
    const __half* Vg = g_vh + (size_t)bh * SEQ * DHEAD;

    const int tid  = threadIdx.x;
    const int lane = tid & 31;
    const int wid  = tid >> 5;
    const int gr   = lane >> 2;
    const int t4   = lane & 3;
    const int r0   = wid * 16;

    const int lr   = lane & 7;
    const int arow = ((lane >> 3) & 1) * 8 + lr;
    const int acol = ((lane >> 4) & 1) * 8;
    const int brow = ((lane >> 4) & 1) * 8 + lr;   // K B-frags
    const int bcol = ((lane >> 3) & 1) * 8;
    const int trow = ((lane >> 3) & 1) * 8 + lr;   // V B-frags (trans)
    const int tcol = ((lane >> 4) & 1) * 8;

    const int jmax = 2 * qb + 1;

    // 64 rows x 8 chunks(16B) = 512 chunks per operand; 2 per thread.
    auto issue = [&](int j, int s) {
        #pragma unroll
        for (int i = 0; i < 2; i++) {
            const int idx = tid + i * 256;     // 0..511
            const int r = idx >> 3, ch = idx & 7;
            const size_t goff = (size_t)(j * ABC + r) * DHEAD + ch * 8;
            cp16(Ksm + s * KVSTR + r * APAD + ch * 8, Kg + goff);
            cp16(Vsm + s * KVSTR + r * APAD + ch * 8, Vg + goff);
        }
    };

    issue(0, 0); cp_commit();
    issue(1, 1); cp_commit();

    // ---- stage Q (x log2e/8) ----
    {
        const int r = tid >> 1, h = (tid & 1) * 32;
        const __half* src = Qg + (size_t)(q0 + r) * DHEAD + h;
        #pragma unroll
        for (int i = 0; i < 4; i++) {
            uint4 u = *(const uint4*)(src + i * 8);
            const __half2* hp = (const __half2*)&u;
            uint4 o;
            uint32_t* op = (uint32_t*)&o;
            #pragma unroll
            for (int k = 0; k < 4; k++) {
                float2 f = __half22float2(hp[k]);
                op[k] = packh2(f.x * QSCALE, f.y * QSCALE);
            }
            *(uint4*)&Qs[r * APAD + h + i * 8] = o;
        }
    }
    __syncthreads();

    uint32_t Qf[4][4];
    #pragma unroll
    for (int kk = 0; kk < 4; kk++)
        ldmx4(Qf[kk], Qs + (r0 + arow) * APAD + kk * 16 + acol);

    float m0 = -1e30f, m1 = -1e30f, l0 = 0.f, l1 = 0.f;
    float oacc[8][4];
    #pragma unroll
    for (int nt = 0; nt < 8; nt++)
        #pragma unroll
        for (int i = 0; i < 4; i++) oacc[nt][i] = 0.f;

    const int rowa = q0 + r0 + gr;
    const int rowb = rowa + 8;

    for (int j = 0; j <= jmax; j++) {
        if (j + 1 <= jmax) cp_wait<1>(); else cp_wait<0>();
        __syncthreads();
        // Buffer (j+2)%3 == (j-1)%3: last read in iter j-1; all warps passed
        // the barrier above => safe to refill now, no second barrier needed.
        if (j + 2 <= jmax) { issue(j + 2, (j + 2) % 3); cp_commit(); }

        const int s = j % 3;
        const __half* Ks = Ksm + s * KVSTR;
        const __half* Vs = Vsm + s * KVSTR;
        const int kv0 = j * ABC;

        // ---- S = Qs * K^T (scale + log2e folded into Q) ----
        float sacc[8][4];
        #pragma unroll
        for (int nt = 0; nt < 8; nt++)
            #pragma unroll
            for (int i = 0; i < 4; i++) sacc[nt][i] = 0.f;

        #pragma unroll
        for (int kk = 0; kk < 4; kk++) {
            #pragma unroll
            for (int np = 0; np < 4; np++) {
                uint32_t bb[4];
                ldmx4(bb, Ks + (np*16 + brow) * APAD + kk*16 + bcol);
                mma_f16(sacc[2*np    ], Qf[kk], &bb[0]);
                mma_f16(sacc[2*np + 1], Qf[kk], &bb[2]);
            }
        }

        // ---- causal mask (diag tiles only) ----
        if (kv0 + ABC - 1 > q0) {
            #pragma unroll
            for (int nt = 0; nt < 8; nt++) {
                const int col0 = kv0 + nt*8 + 2*t4;
                if (col0     > rowa) sacc[nt][0] = -1e30f;
                if (col0 + 1 > rowa) sacc[nt][1] = -1e30f;
                if (col0     > rowb) sacc[nt][2] = -1e30f;
                if (col0 + 1 > rowb) sacc[nt][3] = -1e30f;
            }
        }

        // ---- online softmax, log2 domain (rows gr, gr+8) ----
        float mx0 = -1e30f, mx1 = -1e30f;
        #pragma unroll
        for (int nt = 0; nt < 8; nt++) {
            mx0 = fmaxf(mx0, fmaxf(sacc[nt][0], sacc[nt][1]));
            mx1 = fmaxf(mx1, fmaxf(sacc[nt][2], sacc[nt][3]));
        }
        mx0 = fmaxf(mx0, __shfl_xor_sync(0xffffffffu, mx0, 1));
        mx0 = fmaxf(mx0, __shfl_xor_sync(0xffffffffu, mx0, 2));
        mx1 = fmaxf(mx1, __shfl_xor_sync(0xffffffffu, mx1, 1));
        mx1 = fmaxf(mx1, __shfl_xor_sync(0xffffffffu, mx1, 2));

        const float mn0 = fmaxf(m0, mx0), mn1 = fmaxf(m1, mx1);
        const float a0 = ex2f(m0 - mn0), a1 = ex2f(m1 - mn1);
        float s0 = 0.f, s1 = 0.f;
        #pragma unroll
        for (int nt = 0; nt < 8; nt++) {
            sacc[nt][0] = ex2f(sacc[nt][0] - mn0);
            sacc[nt][1] = ex2f(sacc[nt][1] - mn0);
            sacc[nt][2] = ex2f(sacc[nt][2] - mn1);
            sacc[nt][3] = ex2f(sacc[nt][3] - mn1);
            s0 += sacc[nt][0] + sacc[nt][1];
            s1 += sacc[nt][2] + sacc[nt][3];
        }
        s0 += __shfl_xor_sync(0xffffffffu, s0, 1);
        s0 += __shfl_xor_sync(0xffffffffu, s0, 2);
        s1 += __shfl_xor_sync(0xffffffffu, s1, 1);
        s1 += __shfl_xor_sync(0xffffffffu, s1, 2);
        l0 = l0 * a0 + s0;  m0 = mn0;
        l1 = l1 * a1 + s1;  m1 = mn1;
        #pragma unroll
        for (int nt = 0; nt < 8; nt++) {
            oacc[nt][0] *= a0; oacc[nt][1] *= a0;
            oacc[nt][2] *= a1; oacc[nt][3] *= a1;
        }

        // ---- O += P * V ; P packed from regs (C-frag == A-frag) ----
        #pragma unroll
        for (int kk = 0; kk < 4; kk++) {
            uint32_t pf[4];
            pf[0] = packh2(sacc[2*kk    ][0], sacc[2*kk    ][1]);
            pf[1] = packh2(sacc[2*kk    ][2], sacc[2*kk    ][3]);
            pf[2] = packh2(sacc[2*kk + 1][0], sacc[2*kk + 1][1]);
            pf[3] = packh2(sacc[2*kk + 1][2], sacc[2*kk + 1][3]);
            #pragma unroll
            for (int np = 0; np < 4; np++) {
                uint32_t bt[4];
                ldmx4t(bt, Vs + (kk*16 + trow) * APAD + np*16 + tcol);
                mma_f16(oacc[2*np    ], pf, &bt[0]);
                mma_f16(oacc[2*np + 1], pf, &bt[2]);
            }
        }
    }

    // ---- normalize + write half [B,S,D] ----
    const float inv0 = 1.f / l0, inv1 = 1.f / l1;
    const int b = bh >> 4, h = bh & 15;
    #pragma unroll
    for (int nt = 0; nt < 8; nt++) {
        const int col = h * DHEAD + nt*8 + 2*t4;
        *(uint32_t*)&g_ah[((size_t)(b*SEQ + rowa)) * D_MODEL + col] =
            packh2(oacc[nt][0] * inv0, oacc[nt][1] * inv0);
        *(uint32_t*)&g_ah[((size_t)(b*SEQ + rowb)) * D_MODEL + col] =
            packh2(oacc[nt][2] * inv1, oacc[nt][3] * inv1);
    }
}

// ---------------------------------------------------------------------------
extern "C" void kernel_launch(void* const* d_in, const int* in_sizes, int n_in,
                              void* d_out, int out_size)
{
    const float* x  = (const float*)d_in[0];
    const float* Wq = (const float*)d_in[1];
    const float* bq = (const float*)d_in[2];
    const float* Wk = (const float*)d_in[3];
    const float* bk = (const float*)d_in[4];
    const float* Wv = (const float*)d_in[5];
    const float* bv = (const float*)d_in[6];
    const float* Wo = (const float*)d_in[7];
    const float* bo = (const float*)d_in[8];

    __half *xh, *wqh, *wkh, *wvh, *woh, *ah;
    cudaGetSymbolAddress((void**)&xh,  g_xh);
    cudaGetSymbolAddress((void**)&wqh, g_wqh);
    cudaGetSymbolAddress((void**)&wkh, g_wkh);
    cudaGetSymbolAddress((void**)&wvh, g_wvh);
    cudaGetSymbolAddress((void**)&woh, g_woh);
    cudaGetSymbolAddress((void**)&ah,  g_ah);

    // fused fp32 -> fp16 pre-pass (1 launch)
    cvt_all<<<NCVT/256, 256>>>(x, Wq, Wk, Wv, Wo);

    cudaFuncSetAttribute(gemm_h<true>,
                         cudaFuncAttributeMaxDynamicSharedMemorySize, GEMM_SMEM);
    cudaFuncSetAttribute(gemm_h<false>,
                         cudaFuncAttributeMaxDynamicSharedMemorySize, GEMM_SMEM);
    cudaFuncSetAttribute(attn_h,
                         cudaFuncAttributeMaxDynamicSharedMemorySize, ATTN_SMEM);

    // fused QKV projection (1 launch, z selects head)
    gemm_h<true><<<dim3(D_MODEL/128, NTOK/128, 3), 256, GEMM_SMEM>>>(
        xh, wqh, bq, wkh, bk, wvh, bv, nullptr);

    attn_h<<<dim3(SEQ/ABR, BATCH*NHEAD), 256, ATTN_SMEM>>>();

    // output projection
    gemm_h<false><<<dim3(D_MODEL/128, NTOK/128, 1), 256, GEMM_SMEM>>>(
        ah, woh, bo, nullptr, nullptr, nullptr, nullptr, d_out);
}

// round 10
// speedup vs baseline: 15.1396x; 1.0246x over previous
#include <cuda_runtime.h>
#include <cuda_fp16.h>
#include <math.h>
#include <cstdint>

#define D_MODEL 1024
#define NHEAD   16
#define DHEAD   64
#define BATCH   4
#define SEQ     2048
#define NTOK    (BATCH*SEQ)   // 8192
#define KDIM    1024

// ---------------------------------------------------------------------------
// fp16 scratch (allocation-free rule: __device__ globals)
// ---------------------------------------------------------------------------
__device__ __half g_xh[(size_t)NTOK*KDIM];
__device__ __half g_wqh[(size_t)KDIM*D_MODEL];
__device__ __half g_wkh[(size_t)KDIM*D_MODEL];
__device__ __half g_wvh[(size_t)KDIM*D_MODEL];
__device__ __half g_woh[(size_t)KDIM*D_MODEL];
__device__ __half g_qh[(size_t)BATCH*NHEAD*SEQ*DHEAD];   // [B,H,S,Dh]
__device__ __half g_kh[(size_t)BATCH*NHEAD*SEQ*DHEAD];
__device__ __half g_vh[(size_t)BATCH*NHEAD*SEQ*DHEAD];
__device__ __half g_ah[(size_t)NTOK*D_MODEL];            // [B,S,D]

// ---------------------------------------------------------------------------
// helpers
// ---------------------------------------------------------------------------
__device__ __forceinline__ uint32_t packh2(float a, float b) {
    __half2 h = __floats2half2_rn(a, b);
    return *reinterpret_cast<uint32_t*>(&h);
}
__device__ __forceinline__ float ex2f(float x) {
    float y;
    asm("ex2.approx.ftz.f32 %0, %1;" : "=f"(y) : "f"(x));
    return y;
}
__device__ __forceinline__ void mma_f16(float* c, const uint32_t* a, const uint32_t* b) {
    asm volatile(
        "mma.sync.aligned.m16n8k16.row.col.f32.f16.f16.f32 "
        "{%0,%1,%2,%3}, {%4,%5,%6,%7}, {%8,%9}, {%0,%1,%2,%3};"
        : "+f"(c[0]), "+f"(c[1]), "+f"(c[2]), "+f"(c[3])
        : "r"(a[0]), "r"(a[1]), "r"(a[2]), "r"(a[3]), "r"(b[0]), "r"(b[1]));
}
__device__ __forceinline__ void ldmx4(uint32_t* r, const void* p) {
    uint32_t a = (uint32_t)__cvta_generic_to_shared(p);
    asm volatile("ldmatrix.sync.aligned.m8n8.x4.shared.b16 {%0,%1,%2,%3}, [%4];"
                 : "=r"(r[0]), "=r"(r[1]), "=r"(r[2]), "=r"(r[3]) : "r"(a));
}
__device__ __forceinline__ void ldmx4t(uint32_t* r, const void* p) {
    uint32_t a = (uint32_t)__cvta_generic_to_shared(p);
    asm volatile("ldmatrix.sync.aligned.m8n8.x4.trans.shared.b16 {%0,%1,%2,%3}, [%4];"
                 : "=r"(r[0]), "=r"(r[1]), "=r"(r[2]), "=r"(r[3]) : "r"(a));
}
__device__ __forceinline__ void cp16(void* s, const void* g) {
    uint32_t a = (uint32_t)__cvta_generic_to_shared(s);
    asm volatile("cp.async.cg.shared.global [%0], [%1], 16;" :: "r"(a), "l"(g) : "memory");
}
__device__ __forceinline__ void cp_commit() {
    asm volatile("cp.async.commit_group;" ::: "memory");
}
template<int N>
__device__ __forceinline__ void cp_wait() {
    asm volatile("cp.async.wait_group %0;" :: "n"(N) : "memory");
}

// ---------------------------------------------------------------------------
// fused fp32 -> fp16 conversion
// ---------------------------------------------------------------------------
#define NX8 (NTOK * KDIM / 8)       // 1048576 = 2^20
#define NW8 (KDIM * D_MODEL / 8)    // 131072  = 2^17
#define NCVT (NX8 + 4 * NW8)        // 1572864

__global__ __launch_bounds__(256)
void cvt_all(const float* __restrict__ x,
             const float* __restrict__ w0, const float* __restrict__ w1,
             const float* __restrict__ w2, const float* __restrict__ w3)
{
    const int i = blockIdx.x * 256 + threadIdx.x;
    const float* src;
    __half* dst;
    int off;
    if (i < NX8) {
        src = x; dst = g_xh; off = i;
    } else {
        const int t = i - NX8;
        const int w = t >> 17;            // NW8 = 2^17
        off = t & (NW8 - 1);
        switch (w) {
            case 0:  src = w0; dst = g_wqh; break;
            case 1:  src = w1; dst = g_wkh; break;
            case 2:  src = w2; dst = g_wvh; break;
            default: src = w3; dst = g_woh; break;
        }
    }
    float4 a = ((const float4*)src)[2*off];
    float4 b = ((const float4*)src)[2*off + 1];
    uint4 o;
    o.x = packh2(a.x, a.y);  o.y = packh2(a.z, a.w);
    o.z = packh2(b.x, b.y);  o.w = packh2(b.z, b.w);
    ((uint4*)dst)[off] = o;
}

// ---------------------------------------------------------------------------
// fp16 GEMM (NT), cp.async 4-stage, CTA 128x128, 128 threads (4 warps, 2x2),
// warp tile 64x64: 8 ldmatrix feed 32 MMA per k-halfchunk (smem-BW balanced).
// ---------------------------------------------------------------------------
#define GBK   32
#define GKCH  (KDIM / GBK)      // 32
#define GPAD  40                // halves per smem row
#define GSTR  (128 * GPAD)      // halves per stage per operand
#define GEMM_SMEM (4 * 2 * GSTR * 2)   // 81920 B

template<bool QKV>
__global__ __launch_bounds__(128)
void gemm_h(const __half* __restrict__ A,
            const __half* __restrict__ W0, const float* __restrict__ b0,
            const __half* __restrict__ W1, const float* __restrict__ b1,
            const __half* __restrict__ W2, const float* __restrict__ b2,
            void* __restrict__ Yv)
{
    extern __shared__ __align__(16) char dsm[];
    __half* As = (__half*)dsm;            // [4][128][GPAD]
    __half* Ws = As + 4 * GSTR;           // [4][128][GPAD]

    const __half* Wsel = W0;
    const float*  bsel = b0;
    __half* Hout = g_qh;
    if (QKV) {
        if (blockIdx.z == 1)      { Wsel = W1; bsel = b1; Hout = g_kh; }
        else if (blockIdx.z == 2) { Wsel = W2; bsel = b2; Hout = g_vh; }
    }

    const int tid    = threadIdx.x;
    const int lane   = tid & 31;
    const int wid    = tid >> 5;         // 0..3
    const int warp_m = wid & 1;          // 64-row group
    const int warp_n = wid >> 1;         // 64-col group
    const int gr     = lane >> 2;
    const int t4     = lane & 3;

    const int lr   = lane & 7;
    const int arow = ((lane >> 3) & 1) * 8 + lr;
    const int acol = ((lane >> 4) & 1) * 8;
    const int brow = ((lane >> 4) & 1) * 8 + lr;
    const int bcol = ((lane >> 3) & 1) * 8;

    const int bn = blockIdx.y * 128;
    const int bm = blockIdx.x * 128;

    const __half* Ag = A + (size_t)bn * KDIM;
    const __half* Wg = Wsel + (size_t)bm * KDIM;

    // 128 rows x 4 chunks(16B) per operand = 512 chunks; 4/thread/operand
    auto issue = [&](int c, int s) {
        __half* ab = As + s * GSTR;
        __half* wb = Ws + s * GSTR;
        #pragma unroll
        for (int i = 0; i < 4; i++) {
            const int idx = tid + i * 128;        // 0..511
            const int r = idx >> 2, ch = idx & 3;
            cp16(ab + r * GPAD + ch * 8, Ag + (size_t)r * KDIM + c * GBK + ch * 8);
            cp16(wb + r * GPAD + ch * 8, Wg + (size_t)r * KDIM + c * GBK + ch * 8);
        }
    };

    float acc[4][8][4];
    #pragma unroll
    for (int mt = 0; mt < 4; mt++)
        #pragma unroll
        for (int nt = 0; nt < 8; nt++)
            #pragma unroll
            for (int i = 0; i < 4; i++) acc[mt][nt][i] = 0.f;

    issue(0, 0); cp_commit();
    issue(1, 1); cp_commit();
    issue(2, 2); cp_commit();

    for (int c = 0; c < GKCH; c++) {
        if (c < GKCH - 2)       cp_wait<2>();
        else if (c == GKCH - 2) cp_wait<1>();
        else                    cp_wait<0>();
        __syncthreads();
        // Stage (c+3)&3 == (c-1)&3: read in iter c-1, all warps passed the
        // barrier above => safe to refill.
        if (c + 3 < GKCH) { issue(c + 3, (c + 3) & 3); cp_commit(); }

        const int s = c & 3;
        const __half* Ab = As + s * GSTR + (warp_m * 64) * GPAD;
        const __half* Wb = Ws + s * GSTR + (warp_n * 64) * GPAD;
        #pragma unroll
        for (int kk = 0; kk < 2; kk++) {
            const int k0 = kk * 16;
            uint32_t af[4][4], bb[4][4];
            #pragma unroll
            for (int mt = 0; mt < 4; mt++)
                ldmx4(af[mt], Ab + (mt*16 + arow) * GPAD + k0 + acol);
            #pragma unroll
            for (int np = 0; np < 4; np++)
                ldmx4(bb[np], Wb + (np*16 + brow) * GPAD + k0 + bcol);
            #pragma unroll
            for (int mt = 0; mt < 4; mt++)
                #pragma unroll
                for (int np = 0; np < 4; np++) {
                    mma_f16(acc[mt][2*np    ], af[mt], &bb[np][0]);
                    mma_f16(acc[mt][2*np + 1], af[mt], &bb[np][2]);
                }
        }
    }

    #pragma unroll
    for (int nt = 0; nt < 8; nt++) {
        const int col = bm + warp_n * 64 + nt * 8 + t4 * 2;
        const float2 bv = *(const float2*)&bsel[col];
        #pragma unroll
        for (int mt = 0; mt < 4; mt++) {
            const int row = bn + warp_m * 64 + mt * 16 + gr;
            float2 v0 = make_float2(acc[mt][nt][0] + bv.x, acc[mt][nt][1] + bv.y);
            float2 v1 = make_float2(acc[mt][nt][2] + bv.x, acc[mt][nt][3] + bv.y);
            if (QKV) {
                const int h = col / DHEAD, d = col % DHEAD;
                const int bb0 = row / SEQ, s0 = row % SEQ;
                const int bb1 = (row + 8) / SEQ, s1 = (row + 8) % SEQ;
                *(uint32_t*)&Hout[(((size_t)(bb0*NHEAD + h)*SEQ + s0)*DHEAD) + d] = packh2(v0.x, v0.y);
                *(uint32_t*)&Hout[(((size_t)(bb1*NHEAD + h)*SEQ + s1)*DHEAD) + d] = packh2(v1.x, v1.y);
            } else {
                float* Y = (float*)Yv;
                *(float2*)&Y[(size_t)row * D_MODEL + col] = v0;
                *(float2*)&Y[(size_t)(row + 8) * D_MODEL + col] = v1;
            }
        }
    }
}

// ---------------------------------------------------------------------------
// Causal flash attention, fp16 mma + cp.async triple-buffered K/V staging.
// (unchanged from R9)
// ---------------------------------------------------------------------------
#define ABR   128
#define ABC   64
#define APAD  72
#define KVSTR (ABC * APAD)               // halves per K (or V) stage
#define ATTN_SMEM ((3 * 2 * KVSTR + ABR * APAD) * 2)   // 73728 B
#define QSCALE (0.125f * 1.44269504088896340736f)

__global__ __launch_bounds__(256, 2)
void attn_h()
{
    extern __shared__ __align__(16) char dsm[];
    __half* Ksm = (__half*)dsm;               // [3][64][APAD]
    __half* Vsm = Ksm + 3 * KVSTR;            // [3][64][APAD]
    __half* Qs  = Vsm + 3 * KVSTR;            // [128][APAD]

    const int bh = blockIdx.y;
    const int qb = (int)gridDim.x - 1 - (int)blockIdx.x;   // heavy blocks first
    const int q0 = qb * ABR;

    const __half* Qg = g_qh + (size_t)bh * SEQ * DHEAD;
    const __half* Kg = g_kh + (size_t)bh * SEQ * DHEAD;
    const __half* Vg = g_vh + (size_t)bh * SEQ * DHEAD;

    const int tid  = threadIdx.x;
    const int lane = tid & 31;
    const int wid  = tid >> 5;
    const int gr   = lane >> 2;
    const int t4   = lane & 3;
    const int r0   = wid * 16;

    const int lr   = lane & 7;
    const int arow = ((lane >> 3) & 1) * 8 + lr;
    const int acol = ((lane >> 4) & 1) * 8;
    const int brow = ((lane >> 4) & 1) * 8 + lr;   // K B-frags
    const int bcol = ((lane >> 3) & 1) * 8;
    const int trow = ((lane >> 3) & 1) * 8 + lr;   // V B-frags (trans)
    const int tcol = ((lane >> 4) & 1) * 8;

    const int jmax = 2 * qb + 1;

    auto issue = [&](int j, int s) {
        #pragma unroll
        for (int i = 0; i < 2; i++) {
            const int idx = tid + i * 256;     // 0..511
            const int r = idx >> 3, ch = idx & 7;
            const size_t goff = (size_t)(j * ABC + r) * DHEAD + ch * 8;
            cp16(Ksm + s * KVSTR + r * APAD + ch * 8, Kg + goff);
            cp16(Vsm + s * KVSTR + r * APAD + ch * 8, Vg + goff);
        }
    };

    issue(0, 0); cp_commit();
    issue(1, 1); cp_commit();

    // ---- stage Q (x log2e/8) ----
    {
        const int r = tid >> 1, h = (tid & 1) * 32;
        const __half* src = Qg + (size_t)(q0 + r) * DHEAD + h;
        #pragma unroll
        for (int i = 0; i < 4; i++) {
            uint4 u = *(const uint4*)(src + i * 8);
            const __half2* hp = (const __half2*)&u;
            uint4 o;
            uint32_t* op = (uint32_t*)&o;
            #pragma unroll
            for (int k = 0; k < 4; k++) {
                float2 f = __half22float2(hp[k]);
                op[k] = packh2(f.x * QSCALE, f.y * QSCALE);
            }
            *(uint4*)&Qs[r * APAD + h + i * 8] = o;
        }
    }
    __syncthreads();

    uint32_t Qf[4][4];
    #pragma unroll
    for (int kk = 0; kk < 4; kk++)
        ldmx4(Qf[kk], Qs + (r0 + arow) * APAD + kk * 16 + acol);

    float m0 = -1e30f, m1 = -1e30f, l0 = 0.f, l1 = 0.f;
    float oacc[8][4];
    #pragma unroll
    for (int nt = 0; nt < 8; nt++)
        #pragma unroll
        for (int i = 0; i < 4; i++) oacc[nt][i] = 0.f;

    const int rowa = q0 + r0 + gr;
    const int rowb = rowa + 8;

    for (int j = 0; j <= jmax; j++) {
        if (j + 1 <= jmax) cp_wait<1>(); else cp_wait<0>();
        __syncthreads();
        if (j + 2 <= jmax) { issue(j + 2, (j + 2) % 3); cp_commit(); }

        const int s = j % 3;
        const __half* Ks = Ksm + s * KVSTR;
        const __half* Vs = Vsm + s * KVSTR;
        const int kv0 = j * ABC;

        // ---- S = Qs * K^T (scale + log2e folded into Q) ----
        float sacc[8][4];
        #pragma unroll
        for (int nt = 0; nt < 8; nt++)
            #pragma unroll
            for (int i = 0; i < 4; i++) sacc[nt][i] = 0.f;

        #pragma unroll
        for (int kk = 0; kk < 4; kk++) {
            #pragma unroll
            for (int np = 0; np < 4; np++) {
                uint32_t bb[4];
                ldmx4(bb, Ks + (np*16 + brow) * APAD + kk*16 + bcol);
                mma_f16(sacc[2*np    ], Qf[kk], &bb[0]);
                mma_f16(sacc[2*np + 1], Qf[kk], &bb[2]);
            }
        }

        // ---- causal mask (diag tiles only) ----
        if (kv0 + ABC - 1 > q0) {
            #pragma unroll
            for (int nt = 0; nt < 8; nt++) {
                const int col0 = kv0 + nt*8 + 2*t4;
                if (col0     > rowa) sacc[nt][0] = -1e30f;
                if (col0 + 1 > rowa) sacc[nt][1] = -1e30f;
                if (col0     > rowb) sacc[nt][2] = -1e30f;
                if (col0 + 1 > rowb) sacc[nt][3] = -1e30f;
            }
        }

        // ---- online softmax, log2 domain (rows gr, gr+8) ----
        float mx0 = -1e30f, mx1 = -1e30f;
        #pragma unroll
        for (int nt = 0; nt < 8; nt++) {
            mx0 = fmaxf(mx0, fmaxf(sacc[nt][0], sacc[nt][1]));
            mx1 = fmaxf(mx1, fmaxf(sacc[nt][2], sacc[nt][3]));
        }
        mx0 = fmaxf(mx0, __shfl_xor_sync(0xffffffffu, mx0, 1));
        mx0 = fmaxf(mx0, __shfl_xor_sync(0xffffffffu, mx0, 2));
        mx1 = fmaxf(mx1, __shfl_xor_sync(0xffffffffu, mx1, 1));
        mx1 = fmaxf(mx1, __shfl_xor_sync(0xffffffffu, mx1, 2));

        const float mn0 = fmaxf(m0, mx0), mn1 = fmaxf(m1, mx1);
        const float a0 = ex2f(m0 - mn0), a1 = ex2f(m1 - mn1);
        float s0 = 0.f, s1 = 0.f;
        #pragma unroll
        for (int nt = 0; nt < 8; nt++) {
            sacc[nt][0] = ex2f(sacc[nt][0] - mn0);
            sacc[nt][1] = ex2f(sacc[nt][1] - mn0);
            sacc[nt][2] = ex2f(sacc[nt][2] - mn1);
            sacc[nt][3] = ex2f(sacc[nt][3] - mn1);
            s0 += sacc[nt][0] + sacc[nt][1];
            s1 += sacc[nt][2] + sacc[nt][3];
        }
        s0 += __shfl_xor_sync(0xffffffffu, s0, 1);
        s0 += __shfl_xor_sync(0xffffffffu, s0, 2);
        s1 += __shfl_xor_sync(0xffffffffu, s1, 1);
        s1 += __shfl_xor_sync(0xffffffffu, s1, 2);
        l0 = l0 * a0 + s0;  m0 = mn0;
        l1 = l1 * a1 + s1;  m1 = mn1;
        #pragma unroll
        for (int nt = 0; nt < 8; nt++) {
            oacc[nt][0] *= a0; oacc[nt][1] *= a0;
            oacc[nt][2] *= a1; oacc[nt][3] *= a1;
        }

        // ---- O += P * V ; P packed from regs (C-frag == A-frag) ----
        #pragma unroll
        for (int kk = 0; kk < 4; kk++) {
            uint32_t pf[4];
            pf[0] = packh2(sacc[2*kk    ][0], sacc[2*kk    ][1]);
            pf[1] = packh2(sacc[2*kk    ][2], sacc[2*kk    ][3]);
            pf[2] = packh2(sacc[2*kk + 1][0], sacc[2*kk + 1][1]);
            pf[3] = packh2(sacc[2*kk + 1][2], sacc[2*kk + 1][3]);
            #pragma unroll
            for (int np = 0; np < 4; np++) {
                uint32_t bt[4];
                ldmx4t(bt, Vs + (kk*16 + trow) * APAD + np*16 + tcol);
                mma_f16(oacc[2*np    ], pf, &bt[0]);
                mma_f16(oacc[2*np + 1], pf, &bt[2]);
            }
        }
    }

    // ---- normalize + write half [B,S,D] ----
    const float inv0 = 1.f / l0, inv1 = 1.f / l1;
    const int b = bh >> 4, h = bh & 15;
    #pragma unroll
    for (int nt = 0; nt < 8; nt++) {
        const int col = h * DHEAD + nt*8 + 2*t4;
        *(uint32_t*)&g_ah[((size_t)(b*SEQ + rowa)) * D_MODEL + col] =
            packh2(oacc[nt][0] * inv0, oacc[nt][1] * inv0);
        *(uint32_t*)&g_ah[((size_t)(b*SEQ + rowb)) * D_MODEL + col] =
            packh2(oacc[nt][2] * inv1, oacc[nt][3] * inv1);
    }
}

// ---------------------------------------------------------------------------
extern "C" void kernel_launch(void* const* d_in, const int* in_sizes, int n_in,
                              void* d_out, int out_size)
{
    const float* x  = (const float*)d_in[0];
    const float* Wq = (const float*)d_in[1];
    const float* bq = (const float*)d_in[2];
    const float* Wk = (const float*)d_in[3];
    const float* bk = (const float*)d_in[4];
    const float* Wv = (const float*)d_in[5];
    const float* bv = (const float*)d_in[6];
    const float* Wo = (const float*)d_in[7];
    const float* bo = (const float*)d_in[8];

    __half *xh, *wqh, *wkh, *wvh, *woh, *ah;
    cudaGetSymbolAddress((void**)&xh,  g_xh);
    cudaGetSymbolAddress((void**)&wqh, g_wqh);
    cudaGetSymbolAddress((void**)&wkh, g_wkh);
    cudaGetSymbolAddress((void**)&wvh, g_wvh);
    cudaGetSymbolAddress((void**)&woh, g_woh);
    cudaGetSymbolAddress((void**)&ah,  g_ah);

    // fused fp32 -> fp16 pre-pass (1 launch)
    cvt_all<<<NCVT/256, 256>>>(x, Wq, Wk, Wv, Wo);

    cudaFuncSetAttribute(gemm_h<true>,
                         cudaFuncAttributeMaxDynamicSharedMemorySize, GEMM_SMEM);
    cudaFuncSetAttribute(gemm_h<false>,
                         cudaFuncAttributeMaxDynamicSharedMemorySize, GEMM_SMEM);
    cudaFuncSetAttribute(attn_h,
                         cudaFuncAttributeMaxDynamicSharedMemorySize, ATTN_SMEM);

    // fused QKV projection (1 launch, z selects head)
    gemm_h<true><<<dim3(D_MODEL/128, NTOK/128, 3), 128, GEMM_SMEM>>>(
        xh, wqh, bq, wkh, bk, wvh, bv, nullptr);

    attn_h<<<dim3(SEQ/ABR, BATCH*NHEAD), 256, ATTN_SMEM>>>();

    // output projection
    gemm_h<false><<<dim3(D_MODEL/128, NTOK/128, 1), 128, GEMM_SMEM>>>(
        ah, woh, bo, nullptr, nullptr, nullptr, nullptr, d_out);
}

// round 11
// speedup vs baseline: 16.3678x; 1.0811x over previous
#include <cuda_runtime.h>
#include <cuda_fp16.h>
#include <math.h>
#include <cstdint>

#define D_MODEL 1024
#define NHEAD   16
#define DHEAD   64
#define BATCH   4
#define SEQ     2048
#define NTOK    (BATCH*SEQ)   // 8192
#define KDIM    1024

// ---------------------------------------------------------------------------
// fp16 scratch (allocation-free rule: __device__ globals)
// ---------------------------------------------------------------------------
__device__ __half g_xh[(size_t)NTOK*KDIM];
__device__ __half g_wqh[(size_t)KDIM*D_MODEL];
__device__ __half g_wkh[(size_t)KDIM*D_MODEL];
__device__ __half g_wvh[(size_t)KDIM*D_MODEL];
__device__ __half g_woh[(size_t)KDIM*D_MODEL];
__device__ __half g_qh[(size_t)BATCH*NHEAD*SEQ*DHEAD];   // [B,H,S,Dh]
__device__ __half g_kh[(size_t)BATCH*NHEAD*SEQ*DHEAD];
__device__ __half g_vh[(size_t)BATCH*NHEAD*SEQ*DHEAD];
__device__ __half g_ah[(size_t)NTOK*D_MODEL];            // [B,S,D]

// ---------------------------------------------------------------------------
// helpers
// ---------------------------------------------------------------------------
__device__ __forceinline__ uint32_t packh2(float a, float b) {
    __half2 h = __floats2half2_rn(a, b);
    return *reinterpret_cast<uint32_t*>(&h);
}
__device__ __forceinline__ float ex2f(float x) {
    float y;
    asm("ex2.approx.ftz.f32 %0, %1;" : "=f"(y) : "f"(x));
    return y;
}
__device__ __forceinline__ void mma_f16(float* c, const uint32_t* a, const uint32_t* b) {
    asm volatile(
        "mma.sync.aligned.m16n8k16.row.col.f32.f16.f16.f32 "
        "{%0,%1,%2,%3}, {%4,%5,%6,%7}, {%8,%9}, {%0,%1,%2,%3};"
        : "+f"(c[0]), "+f"(c[1]), "+f"(c[2]), "+f"(c[3])
        : "r"(a[0]), "r"(a[1]), "r"(a[2]), "r"(a[3]), "r"(b[0]), "r"(b[1]));
}
__device__ __forceinline__ void ldmx4(uint32_t* r, const void* p) {
    uint32_t a = (uint32_t)__cvta_generic_to_shared(p);
    asm volatile("ldmatrix.sync.aligned.m8n8.x4.shared.b16 {%0,%1,%2,%3}, [%4];"
                 : "=r"(r[0]), "=r"(r[1]), "=r"(r[2]), "=r"(r[3]) : "r"(a));
}
__device__ __forceinline__ void ldmx4t(uint32_t* r, const void* p) {
    uint32_t a = (uint32_t)__cvta_generic_to_shared(p);
    asm volatile("ldmatrix.sync.aligned.m8n8.x4.trans.shared.b16 {%0,%1,%2,%3}, [%4];"
                 : "=r"(r[0]), "=r"(r[1]), "=r"(r[2]), "=r"(r[3]) : "r"(a));
}
__device__ __forceinline__ void cp16(void* s, const void* g) {
    uint32_t a = (uint32_t)__cvta_generic_to_shared(s);
    asm volatile("cp.async.cg.shared.global [%0], [%1], 16;" :: "r"(a), "l"(g) : "memory");
}
__device__ __forceinline__ void cp_commit() {
    asm volatile("cp.async.commit_group;" ::: "memory");
}
template<int N>
__device__ __forceinline__ void cp_wait() {
    asm volatile("cp.async.wait_group %0;" :: "n"(N) : "memory");
}

// ---------------------------------------------------------------------------
// fused fp32 -> fp16 conversion
// ---------------------------------------------------------------------------
#define NX8 (NTOK * KDIM / 8)       // 1048576 = 2^20
#define NW8 (KDIM * D_MODEL / 8)    // 131072  = 2^17
#define NCVT (NX8 + 4 * NW8)        // 1572864

__global__ __launch_bounds__(256)
void cvt_all(const float* __restrict__ x,
             const float* __restrict__ w0, const float* __restrict__ w1,
             const float* __restrict__ w2, const float* __restrict__ w3)
{
    const int i = blockIdx.x * 256 + threadIdx.x;
    const float* src;
    __half* dst;
    int off;
    if (i < NX8) {
        src = x; dst = g_xh; off = i;
    } else {
        const int t = i - NX8;
        const int w = t >> 17;            // NW8 = 2^17
        off = t & (NW8 - 1);
        switch (w) {
            case 0:  src = w0; dst = g_wqh; break;
            case 1:  src = w1; dst = g_wkh; break;
            case 2:  src = w2; dst = g_wvh; break;
            default: src = w3; dst = g_woh; break;
        }
    }
    float4 a = ((const float4*)src)[2*off];
    float4 b = ((const float4*)src)[2*off + 1];
    uint4 o;
    o.x = packh2(a.x, a.y);  o.y = packh2(a.z, a.w);
    o.z = packh2(b.x, b.y);  o.w = packh2(b.z, b.w);
    ((uint4*)dst)[off] = o;
}

// ---------------------------------------------------------------------------
// fp16 GEMM (NT), cp.async 3-stage, CTA 128x128, 128 threads (4 warps, 2x2),
// warp tile 64x64. 3 CTAs/SM (smem 61.4KB, regs capped by launch_bounds)
// = 12 warps/SM for latency hiding while keeping high AI per smem byte.
// ---------------------------------------------------------------------------
#define GBK   32
#define GKCH  (KDIM / GBK)      // 32
#define GPAD  40                // halves per smem row
#define GSTR  (128 * GPAD)      // halves per stage per operand
#define GEMM_SMEM (3 * 2 * GSTR * 2)   // 61440 B

template<bool QKV>
__global__ __launch_bounds__(128, 3)
void gemm_h(const __half* __restrict__ A,
            const __half* __restrict__ W0, const float* __restrict__ b0,
            const __half* __restrict__ W1, const float* __restrict__ b1,
            const __half* __restrict__ W2, const float* __restrict__ b2,
            void* __restrict__ Yv)
{
    extern __shared__ __align__(16) char dsm[];
    __half* As = (__half*)dsm;            // [3][128][GPAD]
    __half* Ws = As + 3 * GSTR;           // [3][128][GPAD]

    const __half* Wsel = W0;
    const float*  bsel = b0;
    __half* Hout = g_qh;
    if (QKV) {
        if (blockIdx.z == 1)      { Wsel = W1; bsel = b1; Hout = g_kh; }
        else if (blockIdx.z == 2) { Wsel = W2; bsel = b2; Hout = g_vh; }
    }

    const int tid    = threadIdx.x;
    const int lane   = tid & 31;
    const int wid    = tid >> 5;         // 0..3
    const int warp_m = wid & 1;          // 64-row group
    const int warp_n = wid >> 1;         // 64-col group
    const int gr     = lane >> 2;
    const int t4     = lane & 3;

    const int lr   = lane & 7;
    const int arow = ((lane >> 3) & 1) * 8 + lr;
    const int acol = ((lane >> 4) & 1) * 8;
    const int brow = ((lane >> 4) & 1) * 8 + lr;
    const int bcol = ((lane >> 3) & 1) * 8;

    const int bn = blockIdx.y * 128;
    const int bm = blockIdx.x * 128;

    const __half* Ag = A + (size_t)bn * KDIM;
    const __half* Wg = Wsel + (size_t)bm * KDIM;

    // 128 rows x 4 chunks(16B) per operand = 512 chunks; 4/thread/operand
    auto issue = [&](int c, int s) {
        __half* ab = As + s * GSTR;
        __half* wb = Ws + s * GSTR;
        #pragma unroll
        for (int i = 0; i < 4; i++) {
            const int idx = tid + i * 128;        // 0..511
            const int r = idx >> 2, ch = idx & 3;
            cp16(ab + r * GPAD + ch * 8, Ag + (size_t)r * KDIM + c * GBK + ch * 8);
            cp16(wb + r * GPAD + ch * 8, Wg + (size_t)r * KDIM + c * GBK + ch * 8);
        }
    };

    float acc[4][8][4];
    #pragma unroll
    for (int mt = 0; mt < 4; mt++)
        #pragma unroll
        for (int nt = 0; nt < 8; nt++)
            #pragma unroll
            for (int i = 0; i < 4; i++) acc[mt][nt][i] = 0.f;

    issue(0, 0); cp_commit();
    issue(1, 1); cp_commit();

    for (int c = 0; c < GKCH; c++) {
        if (c == GKCH - 1) cp_wait<0>(); else cp_wait<1>();
        __syncthreads();
        // Stage (c+2)%3 == (c-1)%3: read in iter c-1, all warps passed the
        // barrier above => safe to refill.
        if (c + 2 < GKCH) { issue(c + 2, (c + 2) % 3); cp_commit(); }

        const int s = c % 3;
        const __half* Ab = As + s * GSTR + (warp_m * 64) * GPAD;
        const __half* Wb = Ws + s * GSTR + (warp_n * 64) * GPAD;
        #pragma unroll
        for (int kk = 0; kk < 2; kk++) {
            const int k0 = kk * 16;
            uint32_t af[4][4], bb[4][4];
            #pragma unroll
            for (int mt = 0; mt < 4; mt++)
                ldmx4(af[mt], Ab + (mt*16 + arow) * GPAD + k0 + acol);
            #pragma unroll
            for (int np = 0; np < 4; np++)
                ldmx4(bb[np], Wb + (np*16 + brow) * GPAD + k0 + bcol);
            #pragma unroll
            for (int mt = 0; mt < 4; mt++)
                #pragma unroll
                for (int np = 0; np < 4; np++) {
                    mma_f16(acc[mt][2*np    ], af[mt], &bb[np][0]);
                    mma_f16(acc[mt][2*np + 1], af[mt], &bb[np][2]);
                }
        }
    }

    #pragma unroll
    for (int nt = 0; nt < 8; nt++) {
        const int col = bm + warp_n * 64 + nt * 8 + t4 * 2;
        const float2 bv = *(const float2*)&bsel[col];
        #pragma unroll
        for (int mt = 0; mt < 4; mt++) {
            const int row = bn + warp_m * 64 + mt * 16 + gr;
            float2 v0 = make_float2(acc[mt][nt][0] + bv.x, acc[mt][nt][1] + bv.y);
            float2 v1 = make_float2(acc[mt][nt][2] + bv.x, acc[mt][nt][3] + bv.y);
            if (QKV) {
                const int h = col / DHEAD, d = col % DHEAD;
                const int bb0 = row / SEQ, s0 = row % SEQ;
                const int bb1 = (row + 8) / SEQ, s1 = (row + 8) % SEQ;
                *(uint32_t*)&Hout[(((size_t)(bb0*NHEAD + h)*SEQ + s0)*DHEAD) + d] = packh2(v0.x, v0.y);
                *(uint32_t*)&Hout[(((size_t)(bb1*NHEAD + h)*SEQ + s1)*DHEAD) + d] = packh2(v1.x, v1.y);
            } else {
                float* Y = (float*)Yv;
                *(float2*)&Y[(size_t)row * D_MODEL + col] = v0;
                *(float2*)&Y[(size_t)(row + 8) * D_MODEL + col] = v1;
            }
        }
    }
}

// ---------------------------------------------------------------------------
// Causal flash attention, fp16 mma + cp.async triple-buffered K/V staging.
// (unchanged from R9/R10)
// ---------------------------------------------------------------------------
#define ABR   128
#define ABC   64
#define APAD  72
#define KVSTR (ABC * APAD)               // halves per K (or V) stage
#define ATTN_SMEM ((3 * 2 * KVSTR + ABR * APAD) * 2)   // 73728 B
#define QSCALE (0.125f * 1.44269504088896340736f)

__global__ __launch_bounds__(256, 2)
void attn_h()
{
    extern __shared__ __align__(16) char dsm[];
    __half* Ksm = (__half*)dsm;               // [3][64][APAD]
    __half* Vsm = Ksm + 3 * KVSTR;            // [3][64][APAD]
    __half* Qs  = Vsm + 3 * KVSTR;            // [128][APAD]

    const int bh = blockIdx.y;
    const int qb = (int)gridDim.x - 1 - (int)blockIdx.x;   // heavy blocks first
    const int q0 = qb * ABR;

    const __half* Qg = g_qh + (size_t)bh * SEQ * DHEAD;
    const __half* Kg = g_kh + (size_t)bh * SEQ * DHEAD;
    const __half* Vg = g_vh + (size_t)bh * SEQ * DHEAD;

    const int tid  = threadIdx.x;
    const int lane = tid & 31;
    const int wid  = tid >> 5;
    const int gr   = lane >> 2;
    const int t4   = lane & 3;
    const int r0   = wid * 16;

    const int lr   = lane & 7;
    const int arow = ((lane >> 3) & 1) * 8 + lr;
    const int acol = ((lane >> 4) & 1) * 8;
    const int brow = ((lane >> 4) & 1) * 8 + lr;   // K B-frags
    const int bcol = ((lane >> 3) & 1) * 8;
    const int trow = ((lane >> 3) & 1) * 8 + lr;   // V B-frags (trans)
    const int tcol = ((lane >> 4) & 1) * 8;

    const int jmax = 2 * qb + 1;

    auto issue = [&](int j, int s) {
        #pragma unroll
        for (int i = 0; i < 2; i++) {
            const int idx = tid + i * 256;     // 0..511
            const int r = idx >> 3, ch = idx & 7;
            const size_t goff = (size_t)(j * ABC + r) * DHEAD + ch * 8;
            cp16(Ksm + s * KVSTR + r * APAD + ch * 8, Kg + goff);
            cp16(Vsm + s * KVSTR + r * APAD + ch * 8, Vg + goff);
        }
    };

    issue(0, 0); cp_commit();
    issue(1, 1); cp_commit();

    // ---- stage Q (x log2e/8) ----
    {
        const int r = tid >> 1, h = (tid & 1) * 32;
        const __half* src = Qg + (size_t)(q0 + r) * DHEAD + h;
        #pragma unroll
        for (int i = 0; i < 4; i++) {
            uint4 u = *(const uint4*)(src + i * 8);
            const __half2* hp = (const __half2*)&u;
            uint4 o;
            uint32_t* op = (uint32_t*)&o;
            #pragma unroll
            for (int k = 0; k < 4; k++) {
                float2 f = __half22float2(hp[k]);
                op[k] = packh2(f.x * QSCALE, f.y * QSCALE);
            }
            *(uint4*)&Qs[r * APAD + h + i * 8] = o;
        }
    }
    __syncthreads();

    uint32_t Qf[4][4];
    #pragma unroll
    for (int kk = 0; kk < 4; kk++)
        ldmx4(Qf[kk], Qs + (r0 + arow) * APAD + kk * 16 + acol);

    float m0 = -1e30f, m1 = -1e30f, l0 = 0.f, l1 = 0.f;
    float oacc[8][4];
    #pragma unroll
    for (int nt = 0; nt < 8; nt++)
        #pragma unroll
        for (int i = 0; i < 4; i++) oacc[nt][i] = 0.f;

    const int rowa = q0 + r0 + gr;
    const int rowb = rowa + 8;

    for (int j = 0; j <= jmax; j++) {
        if (j + 1 <= jmax) cp_wait<1>(); else cp_wait<0>();
        __syncthreads();
        if (j + 2 <= jmax) { issue(j + 2, (j + 2) % 3); cp_commit(); }

        const int s = j % 3;
        const __half* Ks = Ksm + s * KVSTR;
        const __half* Vs = Vsm + s * KVSTR;
        const int kv0 = j * ABC;

        // ---- S = Qs * K^T (scale + log2e folded into Q) ----
        float sacc[8][4];
        #pragma unroll
        for (int nt = 0; nt < 8; nt++)
            #pragma unroll
            for (int i = 0; i < 4; i++) sacc[nt][i] = 0.f;

        #pragma unroll
        for (int kk = 0; kk < 4; kk++) {
            #pragma unroll
            for (int np = 0; np < 4; np++) {
                uint32_t bb[4];
                ldmx4(bb, Ks + (np*16 + brow) * APAD + kk*16 + bcol);
                mma_f16(sacc[2*np    ], Qf[kk], &bb[0]);
                mma_f16(sacc[2*np + 1], Qf[kk], &bb[2]);
            }
        }

        // ---- causal mask (diag tiles only) ----
        if (kv0 + ABC - 1 > q0) {
            #pragma unroll
            for (int nt = 0; nt < 8; nt++) {
                const int col0 = kv0 + nt*8 + 2*t4;
                if (col0     > rowa) sacc[nt][0] = -1e30f;
                if (col0 + 1 > rowa) sacc[nt][1] = -1e30f;
                if (col0     > rowb) sacc[nt][2] = -1e30f;
                if (col0 + 1 > rowb) sacc[nt][3] = -1e30f;
            }
        }

        // ---- online softmax, log2 domain (rows gr, gr+8) ----
        float mx0 = -1e30f, mx1 = -1e30f;
        #pragma unroll
        for (int nt = 0; nt < 8; nt++) {
            mx0 = fmaxf(mx0, fmaxf(sacc[nt][0], sacc[nt][1]));
            mx1 = fmaxf(mx1, fmaxf(sacc[nt][2], sacc[nt][3]));
        }
        mx0 = fmaxf(mx0, __shfl_xor_sync(0xffffffffu, mx0, 1));
        mx0 = fmaxf(mx0, __shfl_xor_sync(0xffffffffu, mx0, 2));
        mx1 = fmaxf(mx1, __shfl_xor_sync(0xffffffffu, mx1, 1));
        mx1 = fmaxf(mx1, __shfl_xor_sync(0xffffffffu, mx1, 2));

        const float mn0 = fmaxf(m0, mx0), mn1 = fmaxf(m1, mx1);
        const float a0 = ex2f(m0 - mn0), a1 = ex2f(m1 - mn1);
        float s0 = 0.f, s1 = 0.f;
        #pragma unroll
        for (int nt = 0; nt < 8; nt++) {
            sacc[nt][0] = ex2f(sacc[nt][0] - mn0);
            sacc[nt][1] = ex2f(sacc[nt][1] - mn0);
            sacc[nt][2] = ex2f(sacc[nt][2] - mn1);
            sacc[nt][3] = ex2f(sacc[nt][3] - mn1);
            s0 += sacc[nt][0] + sacc[nt][1];
            s1 += sacc[nt][2] + sacc[nt][3];
        }
        s0 += __shfl_xor_sync(0xffffffffu, s0, 1);
        s0 += __shfl_xor_sync(0xffffffffu, s0, 2);
        s1 += __shfl_xor_sync(0xffffffffu, s1, 1);
        s1 += __shfl_xor_sync(0xffffffffu, s1, 2);
        l0 = l0 * a0 + s0;  m0 = mn0;
        l1 = l1 * a1 + s1;  m1 = mn1;
        #pragma unroll
        for (int nt = 0; nt < 8; nt++) {
            oacc[nt][0] *= a0; oacc[nt][1] *= a0;
            oacc[nt][2] *= a1; oacc[nt][3] *= a1;
        }

        // ---- O += P * V ; P packed from regs (C-frag == A-frag) ----
        #pragma unroll
        for (int kk = 0; kk < 4; kk++) {
            uint32_t pf[4];
            pf[0] = packh2(sacc[2*kk    ][0], sacc[2*kk    ][1]);
            pf[1] = packh2(sacc[2*kk    ][2], sacc[2*kk    ][3]);
            pf[2] = packh2(sacc[2*kk + 1][0], sacc[2*kk + 1][1]);
            pf[3] = packh2(sacc[2*kk + 1][2], sacc[2*kk + 1][3]);
            #pragma unroll
            for (int np = 0; np < 4; np++) {
                uint32_t bt[4];
                ldmx4t(bt, Vs + (kk*16 + trow) * APAD + np*16 + tcol);
                mma_f16(oacc[2*np    ], pf, &bt[0]);
                mma_f16(oacc[2*np + 1], pf, &bt[2]);
            }
        }
    }

    // ---- normalize + write half [B,S,D] ----
    const float inv0 = 1.f / l0, inv1 = 1.f / l1;
    const int b = bh >> 4, h = bh & 15;
    #pragma unroll
    for (int nt = 0; nt < 8; nt++) {
        const int col = h * DHEAD + nt*8 + 2*t4;
        *(uint32_t*)&g_ah[((size_t)(b*SEQ + rowa)) * D_MODEL + col] =
            packh2(oacc[nt][0] * inv0, oacc[nt][1] * inv0);
        *(uint32_t*)&g_ah[((size_t)(b*SEQ + rowb)) * D_MODEL + col] =
            packh2(oacc[nt][2] * inv1, oacc[nt][3] * inv1);
    }
}

// ---------------------------------------------------------------------------
extern "C" void kernel_launch(void* const* d_in, const int* in_sizes, int n_in,
                              void* d_out, int out_size)
{
    const float* x  = (const float*)d_in[0];
    const float* Wq = (const float*)d_in[1];
    const float* bq = (const float*)d_in[2];
    const float* Wk = (const float*)d_in[3];
    const float* bk = (const float*)d_in[4];
    const float* Wv = (const float*)d_in[5];
    const float* bv = (const float*)d_in[6];
    const float* Wo = (const float*)d_in[7];
    const float* bo = (const float*)d_in[8];

    __half *xh, *wqh, *wkh, *wvh, *woh, *ah;
    cudaGetSymbolAddress((void**)&xh,  g_xh);
    cudaGetSymbolAddress((void**)&wqh, g_wqh);
    cudaGetSymbolAddress((void**)&wkh, g_wkh);
    cudaGetSymbolAddress((void**)&wvh, g_wvh);
    cudaGetSymbolAddress((void**)&woh, g_woh);
    cudaGetSymbolAddress((void**)&ah,  g_ah);

    // fused fp32 -> fp16 pre-pass (1 launch)
    cvt_all<<<NCVT/256, 256>>>(x, Wq, Wk, Wv, Wo);

    cudaFuncSetAttribute(gemm_h<true>,
                         cudaFuncAttributeMaxDynamicSharedMemorySize, GEMM_SMEM);
    cudaFuncSetAttribute(gemm_h<false>,
                         cudaFuncAttributeMaxDynamicSharedMemorySize, GEMM_SMEM);
    cudaFuncSetAttribute(attn_h,
                         cudaFuncAttributeMaxDynamicSharedMemorySize, ATTN_SMEM);

    // fused QKV projection (1 launch, z selects head)
    gemm_h<true><<<dim3(D_MODEL/128, NTOK/128, 3), 128, GEMM_SMEM>>>(
        xh, wqh, bq, wkh, bk, wvh, bv, nullptr);

    attn_h<<<dim3(SEQ/ABR, BATCH*NHEAD), 256, ATTN_SMEM>>>();

    // output projection
    gemm_h<false><<<dim3(D_MODEL/128, NTOK/128, 1), 128, GEMM_SMEM>>>(
        ah, woh, bo, nullptr, nullptr, nullptr, nullptr, d_out);
}

// round 12
// speedup vs baseline: 16.6458x; 1.0170x over previous
#include <cuda_runtime.h>
#include <cuda_fp16.h>
#include <math.h>
#include <cstdint>

#define D_MODEL 1024
#define NHEAD   16
#define DHEAD   64
#define BATCH   4
#define SEQ     2048
#define NTOK    (BATCH*SEQ)   // 8192
#define KDIM    1024

// ---------------------------------------------------------------------------
// fp16 scratch (allocation-free rule: __device__ globals)
// ---------------------------------------------------------------------------
__device__ __half g_xh[(size_t)NTOK*KDIM];
__device__ __half g_wqh[(size_t)KDIM*D_MODEL];
__device__ __half g_wkh[(size_t)KDIM*D_MODEL];
__device__ __half g_wvh[(size_t)KDIM*D_MODEL];
__device__ __half g_woh[(size_t)KDIM*D_MODEL];
__device__ __half g_qh[(size_t)BATCH*NHEAD*SEQ*DHEAD];   // [B,H,S,Dh]
__device__ __half g_kh[(size_t)BATCH*NHEAD*SEQ*DHEAD];
__device__ __half g_vh[(size_t)BATCH*NHEAD*SEQ*DHEAD];
__device__ __half g_ah[(size_t)NTOK*D_MODEL];            // [B,S,D]

// ---------------------------------------------------------------------------
// helpers
// ---------------------------------------------------------------------------
__device__ __forceinline__ uint32_t packh2(float a, float b) {
    __half2 h = __floats2half2_rn(a, b);
    return *reinterpret_cast<uint32_t*>(&h);
}
__device__ __forceinline__ float ex2f(float x) {
    float y;
    asm("ex2.approx.ftz.f32 %0, %1;" : "=f"(y) : "f"(x));
    return y;
}
__device__ __forceinline__ void mma_f16(float* c, const uint32_t* a, const uint32_t* b) {
    asm volatile(
        "mma.sync.aligned.m16n8k16.row.col.f32.f16.f16.f32 "
        "{%0,%1,%2,%3}, {%4,%5,%6,%7}, {%8,%9}, {%0,%1,%2,%3};"
        : "+f"(c[0]), "+f"(c[1]), "+f"(c[2]), "+f"(c[3])
        : "r"(a[0]), "r"(a[1]), "r"(a[2]), "r"(a[3]), "r"(b[0]), "r"(b[1]));
}
__device__ __forceinline__ void ldmx4(uint32_t* r, const void* p) {
    uint32_t a = (uint32_t)__cvta_generic_to_shared(p);
    asm volatile("ldmatrix.sync.aligned.m8n8.x4.shared.b16 {%0,%1,%2,%3}, [%4];"
                 : "=r"(r[0]), "=r"(r[1]), "=r"(r[2]), "=r"(r[3]) : "r"(a));
}
__device__ __forceinline__ void ldmx4t(uint32_t* r, const void* p) {
    uint32_t a = (uint32_t)__cvta_generic_to_shared(p);
    asm volatile("ldmatrix.sync.aligned.m8n8.x4.trans.shared.b16 {%0,%1,%2,%3}, [%4];"
                 : "=r"(r[0]), "=r"(r[1]), "=r"(r[2]), "=r"(r[3]) : "r"(a));
}
__device__ __forceinline__ void cp16(void* s, const void* g) {
    uint32_t a = (uint32_t)__cvta_generic_to_shared(s);
    asm volatile("cp.async.cg.shared.global [%0], [%1], 16;" :: "r"(a), "l"(g) : "memory");
}
__device__ __forceinline__ void cp_commit() {
    asm volatile("cp.async.commit_group;" ::: "memory");
}
template<int N>
__device__ __forceinline__ void cp_wait() {
    asm volatile("cp.async.wait_group %0;" :: "n"(N) : "memory");
}

// ---------------------------------------------------------------------------
// fused fp32 -> fp16 conversion
// ---------------------------------------------------------------------------
#define NX8 (NTOK * KDIM / 8)       // 1048576 = 2^20
#define NW8 (KDIM * D_MODEL / 8)    // 131072  = 2^17
#define NCVT (NX8 + 4 * NW8)        // 1572864

__global__ __launch_bounds__(256)
void cvt_all(const float* __restrict__ x,
             const float* __restrict__ w0, const float* __restrict__ w1,
             const float* __restrict__ w2, const float* __restrict__ w3)
{
    const int i = blockIdx.x * 256 + threadIdx.x;
    const float* src;
    __half* dst;
    int off;
    if (i < NX8) {
        src = x; dst = g_xh; off = i;
    } else {
        const int t = i - NX8;
        const int w = t >> 17;            // NW8 = 2^17
        off = t & (NW8 - 1);
        switch (w) {
            case 0:  src = w0; dst = g_wqh; break;
            case 1:  src = w1; dst = g_wkh; break;
            case 2:  src = w2; dst = g_wvh; break;
            default: src = w3; dst = g_woh; break;
        }
    }
    float4 a = ((const float4*)src)[2*off];
    float4 b = ((const float4*)src)[2*off + 1];
    uint4 o;
    o.x = packh2(a.x, a.y);  o.y = packh2(a.z, a.w);
    o.z = packh2(b.x, b.y);  o.w = packh2(b.z, b.w);
    ((uint4*)dst)[off] = o;
}

// ---------------------------------------------------------------------------
// QKV fp16 GEMM (NT), cp.async 3-stage, CTA 128x128, 128 thr, warp 64x64.
// 3 CTAs/SM; grid (8,64,3) = 1536 CTAs -> 86.5% wave utilization.
// ---------------------------------------------------------------------------
#define GBK   32
#define GKCH  (KDIM / GBK)      // 32
#define GPAD  40                // halves per smem row
#define GSTR  (128 * GPAD)      // halves per stage per operand
#define GEMM_SMEM (3 * 2 * GSTR * 2)   // 61440 B

__global__ __launch_bounds__(128, 3)
void gemm_qkv(const __half* __restrict__ A,
              const __half* __restrict__ W0, const float* __restrict__ b0,
              const __half* __restrict__ W1, const float* __restrict__ b1,
              const __half* __restrict__ W2, const float* __restrict__ b2)
{
    extern __shared__ __align__(16) char dsm[];
    __half* As = (__half*)dsm;            // [3][128][GPAD]
    __half* Ws = As + 3 * GSTR;           // [3][128][GPAD]

    const __half* Wsel = W0;
    const float*  bsel = b0;
    __half* Hout = g_qh;
    if (blockIdx.z == 1)      { Wsel = W1; bsel = b1; Hout = g_kh; }
    else if (blockIdx.z == 2) { Wsel = W2; bsel = b2; Hout = g_vh; }

    const int tid    = threadIdx.x;
    const int lane   = tid & 31;
    const int wid    = tid >> 5;         // 0..3
    const int warp_m = wid & 1;
    const int warp_n = wid >> 1;
    const int gr     = lane >> 2;
    const int t4     = lane & 3;

    const int lr   = lane & 7;
    const int arow = ((lane >> 3) & 1) * 8 + lr;
    const int acol = ((lane >> 4) & 1) * 8;
    const int brow = ((lane >> 4) & 1) * 8 + lr;
    const int bcol = ((lane >> 3) & 1) * 8;

    const int bn = blockIdx.y * 128;
    const int bm = blockIdx.x * 128;

    const __half* Ag = A + (size_t)bn * KDIM;
    const __half* Wg = Wsel + (size_t)bm * KDIM;

    auto issue = [&](int c, int s) {
        __half* ab = As + s * GSTR;
        __half* wb = Ws + s * GSTR;
        #pragma unroll
        for (int i = 0; i < 4; i++) {
            const int idx = tid + i * 128;        // 0..511
            const int r = idx >> 2, ch = idx & 3;
            cp16(ab + r * GPAD + ch * 8, Ag + (size_t)r * KDIM + c * GBK + ch * 8);
            cp16(wb + r * GPAD + ch * 8, Wg + (size_t)r * KDIM + c * GBK + ch * 8);
        }
    };

    float acc[4][8][4];
    #pragma unroll
    for (int mt = 0; mt < 4; mt++)
        #pragma unroll
        for (int nt = 0; nt < 8; nt++)
            #pragma unroll
            for (int i = 0; i < 4; i++) acc[mt][nt][i] = 0.f;

    issue(0, 0); cp_commit();
    issue(1, 1); cp_commit();

    for (int c = 0; c < GKCH; c++) {
        if (c == GKCH - 1) cp_wait<0>(); else cp_wait<1>();
        __syncthreads();
        if (c + 2 < GKCH) { issue(c + 2, (c + 2) % 3); cp_commit(); }

        const int s = c % 3;
        const __half* Ab = As + s * GSTR + (warp_m * 64) * GPAD;
        const __half* Wb = Ws + s * GSTR + (warp_n * 64) * GPAD;
        #pragma unroll
        for (int kk = 0; kk < 2; kk++) {
            const int k0 = kk * 16;
            uint32_t af[4][4], bb[4][4];
            #pragma unroll
            for (int mt = 0; mt < 4; mt++)
                ldmx4(af[mt], Ab + (mt*16 + arow) * GPAD + k0 + acol);
            #pragma unroll
            for (int np = 0; np < 4; np++)
                ldmx4(bb[np], Wb + (np*16 + brow) * GPAD + k0 + bcol);
            #pragma unroll
            for (int mt = 0; mt < 4; mt++)
                #pragma unroll
                for (int np = 0; np < 4; np++) {
                    mma_f16(acc[mt][2*np    ], af[mt], &bb[np][0]);
                    mma_f16(acc[mt][2*np + 1], af[mt], &bb[np][2]);
                }
        }
    }

    #pragma unroll
    for (int nt = 0; nt < 8; nt++) {
        const int col = bm + warp_n * 64 + nt * 8 + t4 * 2;
        const float2 bv = *(const float2*)&bsel[col];
        #pragma unroll
        for (int mt = 0; mt < 4; mt++) {
            const int row = bn + warp_m * 64 + mt * 16 + gr;
            const int h = col / DHEAD, d = col % DHEAD;
            const int bb0 = row / SEQ, s0 = row % SEQ;
            const int bb1 = (row + 8) / SEQ, s1 = (row + 8) % SEQ;
            *(uint32_t*)&Hout[(((size_t)(bb0*NHEAD + h)*SEQ + s0)*DHEAD) + d] =
                packh2(acc[mt][nt][0] + bv.x, acc[mt][nt][1] + bv.y);
            *(uint32_t*)&Hout[(((size_t)(bb1*NHEAD + h)*SEQ + s1)*DHEAD) + d] =
                packh2(acc[mt][nt][2] + bv.x, acc[mt][nt][3] + bv.y);
        }
    }
}

// ---------------------------------------------------------------------------
// Output projection GEMM: CTA tile 64x128, 128 thr (4 warps 2x2, warp 32x64),
// 3-stage cp.async, 4 CTAs/SM. grid (8,128) = 1024 CTAs over 592 slots
// = 2 waves at 86.5% util (vs 58% for the 128x128 tile's 512 CTAs).
// ---------------------------------------------------------------------------
#define OSTR_A (64 * GPAD)
#define OSTR   (192 * GPAD)              // halves per stage (A 64 rows + B 128)
#define OUT_SMEM (3 * OSTR * 2)          // 46080 B

__global__ __launch_bounds__(128, 4)
void gemm_out(const __half* __restrict__ A, const __half* __restrict__ W,
              const float* __restrict__ bias, float* __restrict__ Y)
{
    extern __shared__ __align__(16) char dsm[];
    __half* Sm = (__half*)dsm;            // [3][ A:64xGPAD | B:128xGPAD ]

    const int tid    = threadIdx.x;
    const int lane   = tid & 31;
    const int wid    = tid >> 5;         // 0..3
    const int warp_m = wid & 1;          // 32-row group
    const int warp_n = wid >> 1;         // 64-col group
    const int gr     = lane >> 2;
    const int t4     = lane & 3;

    const int lr   = lane & 7;
    const int arow = ((lane >> 3) & 1) * 8 + lr;
    const int acol = ((lane >> 4) & 1) * 8;
    const int brow = ((lane >> 4) & 1) * 8 + lr;
    const int bcol = ((lane >> 3) & 1) * 8;

    const int bn = blockIdx.y * 64;
    const int bm = blockIdx.x * 128;

    const __half* Ag = A + (size_t)bn * KDIM;
    const __half* Wg = W + (size_t)bm * KDIM;

    // A: 64 rows x 4 chunks = 256; B: 128 rows x 4 chunks = 512; total 768; 6/thread
    auto issue = [&](int c, int s) {
        __half* base = Sm + s * OSTR;
        #pragma unroll
        for (int i = 0; i < 6; i++) {
            const int idx = tid + i * 128;        // 0..767
            if (idx < 256) {
                const int r = idx >> 2, ch = idx & 3;
                cp16(base + r * GPAD + ch * 8, Ag + (size_t)r * KDIM + c * GBK + ch * 8);
            } else {
                const int j = idx - 256;
                const int r = j >> 2, ch = j & 3;
                cp16(base + OSTR_A + r * GPAD + ch * 8, Wg + (size_t)r * KDIM + c * GBK + ch * 8);
            }
        }
    };

    float acc[2][8][4];
    #pragma unroll
    for (int mt = 0; mt < 2; mt++)
        #pragma unroll
        for (int nt = 0; nt < 8; nt++)
            #pragma unroll
            for (int i = 0; i < 4; i++) acc[mt][nt][i] = 0.f;

    issue(0, 0); cp_commit();
    issue(1, 1); cp_commit();

    for (int c = 0; c < GKCH; c++) {
        if (c == GKCH - 1) cp_wait<0>(); else cp_wait<1>();
        __syncthreads();
        if (c + 2 < GKCH) { issue(c + 2, (c + 2) % 3); cp_commit(); }

        const int s = c % 3;
        const __half* Ab = Sm + s * OSTR + (warp_m * 32) * GPAD;
        const __half* Wb = Sm + s * OSTR + OSTR_A + (warp_n * 64) * GPAD;
        #pragma unroll
        for (int kk = 0; kk < 2; kk++) {
            const int k0 = kk * 16;
            uint32_t af[2][4], bb[4][4];
            #pragma unroll
            for (int mt = 0; mt < 2; mt++)
                ldmx4(af[mt], Ab + (mt*16 + arow) * GPAD + k0 + acol);
            #pragma unroll
            for (int np = 0; np < 4; np++)
                ldmx4(bb[np], Wb + (np*16 + brow) * GPAD + k0 + bcol);
            #pragma unroll
            for (int mt = 0; mt < 2; mt++)
                #pragma unroll
                for (int np = 0; np < 4; np++) {
                    mma_f16(acc[mt][2*np    ], af[mt], &bb[np][0]);
                    mma_f16(acc[mt][2*np + 1], af[mt], &bb[np][2]);
                }
        }
    }

    #pragma unroll
    for (int nt = 0; nt < 8; nt++) {
        const int col = bm + warp_n * 64 + nt * 8 + t4 * 2;
        const float2 bv = *(const float2*)&bias[col];
        #pragma unroll
        for (int mt = 0; mt < 2; mt++) {
            const int row = bn + warp_m * 32 + mt * 16 + gr;
            *(float2*)&Y[(size_t)row * D_MODEL + col] =
                make_float2(acc[mt][nt][0] + bv.x, acc[mt][nt][1] + bv.y);
            *(float2*)&Y[(size_t)(row + 8) * D_MODEL + col] =
                make_float2(acc[mt][nt][2] + bv.x, acc[mt][nt][3] + bv.y);
        }
    }
}

// ---------------------------------------------------------------------------
// Causal flash attention, fp16 mma + cp.async triple-buffered K/V staging.
// (unchanged)
// ---------------------------------------------------------------------------
#define ABR   128
#define ABC   64
#define APAD  72
#define KVSTR (ABC * APAD)               // halves per K (or V) stage
#define ATTN_SMEM ((3 * 2 * KVSTR + ABR * APAD) * 2)   // 73728 B
#define QSCALE (0.125f * 1.44269504088896340736f)

__global__ __launch_bounds__(256, 2)
void attn_h()
{
    extern __shared__ __align__(16) char dsm[];
    __half* Ksm = (__half*)dsm;               // [3][64][APAD]
    __half* Vsm = Ksm + 3 * KVSTR;            // [3][64][APAD]
    __half* Qs  = Vsm + 3 * KVSTR;            // [128][APAD]

    const int bh = blockIdx.y;
    const int qb = (int)gridDim.x - 1 - (int)blockIdx.x;   // heavy blocks first
    const int q0 = qb * ABR;

    const __half* Qg = g_qh + (size_t)bh * SEQ * DHEAD;
    const __half* Kg = g_kh + (size_t)bh * SEQ * DHEAD;
    const __half* Vg = g_vh + (size_t)bh * SEQ * DHEAD;

    const int tid  = threadIdx.x;
    const int lane = tid & 31;
    const int wid  = tid >> 5;
    const int gr   = lane >> 2;
    const int t4   = lane & 3;
    const int r0   = wid * 16;

    const int lr   = lane & 7;
    const int arow = ((lane >> 3) & 1) * 8 + lr;
    const int acol = ((lane >> 4) & 1) * 8;
    const int brow = ((lane >> 4) & 1) * 8 + lr;   // K B-frags
    const int bcol = ((lane >> 3) & 1) * 8;
    const int trow = ((lane >> 3) & 1) * 8 + lr;   // V B-frags (trans)
    const int tcol = ((lane >> 4) & 1) * 8;

    const int jmax = 2 * qb + 1;

    auto issue = [&](int j, int s) {
        #pragma unroll
        for (int i = 0; i < 2; i++) {
            const int idx = tid + i * 256;     // 0..511
            const int r = idx >> 3, ch = idx & 7;
            const size_t goff = (size_t)(j * ABC + r) * DHEAD + ch * 8;
            cp16(Ksm + s * KVSTR + r * APAD + ch * 8, Kg + goff);
            cp16(Vsm + s * KVSTR + r * APAD + ch * 8, Vg + goff);
        }
    };

    issue(0, 0); cp_commit();
    issue(1, 1); cp_commit();

    // ---- stage Q (x log2e/8) ----
    {
        const int r = tid >> 1, h = (tid & 1) * 32;
        const __half* src = Qg + (size_t)(q0 + r) * DHEAD + h;
        #pragma unroll
        for (int i = 0; i < 4; i++) {
            uint4 u = *(const uint4*)(src + i * 8);
            const __half2* hp = (const __half2*)&u;
            uint4 o;
            uint32_t* op = (uint32_t*)&o;
            #pragma unroll
            for (int k = 0; k < 4; k++) {
                float2 f = __half22float2(hp[k]);
                op[k] = packh2(f.x * QSCALE, f.y * QSCALE);
            }
            *(uint4*)&Qs[r * APAD + h + i * 8] = o;
        }
    }
    __syncthreads();

    uint32_t Qf[4][4];
    #pragma unroll
    for (int kk = 0; kk < 4; kk++)
        ldmx4(Qf[kk], Qs + (r0 + arow) * APAD + kk * 16 + acol);

    float m0 = -1e30f, m1 = -1e30f, l0 = 0.f, l1 = 0.f;
    float oacc[8][4];
    #pragma unroll
    for (int nt = 0; nt < 8; nt++)
        #pragma unroll
        for (int i = 0; i < 4; i++) oacc[nt][i] = 0.f;

    const int rowa = q0 + r0 + gr;
    const int rowb = rowa + 8;

    for (int j = 0; j <= jmax; j++) {
        if (j + 1 <= jmax) cp_wait<1>(); else cp_wait<0>();
        __syncthreads();
        if (j + 2 <= jmax) { issue(j + 2, (j + 2) % 3); cp_commit(); }

        const int s = j % 3;
        const __half* Ks = Ksm + s * KVSTR;
        const __half* Vs = Vsm + s * KVSTR;
        const int kv0 = j * ABC;

        // ---- S = Qs * K^T (scale + log2e folded into Q) ----
        float sacc[8][4];
        #pragma unroll
        for (int nt = 0; nt < 8; nt++)
            #pragma unroll
            for (int i = 0; i < 4; i++) sacc[nt][i] = 0.f;

        #pragma unroll
        for (int kk = 0; kk < 4; kk++) {
            #pragma unroll
            for (int np = 0; np < 4; np++) {
                uint32_t bb[4];
                ldmx4(bb, Ks + (np*16 + brow) * APAD + kk*16 + bcol);
                mma_f16(sacc[2*np    ], Qf[kk], &bb[0]);
                mma_f16(sacc[2*np + 1], Qf[kk], &bb[2]);
            }
        }

        // ---- causal mask (diag tiles only) ----
        if (kv0 + ABC - 1 > q0) {
            #pragma unroll
            for (int nt = 0; nt < 8; nt++) {
                const int col0 = kv0 + nt*8 + 2*t4;
                if (col0     > rowa) sacc[nt][0] = -1e30f;
                if (col0 + 1 > rowa) sacc[nt][1] = -1e30f;
                if (col0     > rowb) sacc[nt][2] = -1e30f;
                if (col0 + 1 > rowb) sacc[nt][3] = -1e30f;
            }
        }

        // ---- online softmax, log2 domain (rows gr, gr+8) ----
        float mx0 = -1e30f, mx1 = -1e30f;
        #pragma unroll
        for (int nt = 0; nt < 8; nt++) {
            mx0 = fmaxf(mx0, fmaxf(sacc[nt][0], sacc[nt][1]));
            mx1 = fmaxf(mx1, fmaxf(sacc[nt][2], sacc[nt][3]));
        }
        mx0 = fmaxf(mx0, __shfl_xor_sync(0xffffffffu, mx0, 1));
        mx0 = fmaxf(mx0, __shfl_xor_sync(0xffffffffu, mx0, 2));
        mx1 = fmaxf(mx1, __shfl_xor_sync(0xffffffffu, mx1, 1));
        mx1 = fmaxf(mx1, __shfl_xor_sync(0xffffffffu, mx1, 2));

        const float mn0 = fmaxf(m0, mx0), mn1 = fmaxf(m1, mx1);
        const float a0 = ex2f(m0 - mn0), a1 = ex2f(m1 - mn1);
        float s0 = 0.f, s1 = 0.f;
        #pragma unroll
        for (int nt = 0; nt < 8; nt++) {
            sacc[nt][0] = ex2f(sacc[nt][0] - mn0);
            sacc[nt][1] = ex2f(sacc[nt][1] - mn0);
            sacc[nt][2] = ex2f(sacc[nt][2] - mn1);
            sacc[nt][3] = ex2f(sacc[nt][3] - mn1);
            s0 += sacc[nt][0] + sacc[nt][1];
            s1 += sacc[nt][2] + sacc[nt][3];
        }
        s0 += __shfl_xor_sync(0xffffffffu, s0, 1);
        s0 += __shfl_xor_sync(0xffffffffu, s0, 2);
        s1 += __shfl_xor_sync(0xffffffffu, s1, 1);
        s1 += __shfl_xor_sync(0xffffffffu, s1, 2);
        l0 = l0 * a0 + s0;  m0 = mn0;
        l1 = l1 * a1 + s1;  m1 = mn1;
        #pragma unroll
        for (int nt = 0; nt < 8; nt++) {
            oacc[nt][0] *= a0; oacc[nt][1] *= a0;
            oacc[nt][2] *= a1; oacc[nt][3] *= a1;
        }

        // ---- O += P * V ; P packed from regs (C-frag == A-frag) ----
        #pragma unroll
        for (int kk = 0; kk < 4; kk++) {
            uint32_t pf[4];
            pf[0] = packh2(sacc[2*kk    ][0], sacc[2*kk    ][1]);
            pf[1] = packh2(sacc[2*kk    ][2], sacc[2*kk    ][3]);
            pf[2] = packh2(sacc[2*kk + 1][0], sacc[2*kk + 1][1]);
            pf[3] = packh2(sacc[2*kk + 1][2], sacc[2*kk + 1][3]);
            #pragma unroll
            for (int np = 0; np < 4; np++) {
                uint32_t bt[4];
                ldmx4t(bt, Vs + (kk*16 + trow) * APAD + np*16 + tcol);
                mma_f16(oacc[2*np    ], pf, &bt[0]);
                mma_f16(oacc[2*np + 1], pf, &bt[2]);
            }
        }
    }

    // ---- normalize + write half [B,S,D] ----
    const float inv0 = 1.f / l0, inv1 = 1.f / l1;
    const int b = bh >> 4, h = bh & 15;
    #pragma unroll
    for (int nt = 0; nt < 8; nt++) {
        const int col = h * DHEAD + nt*8 + 2*t4;
        *(uint32_t*)&g_ah[((size_t)(b*SEQ + rowa)) * D_MODEL + col] =
            packh2(oacc[nt][0] * inv0, oacc[nt][1] * inv0);
        *(uint32_t*)&g_ah[((size_t)(b*SEQ + rowb)) * D_MODEL + col] =
            packh2(oacc[nt][2] * inv1, oacc[nt][3] * inv1);
    }
}

// ---------------------------------------------------------------------------
extern "C" void kernel_launch(void* const* d_in, const int* in_sizes, int n_in,
                              void* d_out, int out_size)
{
    const float* x  = (const float*)d_in[0];
    const float* Wq = (const float*)d_in[1];
    const float* bq = (const float*)d_in[2];
    const float* Wk = (const float*)d_in[3];
    const float* bk = (const float*)d_in[4];
    const float* Wv = (const float*)d_in[5];
    const float* bv = (const float*)d_in[6];
    const float* Wo = (const float*)d_in[7];
    const float* bo = (const float*)d_in[8];

    __half *xh, *wqh, *wkh, *wvh, *woh, *ah;
    cudaGetSymbolAddress((void**)&xh,  g_xh);
    cudaGetSymbolAddress((void**)&wqh, g_wqh);
    cudaGetSymbolAddress((void**)&wkh, g_wkh);
    cudaGetSymbolAddress((void**)&wvh, g_wvh);
    cudaGetSymbolAddress((void**)&woh, g_woh);
    cudaGetSymbolAddress((void**)&ah,  g_ah);

    // fused fp32 -> fp16 pre-pass (1 launch)
    cvt_all<<<NCVT/256, 256>>>(x, Wq, Wk, Wv, Wo);

    cudaFuncSetAttribute(gemm_qkv,
                         cudaFuncAttributeMaxDynamicSharedMemorySize, GEMM_SMEM);
    cudaFuncSetAttribute(gemm_out,
                         cudaFuncAttributeMaxDynamicSharedMemorySize, OUT_SMEM);
    cudaFuncSetAttribute(attn_h,
                         cudaFuncAttributeMaxDynamicSharedMemorySize, ATTN_SMEM);

    // fused QKV projection (1 launch, z selects head)
    gemm_qkv<<<dim3(D_MODEL/128, NTOK/128, 3), 128, GEMM_SMEM>>>(
        xh, wqh, bq, wkh, bk, wvh, bv);

    attn_h<<<dim3(SEQ/ABR, BATCH*NHEAD), 256, ATTN_SMEM>>>();

    // output projection: 64x128 tiles -> 1024 CTAs, 4 CTAs/SM, 86.5% wave util
    gemm_out<<<dim3(D_MODEL/128, NTOK/64), 128, OUT_SMEM>>>(
        ah, woh, bo, (float*)d_out);
}

// round 13
// speedup vs baseline: 16.6704x; 1.0015x over previous
#include <cuda_runtime.h>
#include <cuda_fp16.h>
#include <math.h>
#include <cstdint>

#define D_MODEL 1024
#define NHEAD   16
#define DHEAD   64
#define BATCH   4
#define SEQ     2048
#define NTOK    (BATCH*SEQ)   // 8192
#define KDIM    1024

// ---------------------------------------------------------------------------
// fp16 scratch (allocation-free rule: __device__ globals)
// ---------------------------------------------------------------------------
__device__ __half g_xh[(size_t)NTOK*KDIM];
__device__ __half g_wqh[(size_t)KDIM*D_MODEL];
__device__ __half g_wkh[(size_t)KDIM*D_MODEL];
__device__ __half g_wvh[(size_t)KDIM*D_MODEL];
__device__ __half g_woh[(size_t)KDIM*D_MODEL];
__device__ __half g_qh[(size_t)BATCH*NHEAD*SEQ*DHEAD];   // [B,H,S,Dh]
__device__ __half g_kh[(size_t)BATCH*NHEAD*SEQ*DHEAD];
__device__ __half g_vh[(size_t)BATCH*NHEAD*SEQ*DHEAD];
__device__ __half g_ah[(size_t)NTOK*D_MODEL];            // [B,S,D]

// ---------------------------------------------------------------------------
// helpers
// ---------------------------------------------------------------------------
__device__ __forceinline__ uint32_t packh2(float a, float b) {
    __half2 h = __floats2half2_rn(a, b);
    return *reinterpret_cast<uint32_t*>(&h);
}
__device__ __forceinline__ float ex2f(float x) {
    float y;
    asm("ex2.approx.ftz.f32 %0, %1;" : "=f"(y) : "f"(x));
    return y;
}
__device__ __forceinline__ void mma_f16(float* c, const uint32_t* a, const uint32_t* b) {
    asm volatile(
        "mma.sync.aligned.m16n8k16.row.col.f32.f16.f16.f32 "
        "{%0,%1,%2,%3}, {%4,%5,%6,%7}, {%8,%9}, {%0,%1,%2,%3};"
        : "+f"(c[0]), "+f"(c[1]), "+f"(c[2]), "+f"(c[3])
        : "r"(a[0]), "r"(a[1]), "r"(a[2]), "r"(a[3]), "r"(b[0]), "r"(b[1]));
}
__device__ __forceinline__ void ldmx4(uint32_t* r, const void* p) {
    uint32_t a = (uint32_t)__cvta_generic_to_shared(p);
    asm volatile("ldmatrix.sync.aligned.m8n8.x4.shared.b16 {%0,%1,%2,%3}, [%4];"
                 : "=r"(r[0]), "=r"(r[1]), "=r"(r[2]), "=r"(r[3]) : "r"(a));
}
__device__ __forceinline__ void ldmx4t(uint32_t* r, const void* p) {
    uint32_t a = (uint32_t)__cvta_generic_to_shared(p);
    asm volatile("ldmatrix.sync.aligned.m8n8.x4.trans.shared.b16 {%0,%1,%2,%3}, [%4];"
                 : "=r"(r[0]), "=r"(r[1]), "=r"(r[2]), "=r"(r[3]) : "r"(a));
}
__device__ __forceinline__ void ldmx2t(uint32_t* r, const void* p) {
    uint32_t a = (uint32_t)__cvta_generic_to_shared(p);
    asm volatile("ldmatrix.sync.aligned.m8n8.x2.trans.shared.b16 {%0,%1}, [%2];"
                 : "=r"(r[0]), "=r"(r[1]) : "r"(a));
}
__device__ __forceinline__ void cp16(void* s, const void* g) {
    uint32_t a = (uint32_t)__cvta_generic_to_shared(s);
    asm volatile("cp.async.cg.shared.global [%0], [%1], 16;" :: "r"(a), "l"(g) : "memory");
}
__device__ __forceinline__ void cp_commit() {
    asm volatile("cp.async.commit_group;" ::: "memory");
}
template<int N>
__device__ __forceinline__ void cp_wait() {
    asm volatile("cp.async.wait_group %0;" :: "n"(N) : "memory");
}

// ---------------------------------------------------------------------------
// fused fp32 -> fp16 conversion
// ---------------------------------------------------------------------------
#define NX8 (NTOK * KDIM / 8)       // 1048576 = 2^20
#define NW8 (KDIM * D_MODEL / 8)    // 131072  = 2^17
#define NCVT (NX8 + 4 * NW8)        // 1572864

__global__ __launch_bounds__(256)
void cvt_all(const float* __restrict__ x,
             const float* __restrict__ w0, const float* __restrict__ w1,
             const float* __restrict__ w2, const float* __restrict__ w3)
{
    const int i = blockIdx.x * 256 + threadIdx.x;
    const float* src;
    __half* dst;
    int off;
    if (i < NX8) {
        src = x; dst = g_xh; off = i;
    } else {
        const int t = i - NX8;
        const int w = t >> 17;            // NW8 = 2^17
        off = t & (NW8 - 1);
        switch (w) {
            case 0:  src = w0; dst = g_wqh; break;
            case 1:  src = w1; dst = g_wkh; break;
            case 2:  src = w2; dst = g_wvh; break;
            default: src = w3; dst = g_woh; break;
        }
    }
    float4 a = ((const float4*)src)[2*off];
    float4 b = ((const float4*)src)[2*off + 1];
    uint4 o;
    o.x = packh2(a.x, a.y);  o.y = packh2(a.z, a.w);
    o.z = packh2(b.x, b.y);  o.w = packh2(b.z, b.w);
    ((uint4*)dst)[off] = o;
}

// ---------------------------------------------------------------------------
// QKV fp16 GEMM (NT), cp.async 3-stage, CTA 128x128, 128 thr, warp 64x64.
// ---------------------------------------------------------------------------
#define GBK   32
#define GKCH  (KDIM / GBK)      // 32
#define GPAD  40                // halves per smem row
#define GSTR  (128 * GPAD)      // halves per stage per operand
#define GEMM_SMEM (3 * 2 * GSTR * 2)   // 61440 B

__global__ __launch_bounds__(128, 3)
void gemm_qkv(const __half* __restrict__ A,
              const __half* __restrict__ W0, const float* __restrict__ b0,
              const __half* __restrict__ W1, const float* __restrict__ b1,
              const __half* __restrict__ W2, const float* __restrict__ b2)
{
    extern __shared__ __align__(16) char dsm[];
    __half* As = (__half*)dsm;            // [3][128][GPAD]
    __half* Ws = As + 3 * GSTR;           // [3][128][GPAD]

    const __half* Wsel = W0;
    const float*  bsel = b0;
    __half* Hout = g_qh;
    if (blockIdx.z == 1)      { Wsel = W1; bsel = b1; Hout = g_kh; }
    else if (blockIdx.z == 2) { Wsel = W2; bsel = b2; Hout = g_vh; }

    const int tid    = threadIdx.x;
    const int lane   = tid & 31;
    const int wid    = tid >> 5;
    const int warp_m = wid & 1;
    const int warp_n = wid >> 1;
    const int gr     = lane >> 2;
    const int t4     = lane & 3;

    const int lr   = lane & 7;
    const int arow = ((lane >> 3) & 1) * 8 + lr;
    const int acol = ((lane >> 4) & 1) * 8;
    const int brow = ((lane >> 4) & 1) * 8 + lr;
    const int bcol = ((lane >> 3) & 1) * 8;

    const int bn = blockIdx.y * 128;
    const int bm = blockIdx.x * 128;

    const __half* Ag = A + (size_t)bn * KDIM;
    const __half* Wg = Wsel + (size_t)bm * KDIM;

    auto issue = [&](int c, int s) {
        __half* ab = As + s * GSTR;
        __half* wb = Ws + s * GSTR;
        #pragma unroll
        for (int i = 0; i < 4; i++) {
            const int idx = tid + i * 128;        // 0..511
            const int r = idx >> 2, ch = idx & 3;
            cp16(ab + r * GPAD + ch * 8, Ag + (size_t)r * KDIM + c * GBK + ch * 8);
            cp16(wb + r * GPAD + ch * 8, Wg + (size_t)r * KDIM + c * GBK + ch * 8);
        }
    };

    float acc[4][8][4];
    #pragma unroll
    for (int mt = 0; mt < 4; mt++)
        #pragma unroll
        for (int nt = 0; nt < 8; nt++)
            #pragma unroll
            for (int i = 0; i < 4; i++) acc[mt][nt][i] = 0.f;

    issue(0, 0); cp_commit();
    issue(1, 1); cp_commit();

    for (int c = 0; c < GKCH; c++) {
        if (c == GKCH - 1) cp_wait<0>(); else cp_wait<1>();
        __syncthreads();
        if (c + 2 < GKCH) { issue(c + 2, (c + 2) % 3); cp_commit(); }

        const int s = c % 3;
        const __half* Ab = As + s * GSTR + (warp_m * 64) * GPAD;
        const __half* Wb = Ws + s * GSTR + (warp_n * 64) * GPAD;
        #pragma unroll
        for (int kk = 0; kk < 2; kk++) {
            const int k0 = kk * 16;
            uint32_t af[4][4], bb[4][4];
            #pragma unroll
            for (int mt = 0; mt < 4; mt++)
                ldmx4(af[mt], Ab + (mt*16 + arow) * GPAD + k0 + acol);
            #pragma unroll
            for (int np = 0; np < 4; np++)
                ldmx4(bb[np], Wb + (np*16 + brow) * GPAD + k0 + bcol);
            #pragma unroll
            for (int mt = 0; mt < 4; mt++)
                #pragma unroll
                for (int np = 0; np < 4; np++) {
                    mma_f16(acc[mt][2*np    ], af[mt], &bb[np][0]);
                    mma_f16(acc[mt][2*np + 1], af[mt], &bb[np][2]);
                }
        }
    }

    #pragma unroll
    for (int nt = 0; nt < 8; nt++) {
        const int col = bm + warp_n * 64 + nt * 8 + t4 * 2;
        const float2 bv = *(const float2*)&bsel[col];
        #pragma unroll
        for (int mt = 0; mt < 4; mt++) {
            const int row = bn + warp_m * 64 + mt * 16 + gr;
            const int h = col / DHEAD, d = col % DHEAD;
            const int bb0 = row / SEQ, s0 = row % SEQ;
            const int bb1 = (row + 8) / SEQ, s1 = (row + 8) % SEQ;
            *(uint32_t*)&Hout[(((size_t)(bb0*NHEAD + h)*SEQ + s0)*DHEAD) + d] =
                packh2(acc[mt][nt][0] + bv.x, acc[mt][nt][1] + bv.y);
            *(uint32_t*)&Hout[(((size_t)(bb1*NHEAD + h)*SEQ + s1)*DHEAD) + d] =
                packh2(acc[mt][nt][2] + bv.x, acc[mt][nt][3] + bv.y);
        }
    }
}

// ---------------------------------------------------------------------------
// Output projection GEMM: CTA 64x128, 128 thr, 3-stage, 4 CTAs/SM.
// ---------------------------------------------------------------------------
#define OSTR_A (64 * GPAD)
#define OSTR   (192 * GPAD)
#define OUT_SMEM (3 * OSTR * 2)          // 46080 B

__global__ __launch_bounds__(128, 4)
void gemm_out(const __half* __restrict__ A, const __half* __restrict__ W,
              const float* __restrict__ bias, float* __restrict__ Y)
{
    extern __shared__ __align__(16) char dsm[];
    __half* Sm = (__half*)dsm;

    const int tid    = threadIdx.x;
    const int lane   = tid & 31;
    const int wid    = tid >> 5;
    const int warp_m = wid & 1;
    const int warp_n = wid >> 1;
    const int gr     = lane >> 2;
    const int t4     = lane & 3;

    const int lr   = lane & 7;
    const int arow = ((lane >> 3) & 1) * 8 + lr;
    const int acol = ((lane >> 4) & 1) * 8;
    const int brow = ((lane >> 4) & 1) * 8 + lr;
    const int bcol = ((lane >> 3) & 1) * 8;

    const int bn = blockIdx.y * 64;
    const int bm = blockIdx.x * 128;

    const __half* Ag = A + (size_t)bn * KDIM;
    const __half* Wg = W + (size_t)bm * KDIM;

    auto issue = [&](int c, int s) {
        __half* base = Sm + s * OSTR;
        #pragma unroll
        for (int i = 0; i < 6; i++) {
            const int idx = tid + i * 128;        // 0..767
            if (idx < 256) {
                const int r = idx >> 2, ch = idx & 3;
                cp16(base + r * GPAD + ch * 8, Ag + (size_t)r * KDIM + c * GBK + ch * 8);
            } else {
                const int j = idx - 256;
                const int r = j >> 2, ch = j & 3;
                cp16(base + OSTR_A + r * GPAD + ch * 8, Wg + (size_t)r * KDIM + c * GBK + ch * 8);
            }
        }
    };

    float acc[2][8][4];
    #pragma unroll
    for (int mt = 0; mt < 2; mt++)
        #pragma unroll
        for (int nt = 0; nt < 8; nt++)
            #pragma unroll
            for (int i = 0; i < 4; i++) acc[mt][nt][i] = 0.f;

    issue(0, 0); cp_commit();
    issue(1, 1); cp_commit();

    for (int c = 0; c < GKCH; c++) {
        if (c == GKCH - 1) cp_wait<0>(); else cp_wait<1>();
        __syncthreads();
        if (c + 2 < GKCH) { issue(c + 2, (c + 2) % 3); cp_commit(); }

        const int s = c % 3;
        const __half* Ab = Sm + s * OSTR + (warp_m * 32) * GPAD;
        const __half* Wb = Sm + s * OSTR + OSTR_A + (warp_n * 64) * GPAD;
        #pragma unroll
        for (int kk = 0; kk < 2; kk++) {
            const int k0 = kk * 16;
            uint32_t af[2][4], bb[4][4];
            #pragma unroll
            for (int mt = 0; mt < 2; mt++)
                ldmx4(af[mt], Ab + (mt*16 + arow) * GPAD + k0 + acol);
            #pragma unroll
            for (int np = 0; np < 4; np++)
                ldmx4(bb[np], Wb + (np*16 + brow) * GPAD + k0 + bcol);
            #pragma unroll
            for (int mt = 0; mt < 2; mt++)
                #pragma unroll
                for (int np = 0; np < 4; np++) {
                    mma_f16(acc[mt][2*np    ], af[mt], &bb[np][0]);
                    mma_f16(acc[mt][2*np + 1], af[mt], &bb[np][2]);
                }
        }
    }

    #pragma unroll
    for (int nt = 0; nt < 8; nt++) {
        const int col = bm + warp_n * 64 + nt * 8 + t4 * 2;
        const float2 bv = *(const float2*)&bias[col];
        #pragma unroll
        for (int mt = 0; mt < 2; mt++) {
            const int row = bn + warp_m * 32 + mt * 16 + gr;
            *(float2*)&Y[(size_t)row * D_MODEL + col] =
                make_float2(acc[mt][nt][0] + bv.x, acc[mt][nt][1] + bv.y);
            *(float2*)&Y[(size_t)(row + 8) * D_MODEL + col] =
                make_float2(acc[mt][nt][2] + bv.x, acc[mt][nt][3] + bv.y);
        }
    }
}

// ---------------------------------------------------------------------------
// Causal flash attention, fp16 mma + cp.async triple-buffered K/V staging.
// NEW: l computed by the tensor core via a ones-column appended to V
// (smem pad col 64 = 1.0, cols 65-71 = 0; cp.async only writes cols 0-63).
// Removes per-tile sum adds + sum shuffles + final l reduction.
// NEW: warp-vote skip of the oacc rescale when no row max changed.
// ---------------------------------------------------------------------------
#define ABR   128
#define ABC   64
#define APAD  72
#define KVSTR (ABC * APAD)               // halves per K (or V) stage
#define ATTN_SMEM ((3 * 2 * KVSTR + ABR * APAD) * 2)   // 73728 B
#define QSCALE (0.125f * 1.44269504088896340736f)

__global__ __launch_bounds__(256, 2)
void attn_h()
{
    extern __shared__ __align__(16) char dsm[];
    __half* Ksm = (__half*)dsm;               // [3][64][APAD]
    __half* Vsm = Ksm + 3 * KVSTR;            // [3][64][APAD]
    __half* Qs  = Vsm + 3 * KVSTR;            // [128][APAD]

    const int bh = blockIdx.y;
    const int qb = (int)gridDim.x - 1 - (int)blockIdx.x;   // heavy blocks first
    const int q0 = qb * ABR;

    const __half* Qg = g_qh + (size_t)bh * SEQ * DHEAD;
    const __half* Kg = g_kh + (size_t)bh * SEQ * DHEAD;
    const __half* Vg = g_vh + (size_t)bh * SEQ * DHEAD;

    const int tid  = threadIdx.x;
    const int lane = tid & 31;
    const int wid  = tid >> 5;
    const int gr   = lane >> 2;
    const int t4   = lane & 3;
    const int r0   = wid * 16;

    const int lr   = lane & 7;
    const int arow = ((lane >> 3) & 1) * 8 + lr;
    const int acol = ((lane >> 4) & 1) * 8;
    const int brow = ((lane >> 4) & 1) * 8 + lr;   // K B-frags
    const int bcol = ((lane >> 3) & 1) * 8;
    const int trow = ((lane >> 3) & 1) * 8 + lr;   // V B-frags (trans)
    const int tcol = ((lane >> 4) & 1) * 8;
    const int vrow2 = lane & 15;                   // x2 trans row (ones column)

    const int jmax = 2 * qb + 1;

    auto issue = [&](int j, int s) {
        #pragma unroll
        for (int i = 0; i < 2; i++) {
            const int idx = tid + i * 256;     // 0..511
            const int r = idx >> 3, ch = idx & 7;
            const size_t goff = (size_t)(j * ABC + r) * DHEAD + ch * 8;
            cp16(Ksm + s * KVSTR + r * APAD + ch * 8, Kg + goff);
            cp16(Vsm + s * KVSTR + r * APAD + ch * 8, Vg + goff);
        }
    };

    issue(0, 0); cp_commit();
    issue(1, 1); cp_commit();

    // ---- init V pad columns (col 64 = 1.0, 65-71 = 0) for all 3 stages ----
    // cp.async never writes cols >= 64, so this persists across tiles.
    if (tid < 192) {
        const int st = tid / 64, r = tid % 64;
        uint4 ones = make_uint4(0x00003C00u, 0u, 0u, 0u);   // {1.0h,0,...,0}
        *(uint4*)&Vsm[st * KVSTR + r * APAD + 64] = ones;
    }

    // ---- stage Q (x log2e/8) ----
    {
        const int r = tid >> 1, h = (tid & 1) * 32;
        const __half* src = Qg + (size_t)(q0 + r) * DHEAD + h;
        #pragma unroll
        for (int i = 0; i < 4; i++) {
            uint4 u = *(const uint4*)(src + i * 8);
            const __half2* hp = (const __half2*)&u;
            uint4 o;
            uint32_t* op = (uint32_t*)&o;
            #pragma unroll
            for (int k = 0; k < 4; k++) {
                float2 f = __half22float2(hp[k]);
                op[k] = packh2(f.x * QSCALE, f.y * QSCALE);
            }
            *(uint4*)&Qs[r * APAD + h + i * 8] = o;
        }
    }
    __syncthreads();

    uint32_t Qf[4][4];
    #pragma unroll
    for (int kk = 0; kk < 4; kk++)
        ldmx4(Qf[kk], Qs + (r0 + arow) * APAD + kk * 16 + acol);

    float m0 = -1e30f, m1 = -1e30f;
    float oacc[9][4];                 // [8] = l column (P . ones)
    #pragma unroll
    for (int nt = 0; nt < 9; nt++)
        #pragma unroll
        for (int i = 0; i < 4; i++) oacc[nt][i] = 0.f;

    const int rowa = q0 + r0 + gr;
    const int rowb = rowa + 8;

    for (int j = 0; j <= jmax; j++) {
        if (j + 1 <= jmax) cp_wait<1>(); else cp_wait<0>();
        __syncthreads();
        if (j + 2 <= jmax) { issue(j + 2, (j + 2) % 3); cp_commit(); }

        const int s = j % 3;
        const __half* Ks = Ksm + s * KVSTR;
        const __half* Vs = Vsm + s * KVSTR;
        const int kv0 = j * ABC;

        // ---- S = Qs * K^T (scale + log2e folded into Q) ----
        float sacc[8][4];
        #pragma unroll
        for (int nt = 0; nt < 8; nt++)
            #pragma unroll
            for (int i = 0; i < 4; i++) sacc[nt][i] = 0.f;

        #pragma unroll
        for (int kk = 0; kk < 4; kk++) {
            #pragma unroll
            for (int np = 0; np < 4; np++) {
                uint32_t bb[4];
                ldmx4(bb, Ks + (np*16 + brow) * APAD + kk*16 + bcol);
                mma_f16(sacc[2*np    ], Qf[kk], &bb[0]);
                mma_f16(sacc[2*np + 1], Qf[kk], &bb[2]);
            }
        }

        // ---- causal mask (diag tiles only) ----
        if (kv0 + ABC - 1 > q0) {
            #pragma unroll
            for (int nt = 0; nt < 8; nt++) {
                const int col0 = kv0 + nt*8 + 2*t4;
                if (col0     > rowa) sacc[nt][0] = -1e30f;
                if (col0 + 1 > rowa) sacc[nt][1] = -1e30f;
                if (col0     > rowb) sacc[nt][2] = -1e30f;
                if (col0 + 1 > rowb) sacc[nt][3] = -1e30f;
            }
        }

        // ---- online softmax, log2 domain (rows gr, gr+8) ----
        float mx0 = -1e30f, mx1 = -1e30f;
        #pragma unroll
        for (int nt = 0; nt < 8; nt++) {
            mx0 = fmaxf(mx0, fmaxf(sacc[nt][0], sacc[nt][1]));
            mx1 = fmaxf(mx1, fmaxf(sacc[nt][2], sacc[nt][3]));
        }
        mx0 = fmaxf(mx0, __shfl_xor_sync(0xffffffffu, mx0, 1));
        mx0 = fmaxf(mx0, __shfl_xor_sync(0xffffffffu, mx0, 2));
        mx1 = fmaxf(mx1, __shfl_xor_sync(0xffffffffu, mx1, 1));
        mx1 = fmaxf(mx1, __shfl_xor_sync(0xffffffffu, mx1, 2));

        const float mn0 = fmaxf(m0, mx0), mn1 = fmaxf(m1, mx1);
        const bool changed = (mn0 > m0) || (mn1 > m1);
        if (__any_sync(0xffffffffu, changed)) {
            const float a0 = ex2f(m0 - mn0), a1 = ex2f(m1 - mn1);
            #pragma unroll
            for (int nt = 0; nt < 9; nt++) {
                oacc[nt][0] *= a0; oacc[nt][1] *= a0;
                oacc[nt][2] *= a1; oacc[nt][3] *= a1;
            }
            m0 = mn0; m1 = mn1;
        }

        #pragma unroll
        for (int nt = 0; nt < 8; nt++) {
            sacc[nt][0] = ex2f(sacc[nt][0] - m0);
            sacc[nt][1] = ex2f(sacc[nt][1] - m0);
            sacc[nt][2] = ex2f(sacc[nt][2] - m1);
            sacc[nt][3] = ex2f(sacc[nt][3] - m1);
        }

        // ---- O += P * [V | 1] ; P packed from regs (C-frag == A-frag) ----
        #pragma unroll
        for (int kk = 0; kk < 4; kk++) {
            uint32_t pf[4];
            pf[0] = packh2(sacc[2*kk    ][0], sacc[2*kk    ][1]);
            pf[1] = packh2(sacc[2*kk    ][2], sacc[2*kk    ][3]);
            pf[2] = packh2(sacc[2*kk + 1][0], sacc[2*kk + 1][1]);
            pf[3] = packh2(sacc[2*kk + 1][2], sacc[2*kk + 1][3]);
            #pragma unroll
            for (int np = 0; np < 4; np++) {
                uint32_t bt[4];
                ldmx4t(bt, Vs + (kk*16 + trow) * APAD + np*16 + tcol);
                mma_f16(oacc[2*np    ], pf, &bt[0]);
                mma_f16(oacc[2*np + 1], pf, &bt[2]);
            }
            // l column: cols 64-71 (col 64 = 1.0, rest 0)
            uint32_t lb[2];
            ldmx2t(lb, Vs + (kk*16 + vrow2) * APAD + 64);
            mma_f16(oacc[8], pf, lb);
        }
    }

    // ---- l lives in oacc[8]: col 64 -> t4==0's c[0]/c[2]; broadcast ----
    const int qbase = lane & ~3;
    const float inv0 = 1.f / __shfl_sync(0xffffffffu, oacc[8][0], qbase);
    const float inv1 = 1.f / __shfl_sync(0xffffffffu, oacc[8][2], qbase);

    const int b = bh >> 4, h = bh & 15;
    #pragma unroll
    for (int nt = 0; nt < 8; nt++) {
        const int col = h * DHEAD + nt*8 + 2*t4;
        *(uint32_t*)&g_ah[((size_t)(b*SEQ + rowa)) * D_MODEL + col] =
            packh2(oacc[nt][0] * inv0, oacc[nt][1] * inv0);
        *(uint32_t*)&g_ah[((size_t)(b*SEQ + rowb)) * D_MODEL + col] =
            packh2(oacc[nt][2] * inv1, oacc[nt][3] * inv1);
    }
}

// ---------------------------------------------------------------------------
extern "C" void kernel_launch(void* const* d_in, const int* in_sizes, int n_in,
                              void* d_out, int out_size)
{
    const float* x  = (const float*)d_in[0];
    const float* Wq = (const float*)d_in[1];
    const float* bq = (const float*)d_in[2];
    const float* Wk = (const float*)d_in[3];
    const float* bk = (const float*)d_in[4];
    const float* Wv = (const float*)d_in[5];
    const float* bv = (const float*)d_in[6];
    const float* Wo = (const float*)d_in[7];
    const float* bo = (const float*)d_in[8];

    __half *xh, *wqh, *wkh, *wvh, *woh, *ah;
    cudaGetSymbolAddress((void**)&xh,  g_xh);
    cudaGetSymbolAddress((void**)&wqh, g_wqh);
    cudaGetSymbolAddress((void**)&wkh, g_wkh);
    cudaGetSymbolAddress((void**)&wvh, g_wvh);
    cudaGetSymbolAddress((void**)&woh, g_woh);
    cudaGetSymbolAddress((void**)&ah,  g_ah);

    // fused fp32 -> fp16 pre-pass (1 launch)
    cvt_all<<<NCVT/256, 256>>>(x, Wq, Wk, Wv, Wo);

    cudaFuncSetAttribute(gemm_qkv,
                         cudaFuncAttributeMaxDynamicSharedMemorySize, GEMM_SMEM);
    cudaFuncSetAttribute(gemm_out,
                         cudaFuncAttributeMaxDynamicSharedMemorySize, OUT_SMEM);
    cudaFuncSetAttribute(attn_h,
                         cudaFuncAttributeMaxDynamicSharedMemorySize, ATTN_SMEM);

    // fused QKV projection (1 launch, z selects head)
    gemm_qkv<<<dim3(D_MODEL/128, NTOK/128, 3), 128, GEMM_SMEM>>>(
        xh, wqh, bq, wkh, bk, wvh, bv);

    attn_h<<<dim3(SEQ/ABR, BATCH*NHEAD), 256, ATTN_SMEM>>>();

    // output projection
    gemm_out<<<dim3(D_MODEL/128, NTOK/64), 128, OUT_SMEM>>>(
        ah, woh, bo, (float*)d_out);
}

// round 14
// speedup vs baseline: 16.8075x; 1.0082x over previous
#include <cuda_runtime.h>
#include <cuda_fp16.h>
#include <math.h>
#include <cstdint>

#define D_MODEL 1024
#define NHEAD   16
#define DHEAD   64
#define BATCH   4
#define SEQ     2048
#define NTOK    (BATCH*SEQ)   // 8192
#define KDIM    1024

// ---------------------------------------------------------------------------
// fp16 scratch (allocation-free rule: __device__ globals)
// ---------------------------------------------------------------------------
__device__ __half g_xh[(size_t)NTOK*KDIM];
__device__ __half g_wqh[(size_t)KDIM*D_MODEL];
__device__ __half g_wkh[(size_t)KDIM*D_MODEL];
__device__ __half g_wvh[(size_t)KDIM*D_MODEL];
__device__ __half g_woh[(size_t)KDIM*D_MODEL];
__device__ __half g_qh[(size_t)BATCH*NHEAD*SEQ*DHEAD];   // [B,H,S,Dh]
__device__ __half g_kh[(size_t)BATCH*NHEAD*SEQ*DHEAD];
__device__ __half g_vh[(size_t)BATCH*NHEAD*SEQ*DHEAD];
__device__ __half g_ah[(size_t)NTOK*D_MODEL];            // [B,S,D]

// ---------------------------------------------------------------------------
// helpers
// ---------------------------------------------------------------------------
__device__ __forceinline__ uint32_t packh2(float a, float b) {
    __half2 h = __floats2half2_rn(a, b);
    return *reinterpret_cast<uint32_t*>(&h);
}
__device__ __forceinline__ float ex2f(float x) {
    float y;
    asm("ex2.approx.ftz.f32 %0, %1;" : "=f"(y) : "f"(x));
    return y;
}
__device__ __forceinline__ void mma_f16(float* c, const uint32_t* a, const uint32_t* b) {
    asm volatile(
        "mma.sync.aligned.m16n8k16.row.col.f32.f16.f16.f32 "
        "{%0,%1,%2,%3}, {%4,%5,%6,%7}, {%8,%9}, {%0,%1,%2,%3};"
        : "+f"(c[0]), "+f"(c[1]), "+f"(c[2]), "+f"(c[3])
        : "r"(a[0]), "r"(a[1]), "r"(a[2]), "r"(a[3]), "r"(b[0]), "r"(b[1]));
}
__device__ __forceinline__ void ldmx4(uint32_t* r, const void* p) {
    uint32_t a = (uint32_t)__cvta_generic_to_shared(p);
    asm volatile("ldmatrix.sync.aligned.m8n8.x4.shared.b16 {%0,%1,%2,%3}, [%4];"
                 : "=r"(r[0]), "=r"(r[1]), "=r"(r[2]), "=r"(r[3]) : "r"(a));
}
__device__ __forceinline__ void ldmx4t(uint32_t* r, const void* p) {
    uint32_t a = (uint32_t)__cvta_generic_to_shared(p);
    asm volatile("ldmatrix.sync.aligned.m8n8.x4.trans.shared.b16 {%0,%1,%2,%3}, [%4];"
                 : "=r"(r[0]), "=r"(r[1]), "=r"(r[2]), "=r"(r[3]) : "r"(a));
}
__device__ __forceinline__ void cp16(void* s, const void* g) {
    uint32_t a = (uint32_t)__cvta_generic_to_shared(s);
    asm volatile("cp.async.cg.shared.global [%0], [%1], 16;" :: "r"(a), "l"(g) : "memory");
}
__device__ __forceinline__ void cp_commit() {
    asm volatile("cp.async.commit_group;" ::: "memory");
}
template<int N>
__device__ __forceinline__ void cp_wait() {
    asm volatile("cp.async.wait_group %0;" :: "n"(N) : "memory");
}

// ---------------------------------------------------------------------------
// fused fp32 -> fp16 conversion
// ---------------------------------------------------------------------------
#define NX8 (NTOK * KDIM / 8)       // 1048576 = 2^20
#define NW8 (KDIM * D_MODEL / 8)    // 131072  = 2^17
#define NCVT (NX8 + 4 * NW8)        // 1572864

__global__ __launch_bounds__(256)
void cvt_all(const float* __restrict__ x,
             const float* __restrict__ w0, const float* __restrict__ w1,
             const float* __restrict__ w2, const float* __restrict__ w3)
{
    const int i = blockIdx.x * 256 + threadIdx.x;
    const float* src;
    __half* dst;
    int off;
    if (i < NX8) {
        src = x; dst = g_xh; off = i;
    } else {
        const int t = i - NX8;
        const int w = t >> 17;            // NW8 = 2^17
        off = t & (NW8 - 1);
        switch (w) {
            case 0:  src = w0; dst = g_wqh; break;
            case 1:  src = w1; dst = g_wkh; break;
            case 2:  src = w2; dst = g_wvh; break;
            default: src = w3; dst = g_woh; break;
        }
    }
    float4 a = ((const float4*)src)[2*off];
    float4 b = ((const float4*)src)[2*off + 1];
    uint4 o;
    o.x = packh2(a.x, a.y);  o.y = packh2(a.z, a.w);
    o.z = packh2(b.x, b.y);  o.w = packh2(b.z, b.w);
    ((uint4*)dst)[off] = o;
}

// ---------------------------------------------------------------------------
// QKV fp16 GEMM (NT), cp.async 3-stage, CTA 128x128, 128 thr, warp 64x64.
// ---------------------------------------------------------------------------
#define GBK   32
#define GKCH  (KDIM / GBK)      // 32
#define GPAD  40                // halves per smem row
#define GSTR  (128 * GPAD)      // halves per stage per operand
#define GEMM_SMEM (3 * 2 * GSTR * 2)   // 61440 B

__global__ __launch_bounds__(128, 3)
void gemm_qkv(const __half* __restrict__ A,
              const __half* __restrict__ W0, const float* __restrict__ b0,
              const __half* __restrict__ W1, const float* __restrict__ b1,
              const __half* __restrict__ W2, const float* __restrict__ b2)
{
    extern __shared__ __align__(16) char dsm[];
    __half* As = (__half*)dsm;            // [3][128][GPAD]
    __half* Ws = As + 3 * GSTR;           // [3][128][GPAD]

    const __half* Wsel = W0;
    const float*  bsel = b0;
    __half* Hout = g_qh;
    if (blockIdx.z == 1)      { Wsel = W1; bsel = b1; Hout = g_kh; }
    else if (blockIdx.z == 2) { Wsel = W2; bsel = b2; Hout = g_vh; }

    const int tid    = threadIdx.x;
    const int lane   = tid & 31;
    const int wid    = tid >> 5;
    const int warp_m = wid & 1;
    const int warp_n = wid >> 1;
    const int gr     = lane >> 2;
    const int t4     = lane & 3;

    const int lr   = lane & 7;
    const int arow = ((lane >> 3) & 1) * 8 + lr;
    const int acol = ((lane >> 4) & 1) * 8;
    const int brow = ((lane >> 4) & 1) * 8 + lr;
    const int bcol = ((lane >> 3) & 1) * 8;

    const int bn = blockIdx.y * 128;
    const int bm = blockIdx.x * 128;

    const __half* Ag = A + (size_t)bn * KDIM;
    const __half* Wg = Wsel + (size_t)bm * KDIM;

    auto issue = [&](int c, int s) {
        __half* ab = As + s * GSTR;
        __half* wb = Ws + s * GSTR;
        #pragma unroll
        for (int i = 0; i < 4; i++) {
            const int idx = tid + i * 128;        // 0..511
            const int r = idx >> 2, ch = idx & 3;
            cp16(ab + r * GPAD + ch * 8, Ag + (size_t)r * KDIM + c * GBK + ch * 8);
            cp16(wb + r * GPAD + ch * 8, Wg + (size_t)r * KDIM + c * GBK + ch * 8);
        }
    };

    float acc[4][8][4];
    #pragma unroll
    for (int mt = 0; mt < 4; mt++)
        #pragma unroll
        for (int nt = 0; nt < 8; nt++)
            #pragma unroll
            for (int i = 0; i < 4; i++) acc[mt][nt][i] = 0.f;

    issue(0, 0); cp_commit();
    issue(1, 1); cp_commit();

    for (int c = 0; c < GKCH; c++) {
        if (c == GKCH - 1) cp_wait<0>(); else cp_wait<1>();
        __syncthreads();
        if (c + 2 < GKCH) { issue(c + 2, (c + 2) % 3); cp_commit(); }

        const int s = c % 3;
        const __half* Ab = As + s * GSTR + (warp_m * 64) * GPAD;
        const __half* Wb = Ws + s * GSTR + (warp_n * 64) * GPAD;
        #pragma unroll
        for (int kk = 0; kk < 2; kk++) {
            const int k0 = kk * 16;
            uint32_t af[4][4], bb[4][4];
            #pragma unroll
            for (int mt = 0; mt < 4; mt++)
                ldmx4(af[mt], Ab + (mt*16 + arow) * GPAD + k0 + acol);
            #pragma unroll
            for (int np = 0; np < 4; np++)
                ldmx4(bb[np], Wb + (np*16 + brow) * GPAD + k0 + bcol);
            #pragma unroll
            for (int mt = 0; mt < 4; mt++)
                #pragma unroll
                for (int np = 0; np < 4; np++) {
                    mma_f16(acc[mt][2*np    ], af[mt], &bb[np][0]);
                    mma_f16(acc[mt][2*np + 1], af[mt], &bb[np][2]);
                }
        }
    }

    #pragma unroll
    for (int nt = 0; nt < 8; nt++) {
        const int col = bm + warp_n * 64 + nt * 8 + t4 * 2;
        const float2 bv = *(const float2*)&bsel[col];
        #pragma unroll
        for (int mt = 0; mt < 4; mt++) {
            const int row = bn + warp_m * 64 + mt * 16 + gr;
            const int h = col / DHEAD, d = col % DHEAD;
            const int bb0 = row / SEQ, s0 = row % SEQ;
            const int bb1 = (row + 8) / SEQ, s1 = (row + 8) % SEQ;
            *(uint32_t*)&Hout[(((size_t)(bb0*NHEAD + h)*SEQ + s0)*DHEAD) + d] =
                packh2(acc[mt][nt][0] + bv.x, acc[mt][nt][1] + bv.y);
            *(uint32_t*)&Hout[(((size_t)(bb1*NHEAD + h)*SEQ + s1)*DHEAD) + d] =
                packh2(acc[mt][nt][2] + bv.x, acc[mt][nt][3] + bv.y);
        }
    }
}

// ---------------------------------------------------------------------------
// Output projection GEMM: CTA 64x128, 128 thr, 3-stage, 4 CTAs/SM.
// ---------------------------------------------------------------------------
#define OSTR_A (64 * GPAD)
#define OSTR   (192 * GPAD)
#define OUT_SMEM (3 * OSTR * 2)          // 46080 B

__global__ __launch_bounds__(128, 4)
void gemm_out(const __half* __restrict__ A, const __half* __restrict__ W,
              const float* __restrict__ bias, float* __restrict__ Y)
{
    extern __shared__ __align__(16) char dsm[];
    __half* Sm = (__half*)dsm;

    const int tid    = threadIdx.x;
    const int lane   = tid & 31;
    const int wid    = tid >> 5;
    const int warp_m = wid & 1;
    const int warp_n = wid >> 1;
    const int gr     = lane >> 2;
    const int t4     = lane & 3;

    const int lr   = lane & 7;
    const int arow = ((lane >> 3) & 1) * 8 + lr;
    const int acol = ((lane >> 4) & 1) * 8;
    const int brow = ((lane >> 4) & 1) * 8 + lr;
    const int bcol = ((lane >> 3) & 1) * 8;

    const int bn = blockIdx.y * 64;
    const int bm = blockIdx.x * 128;

    const __half* Ag = A + (size_t)bn * KDIM;
    const __half* Wg = W + (size_t)bm * KDIM;

    auto issue = [&](int c, int s) {
        __half* base = Sm + s * OSTR;
        #pragma unroll
        for (int i = 0; i < 6; i++) {
            const int idx = tid + i * 128;        // 0..767
            if (idx < 256) {
                const int r = idx >> 2, ch = idx & 3;
                cp16(base + r * GPAD + ch * 8, Ag + (size_t)r * KDIM + c * GBK + ch * 8);
            } else {
                const int j = idx - 256;
                const int r = j >> 2, ch = j & 3;
                cp16(base + OSTR_A + r * GPAD + ch * 8, Wg + (size_t)r * KDIM + c * GBK + ch * 8);
            }
        }
    };

    float acc[2][8][4];
    #pragma unroll
    for (int mt = 0; mt < 2; mt++)
        #pragma unroll
        for (int nt = 0; nt < 8; nt++)
            #pragma unroll
            for (int i = 0; i < 4; i++) acc[mt][nt][i] = 0.f;

    issue(0, 0); cp_commit();
    issue(1, 1); cp_commit();

    for (int c = 0; c < GKCH; c++) {
        if (c == GKCH - 1) cp_wait<0>(); else cp_wait<1>();
        __syncthreads();
        if (c + 2 < GKCH) { issue(c + 2, (c + 2) % 3); cp_commit(); }

        const int s = c % 3;
        const __half* Ab = Sm + s * OSTR + (warp_m * 32) * GPAD;
        const __half* Wb = Sm + s * OSTR + OSTR_A + (warp_n * 64) * GPAD;
        #pragma unroll
        for (int kk = 0; kk < 2; kk++) {
            const int k0 = kk * 16;
            uint32_t af[2][4], bb[4][4];
            #pragma unroll
            for (int mt = 0; mt < 2; mt++)
                ldmx4(af[mt], Ab + (mt*16 + arow) * GPAD + k0 + acol);
            #pragma unroll
            for (int np = 0; np < 4; np++)
                ldmx4(bb[np], Wb + (np*16 + brow) * GPAD + k0 + bcol);
            #pragma unroll
            for (int mt = 0; mt < 2; mt++)
                #pragma unroll
                for (int np = 0; np < 4; np++) {
                    mma_f16(acc[mt][2*np    ], af[mt], &bb[np][0]);
                    mma_f16(acc[mt][2*np + 1], af[mt], &bb[np][2]);
                }
        }
    }

    #pragma unroll
    for (int nt = 0; nt < 8; nt++) {
        const int col = bm + warp_n * 64 + nt * 8 + t4 * 2;
        const float2 bv = *(const float2*)&bias[col];
        #pragma unroll
        for (int mt = 0; mt < 2; mt++) {
            const int row = bn + warp_m * 32 + mt * 16 + gr;
            *(float2*)&Y[(size_t)row * D_MODEL + col] =
                make_float2(acc[mt][nt][0] + bv.x, acc[mt][nt][1] + bv.y);
            *(float2*)&Y[(size_t)(row + 8) * D_MODEL + col] =
                make_float2(acc[mt][nt][2] + bv.x, acc[mt][nt][3] + bv.y);
        }
    }
}

// ---------------------------------------------------------------------------
// Causal flash attention, fp16 mma.
// NEW: 6-stage 64-col K/V ring, processed in PAIRS: one cp_wait + one barrier
// + one double-issue per 128 kv cols (halves sync count, prefetch depth 4-5).
// Q staging overlays K stages 4-5 (consumed into regs before pair-0 barrier;
// stages 4/5 first refilled after that barrier).
// NEW: l-column B-fragment is a constant (ones col) -> no ldmatrix, no pad init.
// ---------------------------------------------------------------------------
#define ABR   128
#define ABC   64
#define APAD  72
#define KVSTR (ABC * APAD)               // 4608 halves per 64-row stage
#define NSTG  6
#define ATTN_SMEM (NSTG * 2 * KVSTR * 2) // 110592 B (Q overlays K stages 4-5)
#define QSCALE (0.125f * 1.44269504088896340736f)

__global__ __launch_bounds__(256, 2)
void attn_h()
{
    extern __shared__ __align__(16) char dsm[];
    __half* Ksm = (__half*)dsm;               // [6][64][APAD]
    __half* Vsm = Ksm + NSTG * KVSTR;         // [6][64][APAD]
    __half* Qs  = Ksm + 4 * KVSTR;            // overlay: K stages 4,5 (9216 halves)

    const int bh = blockIdx.y;
    const int qb = (int)gridDim.x - 1 - (int)blockIdx.x;   // heavy blocks first
    const int q0 = qb * ABR;

    const __half* Qg = g_qh + (size_t)bh * SEQ * DHEAD;
    const __half* Kg = g_kh + (size_t)bh * SEQ * DHEAD;
    const __half* Vg = g_vh + (size_t)bh * SEQ * DHEAD;

    const int tid  = threadIdx.x;
    const int lane = tid & 31;
    const int wid  = tid >> 5;
    const int gr   = lane >> 2;
    const int t4   = lane & 3;
    const int r0   = wid * 16;

    const int lr   = lane & 7;
    const int arow = ((lane >> 3) & 1) * 8 + lr;
    const int acol = ((lane >> 4) & 1) * 8;
    const int brow = ((lane >> 4) & 1) * 8 + lr;   // K B-frags
    const int bcol = ((lane >> 3) & 1) * 8;
    const int trow = ((lane >> 3) & 1) * 8 + lr;   // V B-frags (trans)
    const int tcol = ((lane >> 4) & 1) * 8;

    // constant ones-column B fragment: B[k][n] = (n==0); lane col = gr
    const uint32_t lones = (gr == 0) ? 0x3C003C00u : 0u;
    const uint32_t lb[2] = { lones, lones };

    const int pmax = qb;   // pairs of 64-col tiles; tiles 2p, 2p+1

    auto issue1 = [&](int t) {
        const int s = t % NSTG;
        #pragma unroll
        for (int i = 0; i < 2; i++) {
            const int idx = tid + i * 256;     // 0..511
            const int r = idx >> 3, ch = idx & 7;
            const size_t goff = (size_t)(t * ABC + r) * DHEAD + ch * 8;
            cp16(Ksm + s * KVSTR + r * APAD + ch * 8, Kg + goff);
            cp16(Vsm + s * KVSTR + r * APAD + ch * 8, Vg + goff);
        }
    };

    issue1(0); issue1(1); cp_commit();                      // group 0
    if (pmax >= 1) { issue1(2); issue1(3); cp_commit(); }   // group 1

    // ---- stage Q (x log2e/8) into overlay region ----
    {
        const int r = tid >> 1, h = (tid & 1) * 32;
        const __half* src = Qg + (size_t)(q0 + r) * DHEAD + h;
        #pragma unroll
        for (int i = 0; i < 4; i++) {
            uint4 u = *(const uint4*)(src + i * 8);
            const __half2* hp = (const __half2*)&u;
            uint4 o;
            uint32_t* op = (uint32_t*)&o;
            #pragma unroll
            for (int k = 0; k < 4; k++) {
                float2 f = __half22float2(hp[k]);
                op[k] = packh2(f.x * QSCALE, f.y * QSCALE);
            }
            *(uint4*)&Qs[r * APAD + h + i * 8] = o;
        }
    }
    __syncthreads();

    uint32_t Qf[4][4];
    #pragma unroll
    for (int kk = 0; kk < 4; kk++)
        ldmx4(Qf[kk], Qs + (r0 + arow) * APAD + kk * 16 + acol);
    // Qf resident; Qs overlay region may be overwritten after the next barrier.

    float m0 = -1e30f, m1 = -1e30f;
    float oacc[9][4];                 // [8] = l column (P . ones)
    #pragma unroll
    for (int nt = 0; nt < 9; nt++)
        #pragma unroll
        for (int i = 0; i < 4; i++) oacc[nt][i] = 0.f;

    const int rowa = q0 + r0 + gr;
    const int rowb = rowa + 8;

    for (int p = 0; p <= pmax; p++) {
        if (p < pmax) cp_wait<1>(); else cp_wait<0>();
        __syncthreads();
        // Stages (2p+4)%6,(2p+5)%6 held tiles 2p-2,2p-1: read in pair p-1,
        // all warps passed the barrier above => safe to refill.
        if (p + 2 <= pmax) { issue1(2*p + 4); issue1(2*p + 5); cp_commit(); }

        const bool needmask = (p == pmax);

        #pragma unroll
        for (int h = 0; h < 2; h++) {
            const int t = 2*p + h;
            const __half* Ks = Ksm + (t % NSTG) * KVSTR;
            const __half* Vs = Vsm + (t % NSTG) * KVSTR;
            const int kv0 = t * ABC;

            // ---- S = Qs * K^T (scale + log2e folded into Q) ----
            float sacc[8][4];
            #pragma unroll
            for (int nt = 0; nt < 8; nt++)
                #pragma unroll
                for (int i = 0; i < 4; i++) sacc[nt][i] = 0.f;

            #pragma unroll
            for (int kk = 0; kk < 4; kk++) {
                #pragma unroll
                for (int np = 0; np < 4; np++) {
                    uint32_t bb[4];
                    ldmx4(bb, Ks + (np*16 + brow) * APAD + kk*16 + bcol);
                    mma_f16(sacc[2*np    ], Qf[kk], &bb[0]);
                    mma_f16(sacc[2*np + 1], Qf[kk], &bb[2]);
                }
            }

            // ---- causal mask (last pair only) ----
            if (needmask) {
                #pragma unroll
                for (int nt = 0; nt < 8; nt++) {
                    const int col0 = kv0 + nt*8 + 2*t4;
                    if (col0     > rowa) sacc[nt][0] = -1e30f;
                    if (col0 + 1 > rowa) sacc[nt][1] = -1e30f;
                    if (col0     > rowb) sacc[nt][2] = -1e30f;
                    if (col0 + 1 > rowb) sacc[nt][3] = -1e30f;
                }
            }

            // ---- online softmax, log2 domain (rows gr, gr+8) ----
            float mx0 = -1e30f, mx1 = -1e30f;
            #pragma unroll
            for (int nt = 0; nt < 8; nt++) {
                mx0 = fmaxf(mx0, fmaxf(sacc[nt][0], sacc[nt][1]));
                mx1 = fmaxf(mx1, fmaxf(sacc[nt][2], sacc[nt][3]));
            }
            mx0 = fmaxf(mx0, __shfl_xor_sync(0xffffffffu, mx0, 1));
            mx0 = fmaxf(mx0, __shfl_xor_sync(0xffffffffu, mx0, 2));
            mx1 = fmaxf(mx1, __shfl_xor_sync(0xffffffffu, mx1, 1));
            mx1 = fmaxf(mx1, __shfl_xor_sync(0xffffffffu, mx1, 2));

            const float mn0 = fmaxf(m0, mx0), mn1 = fmaxf(m1, mx1);
            const bool changed = (mn0 > m0) || (mn1 > m1);
            if (__any_sync(0xffffffffu, changed)) {
                const float a0 = ex2f(m0 - mn0), a1 = ex2f(m1 - mn1);
                #pragma unroll
                for (int nt = 0; nt < 9; nt++) {
                    oacc[nt][0] *= a0; oacc[nt][1] *= a0;
                    oacc[nt][2] *= a1; oacc[nt][3] *= a1;
                }
                m0 = mn0; m1 = mn1;
            }

            #pragma unroll
            for (int nt = 0; nt < 8; nt++) {
                sacc[nt][0] = ex2f(sacc[nt][0] - m0);
                sacc[nt][1] = ex2f(sacc[nt][1] - m0);
                sacc[nt][2] = ex2f(sacc[nt][2] - m1);
                sacc[nt][3] = ex2f(sacc[nt][3] - m1);
            }

            // ---- O += P * V ; l += P . 1 (constant B-frag) ----
            #pragma unroll
            for (int kk = 0; kk < 4; kk++) {
                uint32_t pf[4];
                pf[0] = packh2(sacc[2*kk    ][0], sacc[2*kk    ][1]);
                pf[1] = packh2(sacc[2*kk    ][2], sacc[2*kk    ][3]);
                pf[2] = packh2(sacc[2*kk + 1][0], sacc[2*kk + 1][1]);
                pf[3] = packh2(sacc[2*kk + 1][2], sacc[2*kk + 1][3]);
                #pragma unroll
                for (int np = 0; np < 4; np++) {
                    uint32_t bt[4];
                    ldmx4t(bt, Vs + (kk*16 + trow) * APAD + np*16 + tcol);
                    mma_f16(oacc[2*np    ], pf, &bt[0]);
                    mma_f16(oacc[2*np + 1], pf, &bt[2]);
                }
                mma_f16(oacc[8], pf, lb);
            }
        }
    }

    // ---- l lives in oacc[8]: col 0 -> t4==0's c[0]/c[2]; broadcast ----
    const int qbase = lane & ~3;
    const float inv0 = 1.f / __shfl_sync(0xffffffffu, oacc[8][0], qbase);
    const float inv1 = 1.f / __shfl_sync(0xffffffffu, oacc[8][2], qbase);

    const int b = bh >> 4, h = bh & 15;
    #pragma unroll
    for (int nt = 0; nt < 8; nt++) {
        const int col = h * DHEAD + nt*8 + 2*t4;
        *(uint32_t*)&g_ah[((size_t)(b*SEQ + rowa)) * D_MODEL + col] =
            packh2(oacc[nt][0] * inv0, oacc[nt][1] * inv0);
        *(uint32_t*)&g_ah[((size_t)(b*SEQ + rowb)) * D_MODEL + col] =
            packh2(oacc[nt][2] * inv1, oacc[nt][3] * inv1);
    }
}

// ---------------------------------------------------------------------------
extern "C" void kernel_launch(void* const* d_in, const int* in_sizes, int n_in,
                              void* d_out, int out_size)
{
    const float* x  = (const float*)d_in[0];
    const float* Wq = (const float*)d_in[1];
    const float* bq = (const float*)d_in[2];
    const float* Wk = (const float*)d_in[3];
    const float* bk = (const float*)d_in[4];
    const float* Wv = (const float*)d_in[5];
    const float* bv = (const float*)d_in[6];
    const float* Wo = (const float*)d_in[7];
    const float* bo = (const float*)d_in[8];

    __half *xh, *wqh, *wkh, *wvh, *woh, *ah;
    cudaGetSymbolAddress((void**)&xh,  g_xh);
    cudaGetSymbolAddress((void**)&wqh, g_wqh);
    cudaGetSymbolAddress((void**)&wkh, g_wkh);
    cudaGetSymbolAddress((void**)&wvh, g_wvh);
    cudaGetSymbolAddress((void**)&woh, g_woh);
    cudaGetSymbolAddress((void**)&ah,  g_ah);

    // fused fp32 -> fp16 pre-pass (1 launch)
    cvt_all<<<NCVT/256, 256>>>(x, Wq, Wk, Wv, Wo);

    cudaFuncSetAttribute(gemm_qkv,
                         cudaFuncAttributeMaxDynamicSharedMemorySize, GEMM_SMEM);
    cudaFuncSetAttribute(gemm_out,
                         cudaFuncAttributeMaxDynamicSharedMemorySize, OUT_SMEM);
    cudaFuncSetAttribute(attn_h,
                         cudaFuncAttributeMaxDynamicSharedMemorySize, ATTN_SMEM);

    // fused QKV projection (1 launch, z selects head)
    gemm_qkv<<<dim3(D_MODEL/128, NTOK/128, 3), 128, GEMM_SMEM>>>(
        xh, wqh, bq, wkh, bk, wvh, bv);

    attn_h<<<dim3(SEQ/ABR, BATCH*NHEAD), 256, ATTN_SMEM>>>();

    // output projection
    gemm_out<<<dim3(D_MODEL/128, NTOK/64), 128, OUT_SMEM>>>(
        ah, woh, bo, (float*)d_out);
}

// round 15
// speedup vs baseline: 16.9544x; 1.0087x over previous
#include <cuda_runtime.h>
#include <cuda_fp16.h>
#include <math.h>
#include <cstdint>

#define D_MODEL 1024
#define NHEAD   16
#define DHEAD   64
#define BATCH   4
#define SEQ     2048
#define NTOK    (BATCH*SEQ)   // 8192
#define KDIM    1024

// ---------------------------------------------------------------------------
// fp16 scratch (allocation-free rule: __device__ globals)
// ---------------------------------------------------------------------------
__device__ __half g_xh[(size_t)NTOK*KDIM];
__device__ __half g_wqh[(size_t)KDIM*D_MODEL];
__device__ __half g_wkh[(size_t)KDIM*D_MODEL];
__device__ __half g_wvh[(size_t)KDIM*D_MODEL];
__device__ __half g_woh[(size_t)KDIM*D_MODEL];
__device__ __half g_qh[(size_t)BATCH*NHEAD*SEQ*DHEAD];   // [B,H,S,Dh]
__device__ __half g_kh[(size_t)BATCH*NHEAD*SEQ*DHEAD];
__device__ __half g_vh[(size_t)BATCH*NHEAD*SEQ*DHEAD];
__device__ __half g_ah[(size_t)NTOK*D_MODEL];            // [B,S,D]

// ---------------------------------------------------------------------------
// helpers
// ---------------------------------------------------------------------------
__device__ __forceinline__ uint32_t packh2(float a, float b) {
    __half2 h = __floats2half2_rn(a, b);
    return *reinterpret_cast<uint32_t*>(&h);
}
__device__ __forceinline__ float ex2f(float x) {
    float y;
    asm("ex2.approx.ftz.f32 %0, %1;" : "=f"(y) : "f"(x));
    return y;
}
__device__ __forceinline__ void mma_f16(float* c, const uint32_t* a, const uint32_t* b) {
    asm volatile(
        "mma.sync.aligned.m16n8k16.row.col.f32.f16.f16.f32 "
        "{%0,%1,%2,%3}, {%4,%5,%6,%7}, {%8,%9}, {%0,%1,%2,%3};"
        : "+f"(c[0]), "+f"(c[1]), "+f"(c[2]), "+f"(c[3])
        : "r"(a[0]), "r"(a[1]), "r"(a[2]), "r"(a[3]), "r"(b[0]), "r"(b[1]));
}
__device__ __forceinline__ void ldmx4(uint32_t* r, const void* p) {
    uint32_t a = (uint32_t)__cvta_generic_to_shared(p);
    asm volatile("ldmatrix.sync.aligned.m8n8.x4.shared.b16 {%0,%1,%2,%3}, [%4];"
                 : "=r"(r[0]), "=r"(r[1]), "=r"(r[2]), "=r"(r[3]) : "r"(a));
}
__device__ __forceinline__ void ldmx4t(uint32_t* r, const void* p) {
    uint32_t a = (uint32_t)__cvta_generic_to_shared(p);
    asm volatile("ldmatrix.sync.aligned.m8n8.x4.trans.shared.b16 {%0,%1,%2,%3}, [%4];"
                 : "=r"(r[0]), "=r"(r[1]), "=r"(r[2]), "=r"(r[3]) : "r"(a));
}
__device__ __forceinline__ void cp16(void* s, const void* g) {
    uint32_t a = (uint32_t)__cvta_generic_to_shared(s);
    asm volatile("cp.async.cg.shared.global [%0], [%1], 16;" :: "r"(a), "l"(g) : "memory");
}
__device__ __forceinline__ void cp_commit() {
    asm volatile("cp.async.commit_group;" ::: "memory");
}
template<int N>
__device__ __forceinline__ void cp_wait() {
    asm volatile("cp.async.wait_group %0;" :: "n"(N) : "memory");
}

// ---------------------------------------------------------------------------
// fused fp32 -> fp16 conversion
// ---------------------------------------------------------------------------
#define NX8 (NTOK * KDIM / 8)       // 1048576 = 2^20
#define NW8 (KDIM * D_MODEL / 8)    // 131072  = 2^17
#define NCVT (NX8 + 4 * NW8)        // 1572864

__global__ __launch_bounds__(256)
void cvt_all(const float* __restrict__ x,
             const float* __restrict__ w0, const float* __restrict__ w1,
             const float* __restrict__ w2, const float* __restrict__ w3)
{
    const int i = blockIdx.x * 256 + threadIdx.x;
    const float* src;
    __half* dst;
    int off;
    if (i < NX8) {
        src = x; dst = g_xh; off = i;
    } else {
        const int t = i - NX8;
        const int w = t >> 17;            // NW8 = 2^17
        off = t & (NW8 - 1);
        switch (w) {
            case 0:  src = w0; dst = g_wqh; break;
            case 1:  src = w1; dst = g_wkh; break;
            case 2:  src = w2; dst = g_wvh; break;
            default: src = w3; dst = g_woh; break;
        }
    }
    float4 a = ((const float4*)src)[2*off];
    float4 b = ((const float4*)src)[2*off + 1];
    uint4 o;
    o.x = packh2(a.x, a.y);  o.y = packh2(a.z, a.w);
    o.z = packh2(b.x, b.y);  o.w = packh2(b.z, b.w);
    ((uint4*)dst)[off] = o;
}

// ---------------------------------------------------------------------------
// QKV fp16 GEMM (NT), cp.async 3-stage, CTA 128x128, 128 thr, warp 64x64.
// ---------------------------------------------------------------------------
#define GBK   32
#define GKCH  (KDIM / GBK)      // 32
#define GPAD  40                // halves per smem row
#define GSTR  (128 * GPAD)      // halves per stage per operand
#define GEMM_SMEM (3 * 2 * GSTR * 2)   // 61440 B

__global__ __launch_bounds__(128, 3)
void gemm_qkv(const __half* __restrict__ A,
              const __half* __restrict__ W0, const float* __restrict__ b0,
              const __half* __restrict__ W1, const float* __restrict__ b1,
              const __half* __restrict__ W2, const float* __restrict__ b2)
{
    extern __shared__ __align__(16) char dsm[];
    __half* As = (__half*)dsm;            // [3][128][GPAD]
    __half* Ws = As + 3 * GSTR;           // [3][128][GPAD]

    const __half* Wsel = W0;
    const float*  bsel = b0;
    __half* Hout = g_qh;
    if (blockIdx.z == 1)      { Wsel = W1; bsel = b1; Hout = g_kh; }
    else if (blockIdx.z == 2) { Wsel = W2; bsel = b2; Hout = g_vh; }

    const int tid    = threadIdx.x;
    const int lane   = tid & 31;
    const int wid    = tid >> 5;
    const int warp_m = wid & 1;
    const int warp_n = wid >> 1;
    const int gr     = lane >> 2;
    const int t4     = lane & 3;

    const int lr   = lane & 7;
    const int arow = ((lane >> 3) & 1) * 8 + lr;
    const int acol = ((lane >> 4) & 1) * 8;
    const int brow = ((lane >> 4) & 1) * 8 + lr;
    const int bcol = ((lane >> 3) & 1) * 8;

    const int bn = blockIdx.y * 128;
    const int bm = blockIdx.x * 128;

    const __half* Ag = A + (size_t)bn * KDIM;
    const __half* Wg = Wsel + (size_t)bm * KDIM;

    auto issue = [&](int c, int s) {
        __half* ab = As + s * GSTR;
        __half* wb = Ws + s * GSTR;
        #pragma unroll
        for (int i = 0; i < 4; i++) {
            const int idx = tid + i * 128;        // 0..511
            const int r = idx >> 2, ch = idx & 3;
            cp16(ab + r * GPAD + ch * 8, Ag + (size_t)r * KDIM + c * GBK + ch * 8);
            cp16(wb + r * GPAD + ch * 8, Wg + (size_t)r * KDIM + c * GBK + ch * 8);
        }
    };

    float acc[4][8][4];
    #pragma unroll
    for (int mt = 0; mt < 4; mt++)
        #pragma unroll
        for (int nt = 0; nt < 8; nt++)
            #pragma unroll
            for (int i = 0; i < 4; i++) acc[mt][nt][i] = 0.f;

    issue(0, 0); cp_commit();
    issue(1, 1); cp_commit();

    for (int c = 0; c < GKCH; c++) {
        if (c == GKCH - 1) cp_wait<0>(); else cp_wait<1>();
        __syncthreads();
        if (c + 2 < GKCH) { issue(c + 2, (c + 2) % 3); cp_commit(); }

        const int s = c % 3;
        const __half* Ab = As + s * GSTR + (warp_m * 64) * GPAD;
        const __half* Wb = Ws + s * GSTR + (warp_n * 64) * GPAD;
        #pragma unroll
        for (int kk = 0; kk < 2; kk++) {
            const int k0 = kk * 16;
            uint32_t af[4][4], bb[4][4];
            #pragma unroll
            for (int mt = 0; mt < 4; mt++)
                ldmx4(af[mt], Ab + (mt*16 + arow) * GPAD + k0 + acol);
            #pragma unroll
            for (int np = 0; np < 4; np++)
                ldmx4(bb[np], Wb + (np*16 + brow) * GPAD + k0 + bcol);
            #pragma unroll
            for (int mt = 0; mt < 4; mt++)
                #pragma unroll
                for (int np = 0; np < 4; np++) {
                    mma_f16(acc[mt][2*np    ], af[mt], &bb[np][0]);
                    mma_f16(acc[mt][2*np + 1], af[mt], &bb[np][2]);
                }
        }
    }

    #pragma unroll
    for (int nt = 0; nt < 8; nt++) {
        const int col = bm + warp_n * 64 + nt * 8 + t4 * 2;
        const float2 bv = *(const float2*)&bsel[col];
        #pragma unroll
        for (int mt = 0; mt < 4; mt++) {
            const int row = bn + warp_m * 64 + mt * 16 + gr;
            const int h = col / DHEAD, d = col % DHEAD;
            const int bb0 = row / SEQ, s0 = row % SEQ;
            const int bb1 = (row + 8) / SEQ, s1 = (row + 8) % SEQ;
            *(uint32_t*)&Hout[(((size_t)(bb0*NHEAD + h)*SEQ + s0)*DHEAD) + d] =
                packh2(acc[mt][nt][0] + bv.x, acc[mt][nt][1] + bv.y);
            *(uint32_t*)&Hout[(((size_t)(bb1*NHEAD + h)*SEQ + s1)*DHEAD) + d] =
                packh2(acc[mt][nt][2] + bv.x, acc[mt][nt][3] + bv.y);
        }
    }
}

// ---------------------------------------------------------------------------
// Output projection GEMM: CTA 64x128, 128 thr, 3-stage, 4 CTAs/SM.
// ---------------------------------------------------------------------------
#define OSTR_A (64 * GPAD)
#define OSTR   (192 * GPAD)
#define OUT_SMEM (3 * OSTR * 2)          // 46080 B

__global__ __launch_bounds__(128, 4)
void gemm_out(const __half* __restrict__ A, const __half* __restrict__ W,
              const float* __restrict__ bias, float* __restrict__ Y)
{
    extern __shared__ __align__(16) char dsm[];
    __half* Sm = (__half*)dsm;

    const int tid    = threadIdx.x;
    const int lane   = tid & 31;
    const int wid    = tid >> 5;
    const int warp_m = wid & 1;
    const int warp_n = wid >> 1;
    const int gr     = lane >> 2;
    const int t4     = lane & 3;

    const int lr   = lane & 7;
    const int arow = ((lane >> 3) & 1) * 8 + lr;
    const int acol = ((lane >> 4) & 1) * 8;
    const int brow = ((lane >> 4) & 1) * 8 + lr;
    const int bcol = ((lane >> 3) & 1) * 8;

    const int bn = blockIdx.y * 64;
    const int bm = blockIdx.x * 128;

    const __half* Ag = A + (size_t)bn * KDIM;
    const __half* Wg = W + (size_t)bm * KDIM;

    auto issue = [&](int c, int s) {
        __half* base = Sm + s * OSTR;
        #pragma unroll
        for (int i = 0; i < 6; i++) {
            const int idx = tid + i * 128;        // 0..767
            if (idx < 256) {
                const int r = idx >> 2, ch = idx & 3;
                cp16(base + r * GPAD + ch * 8, Ag + (size_t)r * KDIM + c * GBK + ch * 8);
            } else {
                const int j = idx - 256;
                const int r = j >> 2, ch = j & 3;
                cp16(base + OSTR_A + r * GPAD + ch * 8, Wg + (size_t)r * KDIM + c * GBK + ch * 8);
            }
        }
    };

    float acc[2][8][4];
    #pragma unroll
    for (int mt = 0; mt < 2; mt++)
        #pragma unroll
        for (int nt = 0; nt < 8; nt++)
            #pragma unroll
            for (int i = 0; i < 4; i++) acc[mt][nt][i] = 0.f;

    issue(0, 0); cp_commit();
    issue(1, 1); cp_commit();

    for (int c = 0; c < GKCH; c++) {
        if (c == GKCH - 1) cp_wait<0>(); else cp_wait<1>();
        __syncthreads();
        if (c + 2 < GKCH) { issue(c + 2, (c + 2) % 3); cp_commit(); }

        const int s = c % 3;
        const __half* Ab = Sm + s * OSTR + (warp_m * 32) * GPAD;
        const __half* Wb = Sm + s * OSTR + OSTR_A + (warp_n * 64) * GPAD;
        #pragma unroll
        for (int kk = 0; kk < 2; kk++) {
            const int k0 = kk * 16;
            uint32_t af[2][4], bb[4][4];
            #pragma unroll
            for (int mt = 0; mt < 2; mt++)
                ldmx4(af[mt], Ab + (mt*16 + arow) * GPAD + k0 + acol);
            #pragma unroll
            for (int np = 0; np < 4; np++)
                ldmx4(bb[np], Wb + (np*16 + brow) * GPAD + k0 + bcol);
            #pragma unroll
            for (int mt = 0; mt < 2; mt++)
                #pragma unroll
                for (int np = 0; np < 4; np++) {
                    mma_f16(acc[mt][2*np    ], af[mt], &bb[np][0]);
                    mma_f16(acc[mt][2*np + 1], af[mt], &bb[np][2]);
                }
        }
    }

    #pragma unroll
    for (int nt = 0; nt < 8; nt++) {
        const int col = bm + warp_n * 64 + nt * 8 + t4 * 2;
        const float2 bv = *(const float2*)&bias[col];
        #pragma unroll
        for (int mt = 0; mt < 2; mt++) {
            const int row = bn + warp_m * 32 + mt * 16 + gr;
            *(float2*)&Y[(size_t)row * D_MODEL + col] =
                make_float2(acc[mt][nt][0] + bv.x, acc[mt][nt][1] + bv.y);
            *(float2*)&Y[(size_t)(row + 8) * D_MODEL + col] =
                make_float2(acc[mt][nt][2] + bv.x, acc[mt][nt][3] + bv.y);
        }
    }
}

// ---------------------------------------------------------------------------
// Causal flash attention, fp16 mma. Br=128, 128 threads = 4 warps.
// NEW: 32 q-rows per warp (two 16-row A-frag streams mt=0,1): K/V B-fragments
// are loaded ONCE per warp and feed BOTH streams -> smem frag traffic per
// FLOP halves vs 8-warp/16-row layout (the crossbar was the binding limit).
// 6-stage 64-col K/V ring processed in pairs; tensor-core l column; Q overlay.
// ---------------------------------------------------------------------------
#define ABR   128
#define ABC   64
#define APAD  72
#define KVSTR (ABC * APAD)               // 4608 halves per 64-row stage
#define NSTG  6
#define ATTN_SMEM (NSTG * 2 * KVSTR * 2) // 110592 B
#define QSCALE (0.125f * 1.44269504088896340736f)

__global__ __launch_bounds__(128, 2)
void attn_h()
{
    extern __shared__ __align__(16) char dsm[];
    __half* Ksm = (__half*)dsm;               // [6][64][APAD]
    __half* Vsm = Ksm + NSTG * KVSTR;         // [6][64][APAD]
    __half* Qs  = Ksm + 4 * KVSTR;            // overlay: K stages 4,5 (128 rows)

    const int bh = blockIdx.y;
    const int qb = (int)gridDim.x - 1 - (int)blockIdx.x;   // heavy blocks first
    const int q0 = qb * ABR;

    const __half* Qg = g_qh + (size_t)bh * SEQ * DHEAD;
    const __half* Kg = g_kh + (size_t)bh * SEQ * DHEAD;
    const __half* Vg = g_vh + (size_t)bh * SEQ * DHEAD;

    const int tid  = threadIdx.x;
    const int lane = tid & 31;
    const int wid  = tid >> 5;     // 0..3
    const int gr   = lane >> 2;
    const int t4   = lane & 3;
    const int r0   = wid * 32;     // warp owns q rows [r0, r0+32)

    const int lr   = lane & 7;
    const int arow = ((lane >> 3) & 1) * 8 + lr;
    const int acol = ((lane >> 4) & 1) * 8;
    const int brow = ((lane >> 4) & 1) * 8 + lr;   // K B-frags
    const int bcol = ((lane >> 3) & 1) * 8;
    const int trow = ((lane >> 3) & 1) * 8 + lr;   // V B-frags (trans)
    const int tcol = ((lane >> 4) & 1) * 8;

    // constant ones-column B fragment (l accumulation): B[k][n] = (n==0)
    const uint32_t lones = (gr == 0) ? 0x3C003C00u : 0u;
    const uint32_t lb[2] = { lones, lones };

    const int pmax = qb;   // pairs of 64-col tiles; tiles 2p, 2p+1

    auto issue1 = [&](int t) {
        const int s = t % NSTG;
        #pragma unroll
        for (int i = 0; i < 4; i++) {
            const int idx = tid + i * 128;     // 0..511
            const int r = idx >> 3, ch = idx & 7;
            const size_t goff = (size_t)(t * ABC + r) * DHEAD + ch * 8;
            cp16(Ksm + s * KVSTR + r * APAD + ch * 8, Kg + goff);
            cp16(Vsm + s * KVSTR + r * APAD + ch * 8, Vg + goff);
        }
    };

    issue1(0); issue1(1); cp_commit();                      // group 0
    if (pmax >= 1) { issue1(2); issue1(3); cp_commit(); }   // group 1

    // ---- stage Q (x log2e/8) into overlay region: 1 row per thread ----
    {
        const __half* src = Qg + (size_t)(q0 + tid) * DHEAD;
        #pragma unroll
        for (int i = 0; i < 8; i++) {
            uint4 u = *(const uint4*)(src + i * 8);
            const __half2* hp = (const __half2*)&u;
            uint4 o;
            uint32_t* op = (uint32_t*)&o;
            #pragma unroll
            for (int k = 0; k < 4; k++) {
                float2 f = __half22float2(hp[k]);
                op[k] = packh2(f.x * QSCALE, f.y * QSCALE);
            }
            *(uint4*)&Qs[tid * APAD + i * 8] = o;
        }
    }
    __syncthreads();

    uint32_t Qf[2][4][4];
    #pragma unroll
    for (int mt = 0; mt < 2; mt++)
        #pragma unroll
        for (int kk = 0; kk < 4; kk++)
            ldmx4(Qf[mt][kk], Qs + (r0 + mt*16 + arow) * APAD + kk * 16 + acol);
    // Qf resident; overlay region may be overwritten after the next barrier.

    float m[2][2] = { {-1e30f, -1e30f}, {-1e30f, -1e30f} };
    float oacc[2][9][4];              // [mt][8] = l column (P . ones)
    #pragma unroll
    for (int mt = 0; mt < 2; mt++)
        #pragma unroll
        for (int nt = 0; nt < 9; nt++)
            #pragma unroll
            for (int i = 0; i < 4; i++) oacc[mt][nt][i] = 0.f;

    for (int p = 0; p <= pmax; p++) {
        if (p < pmax) cp_wait<1>(); else cp_wait<0>();
        __syncthreads();
        // Stages (2p+4)%6,(2p+5)%6 were last read in pair p-1; all warps
        // passed the barrier above => safe to refill.
        if (p + 2 <= pmax) { issue1(2*p + 4); issue1(2*p + 5); cp_commit(); }

        const bool needmask = (p == pmax);

        #pragma unroll
        for (int hh = 0; hh < 2; hh++) {
            const int t = 2*p + hh;
            const __half* Ks = Ksm + (t % NSTG) * KVSTR;
            const __half* Vs = Vsm + (t % NSTG) * KVSTR;
            const int kv0 = t * ABC;

            // ---- S = Qs * K^T : one K-frag load feeds both mt streams ----
            float sacc[2][8][4];
            #pragma unroll
            for (int mt = 0; mt < 2; mt++)
                #pragma unroll
                for (int nt = 0; nt < 8; nt++)
                    #pragma unroll
                    for (int i = 0; i < 4; i++) sacc[mt][nt][i] = 0.f;

            #pragma unroll
            for (int kk = 0; kk < 4; kk++) {
                #pragma unroll
                for (int np = 0; np < 4; np++) {
                    uint32_t bb[4];
                    ldmx4(bb, Ks + (np*16 + brow) * APAD + kk*16 + bcol);
                    #pragma unroll
                    for (int mt = 0; mt < 2; mt++) {
                        mma_f16(sacc[mt][2*np    ], Qf[mt][kk], &bb[0]);
                        mma_f16(sacc[mt][2*np + 1], Qf[mt][kk], &bb[2]);
                    }
                }
            }

            // ---- causal mask (last pair only) ----
            if (needmask) {
                #pragma unroll
                for (int mt = 0; mt < 2; mt++) {
                    const int ra = q0 + r0 + mt*16 + gr;
                    const int rb = ra + 8;
                    #pragma unroll
                    for (int nt = 0; nt < 8; nt++) {
                        const int col0 = kv0 + nt*8 + 2*t4;
                        if (col0     > ra) sacc[mt][nt][0] = -1e30f;
                        if (col0 + 1 > ra) sacc[mt][nt][1] = -1e30f;
                        if (col0     > rb) sacc[mt][nt][2] = -1e30f;
                        if (col0 + 1 > rb) sacc[mt][nt][3] = -1e30f;
                    }
                }
            }

            // ---- online softmax, log2 domain (4 rows per thread) ----
            float mx[2][2];
            #pragma unroll
            for (int mt = 0; mt < 2; mt++) {
                float a = -1e30f, bmx = -1e30f;
                #pragma unroll
                for (int nt = 0; nt < 8; nt++) {
                    a   = fmaxf(a,   fmaxf(sacc[mt][nt][0], sacc[mt][nt][1]));
                    bmx = fmaxf(bmx, fmaxf(sacc[mt][nt][2], sacc[mt][nt][3]));
                }
                a   = fmaxf(a,   __shfl_xor_sync(0xffffffffu, a,   1));
                a   = fmaxf(a,   __shfl_xor_sync(0xffffffffu, a,   2));
                bmx = fmaxf(bmx, __shfl_xor_sync(0xffffffffu, bmx, 1));
                bmx = fmaxf(bmx, __shfl_xor_sync(0xffffffffu, bmx, 2));
                mx[mt][0] = fmaxf(m[mt][0], a);
                mx[mt][1] = fmaxf(m[mt][1], bmx);
            }
            const bool changed = (mx[0][0] > m[0][0]) || (mx[0][1] > m[0][1]) ||
                                 (mx[1][0] > m[1][0]) || (mx[1][1] > m[1][1]);
            if (__any_sync(0xffffffffu, changed)) {
                #pragma unroll
                for (int mt = 0; mt < 2; mt++) {
                    const float a0 = ex2f(m[mt][0] - mx[mt][0]);
                    const float a1 = ex2f(m[mt][1] - mx[mt][1]);
                    #pragma unroll
                    for (int nt = 0; nt < 9; nt++) {
                        oacc[mt][nt][0] *= a0; oacc[mt][nt][1] *= a0;
                        oacc[mt][nt][2] *= a1; oacc[mt][nt][3] *= a1;
                    }
                    m[mt][0] = mx[mt][0]; m[mt][1] = mx[mt][1];
                }
            }

            #pragma unroll
            for (int mt = 0; mt < 2; mt++)
                #pragma unroll
                for (int nt = 0; nt < 8; nt++) {
                    sacc[mt][nt][0] = ex2f(sacc[mt][nt][0] - m[mt][0]);
                    sacc[mt][nt][1] = ex2f(sacc[mt][nt][1] - m[mt][0]);
                    sacc[mt][nt][2] = ex2f(sacc[mt][nt][2] - m[mt][1]);
                    sacc[mt][nt][3] = ex2f(sacc[mt][nt][3] - m[mt][1]);
                }

            // ---- O += P * V ; one V-frag load feeds both mt streams ----
            #pragma unroll
            for (int kk = 0; kk < 4; kk++) {
                uint32_t pf[2][4];
                #pragma unroll
                for (int mt = 0; mt < 2; mt++) {
                    pf[mt][0] = packh2(sacc[mt][2*kk    ][0], sacc[mt][2*kk    ][1]);
                    pf[mt][1] = packh2(sacc[mt][2*kk    ][2], sacc[mt][2*kk    ][3]);
                    pf[mt][2] = packh2(sacc[mt][2*kk + 1][0], sacc[mt][2*kk + 1][1]);
                    pf[mt][3] = packh2(sacc[mt][2*kk + 1][2], sacc[mt][2*kk + 1][3]);
                }
                #pragma unroll
                for (int np = 0; np < 4; np++) {
                    uint32_t bt[4];
                    ldmx4t(bt, Vs + (kk*16 + trow) * APAD + np*16 + tcol);
                    #pragma unroll
                    for (int mt = 0; mt < 2; mt++) {
                        mma_f16(oacc[mt][2*np    ], pf[mt], &bt[0]);
                        mma_f16(oacc[mt][2*np + 1], pf[mt], &bt[2]);
                    }
                }
                mma_f16(oacc[0][8], pf[0], lb);
                mma_f16(oacc[1][8], pf[1], lb);
            }
        }
    }

    // ---- l in oacc[mt][8]: col 0 -> t4==0's c[0]/c[2]; broadcast; write ----
    const int qbase = lane & ~3;
    const int b = bh >> 4, h = bh & 15;
    #pragma unroll
    for (int mt = 0; mt < 2; mt++) {
        const float inv0 = 1.f / __shfl_sync(0xffffffffu, oacc[mt][8][0], qbase);
        const float inv1 = 1.f / __shfl_sync(0xffffffffu, oacc[mt][8][2], qbase);
        const int ra = q0 + r0 + mt*16 + gr;
        const int rb = ra + 8;
        #pragma unroll
        for (int nt = 0; nt < 8; nt++) {
            const int col = h * DHEAD + nt*8 + 2*t4;
            *(uint32_t*)&g_ah[((size_t)(b*SEQ + ra)) * D_MODEL + col] =
                packh2(oacc[mt][nt][0] * inv0, oacc[mt][nt][1] * inv0);
            *(uint32_t*)&g_ah[((size_t)(b*SEQ + rb)) * D_MODEL + col] =
                packh2(oacc[mt][nt][2] * inv1, oacc[mt][nt][3] * inv1);
        }
    }
}

// ---------------------------------------------------------------------------
extern "C" void kernel_launch(void* const* d_in, const int* in_sizes, int n_in,
                              void* d_out, int out_size)
{
    const float* x  = (const float*)d_in[0];
    const float* Wq = (const float*)d_in[1];
    const float* bq = (const float*)d_in[2];
    const float* Wk = (const float*)d_in[3];
    const float* bk = (const float*)d_in[4];
    const float* Wv = (const float*)d_in[5];
    const float* bv = (const float*)d_in[6];
    const float* Wo = (const float*)d_in[7];
    const float* bo = (const float*)d_in[8];

    __half *xh, *wqh, *wkh, *wvh, *woh, *ah;
    cudaGetSymbolAddress((void**)&xh,  g_xh);
    cudaGetSymbolAddress((void**)&wqh, g_wqh);
    cudaGetSymbolAddress((void**)&wkh, g_wkh);
    cudaGetSymbolAddress((void**)&wvh, g_wvh);
    cudaGetSymbolAddress((void**)&woh, g_woh);
    cudaGetSymbolAddress((void**)&ah,  g_ah);

    // fused fp32 -> fp16 pre-pass (1 launch)
    cvt_all<<<NCVT/256, 256>>>(x, Wq, Wk, Wv, Wo);

    cudaFuncSetAttribute(gemm_qkv,
                         cudaFuncAttributeMaxDynamicSharedMemorySize, GEMM_SMEM);
    cudaFuncSetAttribute(gemm_out,
                         cudaFuncAttributeMaxDynamicSharedMemorySize, OUT_SMEM);
    cudaFuncSetAttribute(attn_h,
                         cudaFuncAttributeMaxDynamicSharedMemorySize, ATTN_SMEM);

    // fused QKV projection (1 launch, z selects head)
    gemm_qkv<<<dim3(D_MODEL/128, NTOK/128, 3), 128, GEMM_SMEM>>>(
        xh, wqh, bq, wkh, bk, wvh, bv);

    attn_h<<<dim3(SEQ/ABR, BATCH*NHEAD), 128, ATTN_SMEM>>>();

    // output projection
    gemm_out<<<dim3(D_MODEL/128, NTOK/64), 128, OUT_SMEM>>>(
        ah, woh, bo, (float*)d_out);
}

// round 16
// speedup vs baseline: 17.3746x; 1.0248x over previous
#include <cuda_runtime.h>
#include <cuda_fp16.h>
#include <math.h>
#include <cstdint>

#define D_MODEL 1024
#define NHEAD   16
#define DHEAD   64
#define BATCH   4
#define SEQ     2048
#define NTOK    (BATCH*SEQ)   // 8192
#define KDIM    1024

// ---------------------------------------------------------------------------
// fp16 scratch (allocation-free rule: __device__ globals)
// ---------------------------------------------------------------------------
__device__ __half g_xh[(size_t)NTOK*KDIM];
__device__ __half g_wqh[(size_t)KDIM*D_MODEL];
__device__ __half g_wkh[(size_t)KDIM*D_MODEL];
__device__ __half g_wvh[(size_t)KDIM*D_MODEL];
__device__ __half g_woh[(size_t)KDIM*D_MODEL];
__device__ __half g_qh[(size_t)BATCH*NHEAD*SEQ*DHEAD];   // [B,H,S,Dh]
__device__ __half g_kh[(size_t)BATCH*NHEAD*SEQ*DHEAD];
__device__ __half g_vh[(size_t)BATCH*NHEAD*SEQ*DHEAD];
__device__ __half g_ah[(size_t)NTOK*D_MODEL];            // [B,S,D]

// ---------------------------------------------------------------------------
// helpers
// ---------------------------------------------------------------------------
__device__ __forceinline__ uint32_t packh2(float a, float b) {
    __half2 h = __floats2half2_rn(a, b);
    return *reinterpret_cast<uint32_t*>(&h);
}
__device__ __forceinline__ float ex2f(float x) {
    float y;
    asm("ex2.approx.ftz.f32 %0, %1;" : "=f"(y) : "f"(x));
    return y;
}
__device__ __forceinline__ void mma_f16(float* c, const uint32_t* a, const uint32_t* b) {
    asm volatile(
        "mma.sync.aligned.m16n8k16.row.col.f32.f16.f16.f32 "
        "{%0,%1,%2,%3}, {%4,%5,%6,%7}, {%8,%9}, {%0,%1,%2,%3};"
        : "+f"(c[0]), "+f"(c[1]), "+f"(c[2]), "+f"(c[3])
        : "r"(a[0]), "r"(a[1]), "r"(a[2]), "r"(a[3]), "r"(b[0]), "r"(b[1]));
}
__device__ __forceinline__ void ldmx4(uint32_t* r, const void* p) {
    uint32_t a = (uint32_t)__cvta_generic_to_shared(p);
    asm volatile("ldmatrix.sync.aligned.m8n8.x4.shared.b16 {%0,%1,%2,%3}, [%4];"
                 : "=r"(r[0]), "=r"(r[1]), "=r"(r[2]), "=r"(r[3]) : "r"(a));
}
__device__ __forceinline__ void ldmx4t(uint32_t* r, const void* p) {
    uint32_t a = (uint32_t)__cvta_generic_to_shared(p);
    asm volatile("ldmatrix.sync.aligned.m8n8.x4.trans.shared.b16 {%0,%1,%2,%3}, [%4];"
                 : "=r"(r[0]), "=r"(r[1]), "=r"(r[2]), "=r"(r[3]) : "r"(a));
}
__device__ __forceinline__ void cp16(void* s, const void* g) {
    uint32_t a = (uint32_t)__cvta_generic_to_shared(s);
    asm volatile("cp.async.cg.shared.global [%0], [%1], 16;" :: "r"(a), "l"(g) : "memory");
}
__device__ __forceinline__ void cp_commit() {
    asm volatile("cp.async.commit_group;" ::: "memory");
}
template<int N>
__device__ __forceinline__ void cp_wait() {
    asm volatile("cp.async.wait_group %0;" :: "n"(N) : "memory");
}

// ---------------------------------------------------------------------------
// fused fp32 -> fp16 conversion
// ---------------------------------------------------------------------------
#define NX8 (NTOK * KDIM / 8)       // 1048576 = 2^20
#define NW8 (KDIM * D_MODEL / 8)    // 131072  = 2^17
#define NCVT (NX8 + 4 * NW8)        // 1572864

__global__ __launch_bounds__(256)
void cvt_all(const float* __restrict__ x,
             const float* __restrict__ w0, const float* __restrict__ w1,
             const float* __restrict__ w2, const float* __restrict__ w3)
{
    const int i = blockIdx.x * 256 + threadIdx.x;
    const float* src;
    __half* dst;
    int off;
    if (i < NX8) {
        src = x; dst = g_xh; off = i;
    } else {
        const int t = i - NX8;
        const int w = t >> 17;            // NW8 = 2^17
        off = t & (NW8 - 1);
        switch (w) {
            case 0:  src = w0; dst = g_wqh; break;
            case 1:  src = w1; dst = g_wkh; break;
            case 2:  src = w2; dst = g_wvh; break;
            default: src = w3; dst = g_woh; break;
        }
    }
    float4 a = ((const float4*)src)[2*off];
    float4 b = ((const float4*)src)[2*off + 1];
    uint4 o;
    o.x = packh2(a.x, a.y);  o.y = packh2(a.z, a.w);
    o.z = packh2(b.x, b.y);  o.w = packh2(b.z, b.w);
    ((uint4*)dst)[off] = o;
}

// ---------------------------------------------------------------------------
// QKV fp16 GEMM (NT), cp.async 3-stage, CTA 128x128, 128 thr, warp 64x64.
// ---------------------------------------------------------------------------
#define GBK   32
#define GKCH  (KDIM / GBK)      // 32
#define GPAD  40                // halves per smem row
#define GSTR  (128 * GPAD)      // halves per stage per operand
#define GEMM_SMEM (3 * 2 * GSTR * 2)   // 61440 B

__global__ __launch_bounds__(128, 3)
void gemm_qkv(const __half* __restrict__ A,
              const __half* __restrict__ W0, const float* __restrict__ b0,
              const __half* __restrict__ W1, const float* __restrict__ b1,
              const __half* __restrict__ W2, const float* __restrict__ b2)
{
    extern __shared__ __align__(16) char dsm[];
    __half* As = (__half*)dsm;            // [3][128][GPAD]
    __half* Ws = As + 3 * GSTR;           // [3][128][GPAD]

    const __half* Wsel = W0;
    const float*  bsel = b0;
    __half* Hout = g_qh;
    if (blockIdx.z == 1)      { Wsel = W1; bsel = b1; Hout = g_kh; }
    else if (blockIdx.z == 2) { Wsel = W2; bsel = b2; Hout = g_vh; }

    const int tid    = threadIdx.x;
    const int lane   = tid & 31;
    const int wid    = tid >> 5;
    const int warp_m = wid & 1;
    const int warp_n = wid >> 1;
    const int gr     = lane >> 2;
    const int t4     = lane & 3;

    const int lr   = lane & 7;
    const int arow = ((lane >> 3) & 1) * 8 + lr;
    const int acol = ((lane >> 4) & 1) * 8;
    const int brow = ((lane >> 4) & 1) * 8 + lr;
    const int bcol = ((lane >> 3) & 1) * 8;

    const int bn = blockIdx.y * 128;
    const int bm = blockIdx.x * 128;

    const __half* Ag = A + (size_t)bn * KDIM;
    const __half* Wg = Wsel + (size_t)bm * KDIM;

    auto issue = [&](int c, int s) {
        __half* ab = As + s * GSTR;
        __half* wb = Ws + s * GSTR;
        #pragma unroll
        for (int i = 0; i < 4; i++) {
            const int idx = tid + i * 128;        // 0..511
            const int r = idx >> 2, ch = idx & 3;
            cp16(ab + r * GPAD + ch * 8, Ag + (size_t)r * KDIM + c * GBK + ch * 8);
            cp16(wb + r * GPAD + ch * 8, Wg + (size_t)r * KDIM + c * GBK + ch * 8);
        }
    };

    float acc[4][8][4];
    #pragma unroll
    for (int mt = 0; mt < 4; mt++)
        #pragma unroll
        for (int nt = 0; nt < 8; nt++)
            #pragma unroll
            for (int i = 0; i < 4; i++) acc[mt][nt][i] = 0.f;

    issue(0, 0); cp_commit();
    issue(1, 1); cp_commit();

    for (int c = 0; c < GKCH; c++) {
        if (c == GKCH - 1) cp_wait<0>(); else cp_wait<1>();
        __syncthreads();
        if (c + 2 < GKCH) { issue(c + 2, (c + 2) % 3); cp_commit(); }

        const int s = c % 3;
        const __half* Ab = As + s * GSTR + (warp_m * 64) * GPAD;
        const __half* Wb = Ws + s * GSTR + (warp_n * 64) * GPAD;
        #pragma unroll
        for (int kk = 0; kk < 2; kk++) {
            const int k0 = kk * 16;
            uint32_t af[4][4], bb[4][4];
            #pragma unroll
            for (int mt = 0; mt < 4; mt++)
                ldmx4(af[mt], Ab + (mt*16 + arow) * GPAD + k0 + acol);
            #pragma unroll
            for (int np = 0; np < 4; np++)
                ldmx4(bb[np], Wb + (np*16 + brow) * GPAD + k0 + bcol);
            #pragma unroll
            for (int mt = 0; mt < 4; mt++)
                #pragma unroll
                for (int np = 0; np < 4; np++) {
                    mma_f16(acc[mt][2*np    ], af[mt], &bb[np][0]);
                    mma_f16(acc[mt][2*np + 1], af[mt], &bb[np][2]);
                }
        }
    }

    #pragma unroll
    for (int nt = 0; nt < 8; nt++) {
        const int col = bm + warp_n * 64 + nt * 8 + t4 * 2;
        const float2 bv = *(const float2*)&bsel[col];
        #pragma unroll
        for (int mt = 0; mt < 4; mt++) {
            const int row = bn + warp_m * 64 + mt * 16 + gr;
            const int h = col / DHEAD, d = col % DHEAD;
            const int bb0 = row / SEQ, s0 = row % SEQ;
            const int bb1 = (row + 8) / SEQ, s1 = (row + 8) % SEQ;
            *(uint32_t*)&Hout[(((size_t)(bb0*NHEAD + h)*SEQ + s0)*DHEAD) + d] =
                packh2(acc[mt][nt][0] + bv.x, acc[mt][nt][1] + bv.y);
            *(uint32_t*)&Hout[(((size_t)(bb1*NHEAD + h)*SEQ + s1)*DHEAD) + d] =
                packh2(acc[mt][nt][2] + bv.x, acc[mt][nt][3] + bv.y);
        }
    }
}

// ---------------------------------------------------------------------------
// Output projection GEMM: CTA 64x128, 128 thr, 3-stage, 4 CTAs/SM.
// ---------------------------------------------------------------------------
#define OSTR_A (64 * GPAD)
#define OSTR   (192 * GPAD)
#define OUT_SMEM (3 * OSTR * 2)          // 46080 B

__global__ __launch_bounds__(128, 4)
void gemm_out(const __half* __restrict__ A, const __half* __restrict__ W,
              const float* __restrict__ bias, float* __restrict__ Y)
{
    extern __shared__ __align__(16) char dsm[];
    __half* Sm = (__half*)dsm;

    const int tid    = threadIdx.x;
    const int lane   = tid & 31;
    const int wid    = tid >> 5;
    const int warp_m = wid & 1;
    const int warp_n = wid >> 1;
    const int gr     = lane >> 2;
    const int t4     = lane & 3;

    const int lr   = lane & 7;
    const int arow = ((lane >> 3) & 1) * 8 + lr;
    const int acol = ((lane >> 4) & 1) * 8;
    const int brow = ((lane >> 4) & 1) * 8 + lr;
    const int bcol = ((lane >> 3) & 1) * 8;

    const int bn = blockIdx.y * 64;
    const int bm = blockIdx.x * 128;

    const __half* Ag = A + (size_t)bn * KDIM;
    const __half* Wg = W + (size_t)bm * KDIM;

    auto issue = [&](int c, int s) {
        __half* base = Sm + s * OSTR;
        #pragma unroll
        for (int i = 0; i < 6; i++) {
            const int idx = tid + i * 128;        // 0..767
            if (idx < 256) {
                const int r = idx >> 2, ch = idx & 3;
                cp16(base + r * GPAD + ch * 8, Ag + (size_t)r * KDIM + c * GBK + ch * 8);
            } else {
                const int j = idx - 256;
                const int r = j >> 2, ch = j & 3;
                cp16(base + OSTR_A + r * GPAD + ch * 8, Wg + (size_t)r * KDIM + c * GBK + ch * 8);
            }
        }
    };

    float acc[2][8][4];
    #pragma unroll
    for (int mt = 0; mt < 2; mt++)
        #pragma unroll
        for (int nt = 0; nt < 8; nt++)
            #pragma unroll
            for (int i = 0; i < 4; i++) acc[mt][nt][i] = 0.f;

    issue(0, 0); cp_commit();
    issue(1, 1); cp_commit();

    for (int c = 0; c < GKCH; c++) {
        if (c == GKCH - 1) cp_wait<0>(); else cp_wait<1>();
        __syncthreads();
        if (c + 2 < GKCH) { issue(c + 2, (c + 2) % 3); cp_commit(); }

        const int s = c % 3;
        const __half* Ab = Sm + s * OSTR + (warp_m * 32) * GPAD;
        const __half* Wb = Sm + s * OSTR + OSTR_A + (warp_n * 64) * GPAD;
        #pragma unroll
        for (int kk = 0; kk < 2; kk++) {
            const int k0 = kk * 16;
            uint32_t af[2][4], bb[4][4];
            #pragma unroll
            for (int mt = 0; mt < 2; mt++)
                ldmx4(af[mt], Ab + (mt*16 + arow) * GPAD + k0 + acol);
            #pragma unroll
            for (int np = 0; np < 4; np++)
                ldmx4(bb[np], Wb + (np*16 + brow) * GPAD + k0 + bcol);
            #pragma unroll
            for (int mt = 0; mt < 2; mt++)
                #pragma unroll
                for (int np = 0; np < 4; np++) {
                    mma_f16(acc[mt][2*np    ], af[mt], &bb[np][0]);
                    mma_f16(acc[mt][2*np + 1], af[mt], &bb[np][2]);
                }
        }
    }

    #pragma unroll
    for (int nt = 0; nt < 8; nt++) {
        const int col = bm + warp_n * 64 + nt * 8 + t4 * 2;
        const float2 bv = *(const float2*)&bias[col];
        #pragma unroll
        for (int mt = 0; mt < 2; mt++) {
            const int row = bn + warp_m * 32 + mt * 16 + gr;
            *(float2*)&Y[(size_t)row * D_MODEL + col] =
                make_float2(acc[mt][nt][0] + bv.x, acc[mt][nt][1] + bv.y);
            *(float2*)&Y[(size_t)(row + 8) * D_MODEL + col] =
                make_float2(acc[mt][nt][2] + bv.x, acc[mt][nt][3] + bv.y);
        }
    }
}

// ---------------------------------------------------------------------------
// Causal flash attention, fp16 mma. PERSISTENT: grid = 296 slots; each CTA
// loops over tiles g = bid + k*296, qb = 15 - (g>>6) (qb-major: heavy tiles
// spread evenly across slots -> per-CTA work ~= constant, no wave tails).
// 128 threads, 32 q-rows/warp (2 mt streams); 6-stage paired K/V ring;
// tensor-core l column; Q staged in K-stage-4/5 overlay.
// ---------------------------------------------------------------------------
#define ABR   128
#define ABC   64
#define APAD  72
#define KVSTR (ABC * APAD)               // 4608 halves per 64-row stage
#define NSTG  6
#define ATTN_SMEM (NSTG * 2 * KVSTR * 2) // 110592 B
#define QSCALE (0.125f * 1.44269504088896340736f)
#define NQB   (SEQ / ABR)                // 16
#define NTILE (NQB * BATCH * NHEAD)      // 1024
#define NSLOT 296                        // 148 SMs * 2 CTAs

__global__ __launch_bounds__(128, 2)
void attn_h()
{
    extern __shared__ __align__(16) char dsm[];
    __half* Ksm = (__half*)dsm;               // [6][64][APAD]
    __half* Vsm = Ksm + NSTG * KVSTR;         // [6][64][APAD]
    __half* Qs  = Ksm + 4 * KVSTR;            // overlay: K stages 4,5 (128 rows)

    const int tid  = threadIdx.x;
    const int lane = tid & 31;
    const int wid  = tid >> 5;     // 0..3
    const int gr   = lane >> 2;
    const int t4   = lane & 3;
    const int r0   = wid * 32;     // warp owns q rows [r0, r0+32)

    const int lr   = lane & 7;
    const int arow = ((lane >> 3) & 1) * 8 + lr;
    const int acol = ((lane >> 4) & 1) * 8;
    const int brow = ((lane >> 4) & 1) * 8 + lr;   // K B-frags
    const int bcol = ((lane >> 3) & 1) * 8;
    const int trow = ((lane >> 3) & 1) * 8 + lr;   // V B-frags (trans)
    const int tcol = ((lane >> 4) & 1) * 8;

    // constant ones-column B fragment (l accumulation): B[k][n] = (n==0)
    const uint32_t lones = (gr == 0) ? 0x3C003C00u : 0u;
    const uint32_t lb[2] = { lones, lones };

    for (int g = blockIdx.x; g < NTILE; g += NSLOT) {
        const int qb = (NQB - 1) - (g >> 6);   // qb-major, heavy first
        const int bh = g & 63;
        const int q0 = qb * ABR;

        const __half* Qg = g_qh + (size_t)bh * SEQ * DHEAD;
        const __half* Kg = g_kh + (size_t)bh * SEQ * DHEAD;
        const __half* Vg = g_vh + (size_t)bh * SEQ * DHEAD;

        const int pmax = qb;   // pairs of 64-col tiles; tiles 2p, 2p+1

        auto issue1 = [&](int t) {
            const int s = t % NSTG;
            #pragma unroll
            for (int i = 0; i < 4; i++) {
                const int idx = tid + i * 128;     // 0..511
                const int r = idx >> 3, ch = idx & 7;
                const size_t goff = (size_t)(t * ABC + r) * DHEAD + ch * 8;
                cp16(Ksm + s * KVSTR + r * APAD + ch * 8, Kg + goff);
                cp16(Vsm + s * KVSTR + r * APAD + ch * 8, Vg + goff);
            }
        };

        // All prior-tile smem reads complete before refilling any stage
        // (previous tile ended with cp_wait<0>; epilogue touches regs only).
        __syncthreads();

        issue1(0); issue1(1); cp_commit();                      // group 0
        if (pmax >= 1) { issue1(2); issue1(3); cp_commit(); }   // group 1

        // ---- stage Q (x log2e/8) into overlay region: 1 row per thread ----
        {
            const __half* src = Qg + (size_t)(q0 + tid) * DHEAD;
            #pragma unroll
            for (int i = 0; i < 8; i++) {
                uint4 u = *(const uint4*)(src + i * 8);
                const __half2* hp = (const __half2*)&u;
                uint4 o;
                uint32_t* op = (uint32_t*)&o;
                #pragma unroll
                for (int k = 0; k < 4; k++) {
                    float2 f = __half22float2(hp[k]);
                    op[k] = packh2(f.x * QSCALE, f.y * QSCALE);
                }
                *(uint4*)&Qs[tid * APAD + i * 8] = o;
            }
        }
        __syncthreads();

        uint32_t Qf[2][4][4];
        #pragma unroll
        for (int mt = 0; mt < 2; mt++)
            #pragma unroll
            for (int kk = 0; kk < 4; kk++)
                ldmx4(Qf[mt][kk], Qs + (r0 + mt*16 + arow) * APAD + kk * 16 + acol);
        // Qf resident; overlay may be overwritten after the next barrier.

        float m[2][2] = { {-1e30f, -1e30f}, {-1e30f, -1e30f} };
        float oacc[2][9][4];              // [mt][8] = l column (P . ones)
        #pragma unroll
        for (int mt = 0; mt < 2; mt++)
            #pragma unroll
            for (int nt = 0; nt < 9; nt++)
                #pragma unroll
                for (int i = 0; i < 4; i++) oacc[mt][nt][i] = 0.f;

        for (int p = 0; p <= pmax; p++) {
            if (p < pmax) cp_wait<1>(); else cp_wait<0>();
            __syncthreads();
            // Stages (2p+4)%6,(2p+5)%6 last read in pair p-1; all warps
            // passed the barrier above => safe to refill.
            if (p + 2 <= pmax) { issue1(2*p + 4); issue1(2*p + 5); cp_commit(); }

            const bool needmask = (p == pmax);

            #pragma unroll
            for (int hh = 0; hh < 2; hh++) {
                const int t = 2*p + hh;
                const __half* Ks = Ksm + (t % NSTG) * KVSTR;
                const __half* Vs = Vsm + (t % NSTG) * KVSTR;
                const int kv0 = t * ABC;

                // ---- S = Qs * K^T : one K-frag load feeds both streams ----
                float sacc[2][8][4];
                #pragma unroll
                for (int mt = 0; mt < 2; mt++)
                    #pragma unroll
                    for (int nt = 0; nt < 8; nt++)
                        #pragma unroll
                        for (int i = 0; i < 4; i++) sacc[mt][nt][i] = 0.f;

                #pragma unroll
                for (int kk = 0; kk < 4; kk++) {
                    #pragma unroll
                    for (int np = 0; np < 4; np++) {
                        uint32_t bb[4];
                        ldmx4(bb, Ks + (np*16 + brow) * APAD + kk*16 + bcol);
                        #pragma unroll
                        for (int mt = 0; mt < 2; mt++) {
                            mma_f16(sacc[mt][2*np    ], Qf[mt][kk], &bb[0]);
                            mma_f16(sacc[mt][2*np + 1], Qf[mt][kk], &bb[2]);
                        }
                    }
                }

                // ---- causal mask (last pair only) ----
                if (needmask) {
                    #pragma unroll
                    for (int mt = 0; mt < 2; mt++) {
                        const int ra = q0 + r0 + mt*16 + gr;
                        const int rb = ra + 8;
                        #pragma unroll
                        for (int nt = 0; nt < 8; nt++) {
                            const int col0 = kv0 + nt*8 + 2*t4;
                            if (col0     > ra) sacc[mt][nt][0] = -1e30f;
                            if (col0 + 1 > ra) sacc[mt][nt][1] = -1e30f;
                            if (col0     > rb) sacc[mt][nt][2] = -1e30f;
                            if (col0 + 1 > rb) sacc[mt][nt][3] = -1e30f;
                        }
                    }
                }

                // ---- online softmax, log2 domain (4 rows per thread) ----
                float mx[2][2];
                #pragma unroll
                for (int mt = 0; mt < 2; mt++) {
                    float a = -1e30f, bmx = -1e30f;
                    #pragma unroll
                    for (int nt = 0; nt < 8; nt++) {
                        a   = fmaxf(a,   fmaxf(sacc[mt][nt][0], sacc[mt][nt][1]));
                        bmx = fmaxf(bmx, fmaxf(sacc[mt][nt][2], sacc[mt][nt][3]));
                    }
                    a   = fmaxf(a,   __shfl_xor_sync(0xffffffffu, a,   1));
                    a   = fmaxf(a,   __shfl_xor_sync(0xffffffffu, a,   2));
                    bmx = fmaxf(bmx, __shfl_xor_sync(0xffffffffu, bmx, 1));
                    bmx = fmaxf(bmx, __shfl_xor_sync(0xffffffffu, bmx, 2));
                    mx[mt][0] = fmaxf(m[mt][0], a);
                    mx[mt][1] = fmaxf(m[mt][1], bmx);
                }
                const bool changed = (mx[0][0] > m[0][0]) || (mx[0][1] > m[0][1]) ||
                                     (mx[1][0] > m[1][0]) || (mx[1][1] > m[1][1]);
                if (__any_sync(0xffffffffu, changed)) {
                    #pragma unroll
                    for (int mt = 0; mt < 2; mt++) {
                        const float a0 = ex2f(m[mt][0] - mx[mt][0]);
                        const float a1 = ex2f(m[mt][1] - mx[mt][1]);
                        #pragma unroll
                        for (int nt = 0; nt < 9; nt++) {
                            oacc[mt][nt][0] *= a0; oacc[mt][nt][1] *= a0;
                            oacc[mt][nt][2] *= a1; oacc[mt][nt][3] *= a1;
                        }
                        m[mt][0] = mx[mt][0]; m[mt][1] = mx[mt][1];
                    }
                }

                #pragma unroll
                for (int mt = 0; mt < 2; mt++)
                    #pragma unroll
                    for (int nt = 0; nt < 8; nt++) {
                        sacc[mt][nt][0] = ex2f(sacc[mt][nt][0] - m[mt][0]);
                        sacc[mt][nt][1] = ex2f(sacc[mt][nt][1] - m[mt][0]);
                        sacc[mt][nt][2] = ex2f(sacc[mt][nt][2] - m[mt][1]);
                        sacc[mt][nt][3] = ex2f(sacc[mt][nt][3] - m[mt][1]);
                    }

                // ---- O += P * V ; one V-frag load feeds both streams ----
                #pragma unroll
                for (int kk = 0; kk < 4; kk++) {
                    uint32_t pf[2][4];
                    #pragma unroll
                    for (int mt = 0; mt < 2; mt++) {
                        pf[mt][0] = packh2(sacc[mt][2*kk    ][0], sacc[mt][2*kk    ][1]);
                        pf[mt][1] = packh2(sacc[mt][2*kk    ][2], sacc[mt][2*kk    ][3]);
                        pf[mt][2] = packh2(sacc[mt][2*kk + 1][0], sacc[mt][2*kk + 1][1]);
                        pf[mt][3] = packh2(sacc[mt][2*kk + 1][2], sacc[mt][2*kk + 1][3]);
                    }
                    #pragma unroll
                    for (int np = 0; np < 4; np++) {
                        uint32_t bt[4];
                        ldmx4t(bt, Vs + (kk*16 + trow) * APAD + np*16 + tcol);
                        #pragma unroll
                        for (int mt = 0; mt < 2; mt++) {
                            mma_f16(oacc[mt][2*np    ], pf[mt], &bt[0]);
                            mma_f16(oacc[mt][2*np + 1], pf[mt], &bt[2]);
                        }
                    }
                    mma_f16(oacc[0][8], pf[0], lb);
                    mma_f16(oacc[1][8], pf[1], lb);
                }
            }
        }

        // ---- l in oacc[mt][8]: broadcast; normalize; write ----
        const int qbase = lane & ~3;
        const int b = bh >> 4, h = bh & 15;
        #pragma unroll
        for (int mt = 0; mt < 2; mt++) {
            const float inv0 = 1.f / __shfl_sync(0xffffffffu, oacc[mt][8][0], qbase);
            const float inv1 = 1.f / __shfl_sync(0xffffffffu, oacc[mt][8][2], qbase);
            const int ra = q0 + r0 + mt*16 + gr;
            const int rb = ra + 8;
            #pragma unroll
            for (int nt = 0; nt < 8; nt++) {
                const int col = h * DHEAD + nt*8 + 2*t4;
                *(uint32_t*)&g_ah[((size_t)(b*SEQ + ra)) * D_MODEL + col] =
                    packh2(oacc[mt][nt][0] * inv0, oacc[mt][nt][1] * inv0);
                *(uint32_t*)&g_ah[((size_t)(b*SEQ + rb)) * D_MODEL + col] =
                    packh2(oacc[mt][nt][2] * inv1, oacc[mt][nt][3] * inv1);
            }
        }
    }
}

// ---------------------------------------------------------------------------
extern "C" void kernel_launch(void* const* d_in, const int* in_sizes, int n_in,
                              void* d_out, int out_size)
{
    const float* x  = (const float*)d_in[0];
    const float* Wq = (const float*)d_in[1];
    const float* bq = (const float*)d_in[2];
    const float* Wk = (const float*)d_in[3];
    const float* bk = (const float*)d_in[4];
    const float* Wv = (const float*)d_in[5];
    const float* bv = (const float*)d_in[6];
    const float* Wo = (const float*)d_in[7];
    const float* bo = (const float*)d_in[8];

    __half *xh, *wqh, *wkh, *wvh, *woh, *ah;
    cudaGetSymbolAddress((void**)&xh,  g_xh);
    cudaGetSymbolAddress((void**)&wqh, g_wqh);
    cudaGetSymbolAddress((void**)&wkh, g_wkh);
    cudaGetSymbolAddress((void**)&wvh, g_wvh);
    cudaGetSymbolAddress((void**)&woh, g_woh);
    cudaGetSymbolAddress((void**)&ah,  g_ah);

    // fused fp32 -> fp16 pre-pass (1 launch)
    cvt_all<<<NCVT/256, 256>>>(x, Wq, Wk, Wv, Wo);

    cudaFuncSetAttribute(gemm_qkv,
                         cudaFuncAttributeMaxDynamicSharedMemorySize, GEMM_SMEM);
    cudaFuncSetAttribute(gemm_out,
                         cudaFuncAttributeMaxDynamicSharedMemorySize, OUT_SMEM);
    cudaFuncSetAttribute(attn_h,
                         cudaFuncAttributeMaxDynamicSharedMemorySize, ATTN_SMEM);

    // fused QKV projection (1 launch, z selects head)
    gemm_qkv<<<dim3(D_MODEL/128, NTOK/128, 3), 128, GEMM_SMEM>>>(
        xh, wqh, bq, wkh, bk, wvh, bv);

    // persistent attention: one CTA per slot, qb-major static schedule
    attn_h<<<NSLOT, 128, ATTN_SMEM>>>();

    // output projection
    gemm_out<<<dim3(D_MODEL/128, NTOK/64), 128, OUT_SMEM>>>(
        ah, woh, bo, (float*)d_out);
}

// round 17
// speedup vs baseline: 17.7898x; 1.0239x over previous
#include <cuda_runtime.h>
#include <cuda_fp16.h>
#include <math.h>
#include <cstdint>

#define D_MODEL 1024
#define NHEAD   16
#define DHEAD   64
#define BATCH   4
#define SEQ     2048
#define NTOK    (BATCH*SEQ)   // 8192
#define KDIM    1024

// ---------------------------------------------------------------------------
// fp16 scratch (allocation-free rule: __device__ globals)
// ---------------------------------------------------------------------------
__device__ __half g_xh[(size_t)NTOK*KDIM];
__device__ __half g_wqh[(size_t)KDIM*D_MODEL];
__device__ __half g_wkh[(size_t)KDIM*D_MODEL];
__device__ __half g_wvh[(size_t)KDIM*D_MODEL];
__device__ __half g_woh[(size_t)KDIM*D_MODEL];
__device__ __half g_qh[(size_t)BATCH*NHEAD*SEQ*DHEAD];   // [B,H,S,Dh]
__device__ __half g_kh[(size_t)BATCH*NHEAD*SEQ*DHEAD];
__device__ __half g_vh[(size_t)BATCH*NHEAD*SEQ*DHEAD];
__device__ __half g_ah[(size_t)NTOK*D_MODEL];            // [B,S,D]

// ---------------------------------------------------------------------------
// helpers
// ---------------------------------------------------------------------------
__device__ __forceinline__ uint32_t packh2(float a, float b) {
    __half2 h = __floats2half2_rn(a, b);
    return *reinterpret_cast<uint32_t*>(&h);
}
__device__ __forceinline__ float ex2f(float x) {
    float y;
    asm("ex2.approx.ftz.f32 %0, %1;" : "=f"(y) : "f"(x));
    return y;
}
__device__ __forceinline__ void mma_f16(float* c, const uint32_t* a, const uint32_t* b) {
    asm volatile(
        "mma.sync.aligned.m16n8k16.row.col.f32.f16.f16.f32 "
        "{%0,%1,%2,%3}, {%4,%5,%6,%7}, {%8,%9}, {%0,%1,%2,%3};"
        : "+f"(c[0]), "+f"(c[1]), "+f"(c[2]), "+f"(c[3])
        : "r"(a[0]), "r"(a[1]), "r"(a[2]), "r"(a[3]), "r"(b[0]), "r"(b[1]));
}
__device__ __forceinline__ void ldmx4(uint32_t* r, const void* p) {
    uint32_t a = (uint32_t)__cvta_generic_to_shared(p);
    asm volatile("ldmatrix.sync.aligned.m8n8.x4.shared.b16 {%0,%1,%2,%3}, [%4];"
                 : "=r"(r[0]), "=r"(r[1]), "=r"(r[2]), "=r"(r[3]) : "r"(a));
}
__device__ __forceinline__ void ldmx4t(uint32_t* r, const void* p) {
    uint32_t a = (uint32_t)__cvta_generic_to_shared(p);
    asm volatile("ldmatrix.sync.aligned.m8n8.x4.trans.shared.b16 {%0,%1,%2,%3}, [%4];"
                 : "=r"(r[0]), "=r"(r[1]), "=r"(r[2]), "=r"(r[3]) : "r"(a));
}
__device__ __forceinline__ void cp16(void* s, const void* g) {
    uint32_t a = (uint32_t)__cvta_generic_to_shared(s);
    asm volatile("cp.async.cg.shared.global [%0], [%1], 16;" :: "r"(a), "l"(g) : "memory");
}
__device__ __forceinline__ void cp_commit() {
    asm volatile("cp.async.commit_group;" ::: "memory");
}
template<int N>
__device__ __forceinline__ void cp_wait() {
    asm volatile("cp.async.wait_group %0;" :: "n"(N) : "memory");
}

// ---------------------------------------------------------------------------
// fused fp32 -> fp16 conversion
// ---------------------------------------------------------------------------
#define NX8 (NTOK * KDIM / 8)       // 1048576 = 2^20
#define NW8 (KDIM * D_MODEL / 8)    // 131072  = 2^17
#define NCVT (NX8 + 4 * NW8)        // 1572864

__global__ __launch_bounds__(256)
void cvt_all(const float* __restrict__ x,
             const float* __restrict__ w0, const float* __restrict__ w1,
             const float* __restrict__ w2, const float* __restrict__ w3)
{
    const int i = blockIdx.x * 256 + threadIdx.x;
    const float* src;
    __half* dst;
    int off;
    if (i < NX8) {
        src = x; dst = g_xh; off = i;
    } else {
        const int t = i - NX8;
        const int w = t >> 17;            // NW8 = 2^17
        off = t & (NW8 - 1);
        switch (w) {
            case 0:  src = w0; dst = g_wqh; break;
            case 1:  src = w1; dst = g_wkh; break;
            case 2:  src = w2; dst = g_wvh; break;
            default: src = w3; dst = g_woh; break;
        }
    }
    float4 a = ((const float4*)src)[2*off];
    float4 b = ((const float4*)src)[2*off + 1];
    uint4 o;
    o.x = packh2(a.x, a.y);  o.y = packh2(a.z, a.w);
    o.z = packh2(b.x, b.y);  o.w = packh2(b.z, b.w);
    ((uint4*)dst)[off] = o;
}

// ---------------------------------------------------------------------------
// QKV fp16 GEMM (NT), cp.async 3-stage, CTA 128x128, 128 thr, warp 64x64.
// ---------------------------------------------------------------------------
#define GBK   32
#define GKCH  (KDIM / GBK)      // 32
#define GPAD  40                // halves per smem row
#define GSTR  (128 * GPAD)      // halves per stage per operand
#define GEMM_SMEM (3 * 2 * GSTR * 2)   // 61440 B

__global__ __launch_bounds__(128, 3)
void gemm_qkv(const __half* __restrict__ A,
              const __half* __restrict__ W0, const float* __restrict__ b0,
              const __half* __restrict__ W1, const float* __restrict__ b1,
              const __half* __restrict__ W2, const float* __restrict__ b2)
{
    extern __shared__ __align__(16) char dsm[];
    __half* As = (__half*)dsm;            // [3][128][GPAD]
    __half* Ws = As + 3 * GSTR;           // [3][128][GPAD]

    const __half* Wsel = W0;
    const float*  bsel = b0;
    __half* Hout = g_qh;
    if (blockIdx.z == 1)      { Wsel = W1; bsel = b1; Hout = g_kh; }
    else if (blockIdx.z == 2) { Wsel = W2; bsel = b2; Hout = g_vh; }

    const int tid    = threadIdx.x;
    const int lane   = tid & 31;
    const int wid    = tid >> 5;
    const int warp_m = wid & 1;
    const int warp_n = wid >> 1;
    const int gr     = lane >> 2;
    const int t4     = lane & 3;

    const int lr   = lane & 7;
    const int arow = ((lane >> 3) & 1) * 8 + lr;
    const int acol = ((lane >> 4) & 1) * 8;
    const int brow = ((lane >> 4) & 1) * 8 + lr;
    const int bcol = ((lane >> 3) & 1) * 8;

    const int bn = blockIdx.y * 128;
    const int bm = blockIdx.x * 128;

    const __half* Ag = A + (size_t)bn * KDIM;
    const __half* Wg = Wsel + (size_t)bm * KDIM;

    auto issue = [&](int c, int s) {
        __half* ab = As + s * GSTR;
        __half* wb = Ws + s * GSTR;
        #pragma unroll
        for (int i = 0; i < 4; i++) {
            const int idx = tid + i * 128;        // 0..511
            const int r = idx >> 2, ch = idx & 3;
            cp16(ab + r * GPAD + ch * 8, Ag + (size_t)r * KDIM + c * GBK + ch * 8);
            cp16(wb + r * GPAD + ch * 8, Wg + (size_t)r * KDIM + c * GBK + ch * 8);
        }
    };

    float acc[4][8][4];
    #pragma unroll
    for (int mt = 0; mt < 4; mt++)
        #pragma unroll
        for (int nt = 0; nt < 8; nt++)
            #pragma unroll
            for (int i = 0; i < 4; i++) acc[mt][nt][i] = 0.f;

    issue(0, 0); cp_commit();
    issue(1, 1); cp_commit();

    for (int c = 0; c < GKCH; c++) {
        if (c == GKCH - 1) cp_wait<0>(); else cp_wait<1>();
        __syncthreads();
        if (c + 2 < GKCH) { issue(c + 2, (c + 2) % 3); cp_commit(); }

        const int s = c % 3;
        const __half* Ab = As + s * GSTR + (warp_m * 64) * GPAD;
        const __half* Wb = Ws + s * GSTR + (warp_n * 64) * GPAD;
        #pragma unroll
        for (int kk = 0; kk < 2; kk++) {
            const int k0 = kk * 16;
            uint32_t af[4][4], bb[4][4];
            #pragma unroll
            for (int mt = 0; mt < 4; mt++)
                ldmx4(af[mt], Ab + (mt*16 + arow) * GPAD + k0 + acol);
            #pragma unroll
            for (int np = 0; np < 4; np++)
                ldmx4(bb[np], Wb + (np*16 + brow) * GPAD + k0 + bcol);
            #pragma unroll
            for (int mt = 0; mt < 4; mt++)
                #pragma unroll
                for (int np = 0; np < 4; np++) {
                    mma_f16(acc[mt][2*np    ], af[mt], &bb[np][0]);
                    mma_f16(acc[mt][2*np + 1], af[mt], &bb[np][2]);
                }
        }
    }

    #pragma unroll
    for (int nt = 0; nt < 8; nt++) {
        const int col = bm + warp_n * 64 + nt * 8 + t4 * 2;
        const float2 bv = *(const float2*)&bsel[col];
        #pragma unroll
        for (int mt = 0; mt < 4; mt++) {
            const int row = bn + warp_m * 64 + mt * 16 + gr;
            const int h = col / DHEAD, d = col % DHEAD;
            const int bb0 = row / SEQ, s0 = row % SEQ;
            const int bb1 = (row + 8) / SEQ, s1 = (row + 8) % SEQ;
            *(uint32_t*)&Hout[(((size_t)(bb0*NHEAD + h)*SEQ + s0)*DHEAD) + d] =
                packh2(acc[mt][nt][0] + bv.x, acc[mt][nt][1] + bv.y);
            *(uint32_t*)&Hout[(((size_t)(bb1*NHEAD + h)*SEQ + s1)*DHEAD) + d] =
                packh2(acc[mt][nt][2] + bv.x, acc[mt][nt][3] + bv.y);
        }
    }
}

// ---------------------------------------------------------------------------
// Output projection GEMM: CTA 64x128, 128 thr, 3-stage, 4 CTAs/SM.
// ---------------------------------------------------------------------------
#define OSTR_A (64 * GPAD)
#define OSTR   (192 * GPAD)
#define OUT_SMEM (3 * OSTR * 2)          // 46080 B

__global__ __launch_bounds__(128, 4)
void gemm_out(const __half* __restrict__ A, const __half* __restrict__ W,
              const float* __restrict__ bias, float* __restrict__ Y)
{
    extern __shared__ __align__(16) char dsm[];
    __half* Sm = (__half*)dsm;

    const int tid    = threadIdx.x;
    const int lane   = tid & 31;
    const int wid    = tid >> 5;
    const int warp_m = wid & 1;
    const int warp_n = wid >> 1;
    const int gr     = lane >> 2;
    const int t4     = lane & 3;

    const int lr   = lane & 7;
    const int arow = ((lane >> 3) & 1) * 8 + lr;
    const int acol = ((lane >> 4) & 1) * 8;
    const int brow = ((lane >> 4) & 1) * 8 + lr;
    const int bcol = ((lane >> 3) & 1) * 8;

    const int bn = blockIdx.y * 64;
    const int bm = blockIdx.x * 128;

    const __half* Ag = A + (size_t)bn * KDIM;
    const __half* Wg = W + (size_t)bm * KDIM;

    auto issue = [&](int c, int s) {
        __half* base = Sm + s * OSTR;
        #pragma unroll
        for (int i = 0; i < 6; i++) {
            const int idx = tid + i * 128;        // 0..767
            if (idx < 256) {
                const int r = idx >> 2, ch = idx & 3;
                cp16(base + r * GPAD + ch * 8, Ag + (size_t)r * KDIM + c * GBK + ch * 8);
            } else {
                const int j = idx - 256;
                const int r = j >> 2, ch = j & 3;
                cp16(base + OSTR_A + r * GPAD + ch * 8, Wg + (size_t)r * KDIM + c * GBK + ch * 8);
            }
        }
    };

    float acc[2][8][4];
    #pragma unroll
    for (int mt = 0; mt < 2; mt++)
        #pragma unroll
        for (int nt = 0; nt < 8; nt++)
            #pragma unroll
            for (int i = 0; i < 4; i++) acc[mt][nt][i] = 0.f;

    issue(0, 0); cp_commit();
    issue(1, 1); cp_commit();

    for (int c = 0; c < GKCH; c++) {
        if (c == GKCH - 1) cp_wait<0>(); else cp_wait<1>();
        __syncthreads();
        if (c + 2 < GKCH) { issue(c + 2, (c + 2) % 3); cp_commit(); }

        const int s = c % 3;
        const __half* Ab = Sm + s * OSTR + (warp_m * 32) * GPAD;
        const __half* Wb = Sm + s * OSTR + OSTR_A + (warp_n * 64) * GPAD;
        #pragma unroll
        for (int kk = 0; kk < 2; kk++) {
            const int k0 = kk * 16;
            uint32_t af[2][4], bb[4][4];
            #pragma unroll
            for (int mt = 0; mt < 2; mt++)
                ldmx4(af[mt], Ab + (mt*16 + arow) * GPAD + k0 + acol);
            #pragma unroll
            for (int np = 0; np < 4; np++)
                ldmx4(bb[np], Wb + (np*16 + brow) * GPAD + k0 + bcol);
            #pragma unroll
            for (int mt = 0; mt < 2; mt++)
                #pragma unroll
                for (int np = 0; np < 4; np++) {
                    mma_f16(acc[mt][2*np    ], af[mt], &bb[np][0]);
                    mma_f16(acc[mt][2*np + 1], af[mt], &bb[np][2]);
                }
        }
    }

    #pragma unroll
    for (int nt = 0; nt < 8; nt++) {
        const int col = bm + warp_n * 64 + nt * 8 + t4 * 2;
        const float2 bv = *(const float2*)&bias[col];
        #pragma unroll
        for (int mt = 0; mt < 2; mt++) {
            const int row = bn + warp_m * 32 + mt * 16 + gr;
            *(float2*)&Y[(size_t)row * D_MODEL + col] =
                make_float2(acc[mt][nt][0] + bv.x, acc[mt][nt][1] + bv.y);
            *(float2*)&Y[(size_t)(row + 8) * D_MODEL + col] =
                make_float2(acc[mt][nt][2] + bv.x, acc[mt][nt][3] + bv.y);
        }
    }
}

// ---------------------------------------------------------------------------
// Causal flash attention, fp16 mma. PERSISTENT, 296 slots.
// NEW: boustrophedon schedule: round k, slot i -> tile 296k + (k odd ?
// 295-i : i). Ascending-qb rounds cancel descending-qb rounds: per-slot
// load ~28-30 units (was 22-38) -> wall drops ~21%.
// NEW: ping-pong B-fragment prefetch in S and PV loops (hides LDS latency).
// 128 threads, 32 q-rows/warp; 6-stage paired K/V ring; tensor-core l col.
// ---------------------------------------------------------------------------
#define ABR   128
#define ABC   64
#define APAD  72
#define KVSTR (ABC * APAD)               // 4608 halves per 64-row stage
#define NSTG  6
#define ATTN_SMEM (NSTG * 2 * KVSTR * 2) // 110592 B
#define QSCALE (0.125f * 1.44269504088896340736f)
#define NQB   (SEQ / ABR)                // 16
#define NTILE (NQB * BATCH * NHEAD)      // 1024
#define NSLOT 296                        // 148 SMs * 2 CTAs

__global__ __launch_bounds__(128, 2)
void attn_h()
{
    extern __shared__ __align__(16) char dsm[];
    __half* Ksm = (__half*)dsm;               // [6][64][APAD]
    __half* Vsm = Ksm + NSTG * KVSTR;         // [6][64][APAD]
    __half* Qs  = Ksm + 4 * KVSTR;            // overlay: K stages 4,5 (128 rows)

    const int tid  = threadIdx.x;
    const int lane = tid & 31;
    const int wid  = tid >> 5;     // 0..3
    const int gr   = lane >> 2;
    const int t4   = lane & 3;
    const int r0   = wid * 32;     // warp owns q rows [r0, r0+32)

    const int lr   = lane & 7;
    const int arow = ((lane >> 3) & 1) * 8 + lr;
    const int acol = ((lane >> 4) & 1) * 8;
    const int brow = ((lane >> 4) & 1) * 8 + lr;   // K B-frags
    const int bcol = ((lane >> 3) & 1) * 8;
    const int trow = ((lane >> 3) & 1) * 8 + lr;   // V B-frags (trans)
    const int tcol = ((lane >> 4) & 1) * 8;

    // constant ones-column B fragment (l accumulation): B[k][n] = (n==0)
    const uint32_t lones = (gr == 0) ? 0x3C003C00u : 0u;
    const uint32_t lb[2] = { lones, lones };

    #pragma unroll 1
    for (int k = 0; k < 4; k++) {
        const int g = k * NSLOT + ((k & 1) ? (NSLOT - 1 - (int)blockIdx.x)
                                           : (int)blockIdx.x);
        if (g >= NTILE) continue;
        const int qb = (NQB - 1) - (g >> 6);   // qb-major, heavy first
        const int bh = g & 63;
        const int q0 = qb * ABR;

        const __half* Qg = g_qh + (size_t)bh * SEQ * DHEAD;
        const __half* Kg = g_kh + (size_t)bh * SEQ * DHEAD;
        const __half* Vg = g_vh + (size_t)bh * SEQ * DHEAD;

        const int pmax = qb;   // pairs of 64-col tiles; tiles 2p, 2p+1

        auto issue1 = [&](int t) {
            const int s = t % NSTG;
            #pragma unroll
            for (int i = 0; i < 4; i++) {
                const int idx = tid + i * 128;     // 0..511
                const int r = idx >> 3, ch = idx & 7;
                const size_t goff = (size_t)(t * ABC + r) * DHEAD + ch * 8;
                cp16(Ksm + s * KVSTR + r * APAD + ch * 8, Kg + goff);
                cp16(Vsm + s * KVSTR + r * APAD + ch * 8, Vg + goff);
            }
        };

        // Prior-tile smem reads complete (ended with cp_wait<0>; epilogue
        // is regs/gmem only) -> barrier then refill.
        __syncthreads();

        issue1(0); issue1(1); cp_commit();                      // group 0
        if (pmax >= 1) { issue1(2); issue1(3); cp_commit(); }   // group 1

        // ---- stage Q (x log2e/8) into overlay region: 1 row per thread ----
        {
            const __half* src = Qg + (size_t)(q0 + tid) * DHEAD;
            #pragma unroll
            for (int i = 0; i < 8; i++) {
                uint4 u = *(const uint4*)(src + i * 8);
                const __half2* hp = (const __half2*)&u;
                uint4 o;
                uint32_t* op = (uint32_t*)&o;
                #pragma unroll
                for (int kq = 0; kq < 4; kq++) {
                    float2 f = __half22float2(hp[kq]);
                    op[kq] = packh2(f.x * QSCALE, f.y * QSCALE);
                }
                *(uint4*)&Qs[tid * APAD + i * 8] = o;
            }
        }
        __syncthreads();

        uint32_t Qf[2][4][4];
        #pragma unroll
        for (int mt = 0; mt < 2; mt++)
            #pragma unroll
            for (int kk = 0; kk < 4; kk++)
                ldmx4(Qf[mt][kk], Qs + (r0 + mt*16 + arow) * APAD + kk * 16 + acol);
        // Qf resident; overlay may be overwritten after the next barrier.

        float m[2][2] = { {-1e30f, -1e30f}, {-1e30f, -1e30f} };
        float oacc[2][9][4];              // [mt][8] = l column (P . ones)
        #pragma unroll
        for (int mt = 0; mt < 2; mt++)
            #pragma unroll
            for (int nt = 0; nt < 9; nt++)
                #pragma unroll
                for (int i = 0; i < 4; i++) oacc[mt][nt][i] = 0.f;

        for (int p = 0; p <= pmax; p++) {
            if (p < pmax) cp_wait<1>(); else cp_wait<0>();
            __syncthreads();
            if (p + 2 <= pmax) { issue1(2*p + 4); issue1(2*p + 5); cp_commit(); }

            const bool needmask = (p == pmax);

            #pragma unroll
            for (int hh = 0; hh < 2; hh++) {
                const int t = 2*p + hh;
                const __half* Ks = Ksm + (t % NSTG) * KVSTR;
                const __half* Vs = Vsm + (t % NSTG) * KVSTR;
                const int kv0 = t * ABC;

                // ---- S = Qs * K^T with ping-pong K-frag prefetch ----
                float sacc[2][8][4];
                #pragma unroll
                for (int mt = 0; mt < 2; mt++)
                    #pragma unroll
                    for (int nt = 0; nt < 8; nt++)
                        #pragma unroll
                        for (int i = 0; i < 4; i++) sacc[mt][nt][i] = 0.f;

                {
                    uint32_t bb[2][4];
                    ldmx4(bb[0], Ks + brow * APAD + bcol);   // (kk=0,np=0)
                    int cur = 0;
                    #pragma unroll
                    for (int st = 0; st < 16; st++) {
                        const int kk = st >> 2, np = st & 3;
                        if (st < 15) {
                            const int nst = st + 1;
                            const int nkk = nst >> 2, nnp = nst & 3;
                            ldmx4(bb[cur ^ 1],
                                  Ks + (nnp*16 + brow) * APAD + nkk*16 + bcol);
                        }
                        #pragma unroll
                        for (int mt = 0; mt < 2; mt++) {
                            mma_f16(sacc[mt][2*np    ], Qf[mt][kk], &bb[cur][0]);
                            mma_f16(sacc[mt][2*np + 1], Qf[mt][kk], &bb[cur][2]);
                        }
                        cur ^= 1;
                    }
                }

                // ---- causal mask (last pair only) ----
                if (needmask) {
                    #pragma unroll
                    for (int mt = 0; mt < 2; mt++) {
                        const int ra = q0 + r0 + mt*16 + gr;
                        const int rb = ra + 8;
                        #pragma unroll
                        for (int nt = 0; nt < 8; nt++) {
                            const int col0 = kv0 + nt*8 + 2*t4;
                            if (col0     > ra) sacc[mt][nt][0] = -1e30f;
                            if (col0 + 1 > ra) sacc[mt][nt][1] = -1e30f;
                            if (col0     > rb) sacc[mt][nt][2] = -1e30f;
                            if (col0 + 1 > rb) sacc[mt][nt][3] = -1e30f;
                        }
                    }
                }

                // ---- online softmax, log2 domain (4 rows per thread) ----
                float mx[2][2];
                #pragma unroll
                for (int mt = 0; mt < 2; mt++) {
                    float a = -1e30f, bmx = -1e30f;
                    #pragma unroll
                    for (int nt = 0; nt < 8; nt++) {
                        a   = fmaxf(a,   fmaxf(sacc[mt][nt][0], sacc[mt][nt][1]));
                        bmx = fmaxf(bmx, fmaxf(sacc[mt][nt][2], sacc[mt][nt][3]));
                    }
                    a   = fmaxf(a,   __shfl_xor_sync(0xffffffffu, a,   1));
                    a   = fmaxf(a,   __shfl_xor_sync(0xffffffffu, a,   2));
                    bmx = fmaxf(bmx, __shfl_xor_sync(0xffffffffu, bmx, 1));
                    bmx = fmaxf(bmx, __shfl_xor_sync(0xffffffffu, bmx, 2));
                    mx[mt][0] = fmaxf(m[mt][0], a);
                    mx[mt][1] = fmaxf(m[mt][1], bmx);
                }
                const bool changed = (mx[0][0] > m[0][0]) || (mx[0][1] > m[0][1]) ||
                                     (mx[1][0] > m[1][0]) || (mx[1][1] > m[1][1]);
                if (__any_sync(0xffffffffu, changed)) {
                    #pragma unroll
                    for (int mt = 0; mt < 2; mt++) {
                        const float a0 = ex2f(m[mt][0] - mx[mt][0]);
                        const float a1 = ex2f(m[mt][1] - mx[mt][1]);
                        #pragma unroll
                        for (int nt = 0; nt < 9; nt++) {
                            oacc[mt][nt][0] *= a0; oacc[mt][nt][1] *= a0;
                            oacc[mt][nt][2] *= a1; oacc[mt][nt][3] *= a1;
                        }
                        m[mt][0] = mx[mt][0]; m[mt][1] = mx[mt][1];
                    }
                }

                #pragma unroll
                for (int mt = 0; mt < 2; mt++)
                    #pragma unroll
                    for (int nt = 0; nt < 8; nt++) {
                        sacc[mt][nt][0] = ex2f(sacc[mt][nt][0] - m[mt][0]);
                        sacc[mt][nt][1] = ex2f(sacc[mt][nt][1] - m[mt][0]);
                        sacc[mt][nt][2] = ex2f(sacc[mt][nt][2] - m[mt][1]);
                        sacc[mt][nt][3] = ex2f(sacc[mt][nt][3] - m[mt][1]);
                    }

                // ---- O += P * V with ping-pong V-frag prefetch ----
                {
                    uint32_t bt[2][4];
                    ldmx4t(bt[0], Vs + trow * APAD + tcol);   // (kk=0,np=0)
                    int cur = 0;
                    uint32_t pf[2][4];
                    #pragma unroll
                    for (int st = 0; st < 16; st++) {
                        const int kk = st >> 2, np = st & 3;
                        if (np == 0) {
                            #pragma unroll
                            for (int mt = 0; mt < 2; mt++) {
                                pf[mt][0] = packh2(sacc[mt][2*kk    ][0], sacc[mt][2*kk    ][1]);
                                pf[mt][1] = packh2(sacc[mt][2*kk    ][2], sacc[mt][2*kk    ][3]);
                                pf[mt][2] = packh2(sacc[mt][2*kk + 1][0], sacc[mt][2*kk + 1][1]);
                                pf[mt][3] = packh2(sacc[mt][2*kk + 1][2], sacc[mt][2*kk + 1][3]);
                            }
                        }
                        if (st < 15) {
                            const int nst = st + 1;
                            const int nkk = nst >> 2, nnp = nst & 3;
                            ldmx4t(bt[cur ^ 1],
                                   Vs + (nkk*16 + trow) * APAD + nnp*16 + tcol);
                        }
                        #pragma unroll
                        for (int mt = 0; mt < 2; mt++) {
                            mma_f16(oacc[mt][2*np    ], pf[mt], &bt[cur][0]);
                            mma_f16(oacc[mt][2*np + 1], pf[mt], &bt[cur][2]);
                        }
                        if (np == 3) {
                            mma_f16(oacc[0][8], pf[0], lb);
                            mma_f16(oacc[1][8], pf[1], lb);
                        }
                        cur ^= 1;
                    }
                }
            }
        }

        // ---- l in oacc[mt][8]: broadcast; normalize; write ----
        const int qbase = lane & ~3;
        const int b = bh >> 4, h = bh & 15;
        #pragma unroll
        for (int mt = 0; mt < 2; mt++) {
            const float inv0 = 1.f / __shfl_sync(0xffffffffu, oacc[mt][8][0], qbase);
            const float inv1 = 1.f / __shfl_sync(0xffffffffu, oacc[mt][8][2], qbase);
            const int ra = q0 + r0 + mt*16 + gr;
            const int rb = ra + 8;
            #pragma unroll
            for (int nt = 0; nt < 8; nt++) {
                const int col = h * DHEAD + nt*8 + 2*t4;
                *(uint32_t*)&g_ah[((size_t)(b*SEQ + ra)) * D_MODEL + col] =
                    packh2(oacc[mt][nt][0] * inv0, oacc[mt][nt][1] * inv0);
                *(uint32_t*)&g_ah[((size_t)(b*SEQ + rb)) * D_MODEL + col] =
                    packh2(oacc[mt][nt][2] * inv1, oacc[mt][nt][3] * inv1);
            }
        }
    }
}

// ---------------------------------------------------------------------------
extern "C" void kernel_launch(void* const* d_in, const int* in_sizes, int n_in,
                              void* d_out, int out_size)
{
    const float* x  = (const float*)d_in[0];
    const float* Wq = (const float*)d_in[1];
    const float* bq = (const float*)d_in[2];
    const float* Wk = (const float*)d_in[3];
    const float* bk = (const float*)d_in[4];
    const float* Wv = (const float*)d_in[5];
    const float* bv = (const float*)d_in[6];
    const float* Wo = (const float*)d_in[7];
    const float* bo = (const float*)d_in[8];

    __half *xh, *wqh, *wkh, *wvh, *woh, *ah;
    cudaGetSymbolAddress((void**)&xh,  g_xh);
    cudaGetSymbolAddress((void**)&wqh, g_wqh);
    cudaGetSymbolAddress((void**)&wkh, g_wkh);
    cudaGetSymbolAddress((void**)&wvh, g_wvh);
    cudaGetSymbolAddress((void**)&woh, g_woh);
    cudaGetSymbolAddress((void**)&ah,  g_ah);

    // fused fp32 -> fp16 pre-pass (1 launch)
    cvt_all<<<NCVT/256, 256>>>(x, Wq, Wk, Wv, Wo);

    cudaFuncSetAttribute(gemm_qkv,
                         cudaFuncAttributeMaxDynamicSharedMemorySize, GEMM_SMEM);
    cudaFuncSetAttribute(gemm_out,
                         cudaFuncAttributeMaxDynamicSharedMemorySize, OUT_SMEM);
    cudaFuncSetAttribute(attn_h,
                         cudaFuncAttributeMaxDynamicSharedMemorySize, ATTN_SMEM);

    // fused QKV projection (1 launch, z selects head)
    gemm_qkv<<<dim3(D_MODEL/128, NTOK/128, 3), 128, GEMM_SMEM>>>(
        xh, wqh, bq, wkh, bk, wvh, bv);

    // persistent attention: boustrophedon-balanced static schedule
    attn_h<<<NSLOT, 128, ATTN_SMEM>>>();

    // output projection
    gemm_out<<<dim3(D_MODEL/128, NTOK/64), 128, OUT_SMEM>>>(
        ah, woh, bo, (float*)d_out);
}